// round 4
// baseline (speedup 1.0000x reference)
#include <cuda_runtime.h>
#include <cstdint>
#include <math.h>

#define BB    2
#define CC    256
#define NPix  3600
#define NCls  2
#define HOUT  473
#define WOUT  473
#define NCHUNK 30

// ---------------- scratch ----------------
__device__ float g_E [BB*NPix*NPix];        // exp(S)
__device__ float g_Wv[BB*CC*NPix];
__device__ float g_rowinv[BB*NPix];
__device__ float g_colps[NCHUNK*BB*NPix];
__device__ float g_colinv[BB*NPix];
__device__ float g_att1[BB*CC*NPix];
__device__ float g_att2[BB*CC*NPix];
__device__ float g_x1[BB*CC*NPix];
__device__ float g_x2[BB*CC*NPix];
__device__ float g_bnsc1[CC], g_bnsh1[CC];
__device__ float g_bnsc2[CC], g_bnsh2[CC];
__device__ float g_y1[BB*NCls*NPix];
__device__ float g_y2[BB*NCls*NPix];

// ---------------- tf32 helpers ----------------
__device__ __forceinline__ uint32_t f2tf32(float v) {
    uint32_t r; asm("cvt.rna.tf32.f32 %0, %1;" : "=r"(r) : "f"(v)); return r;
}

// SMEM fragment layout (floats):
// A: [stage 2][s 4][mt 8][lane 32][reg 4] = 8192 floats
// B: 8192 + [stage 2][s 4][nt 16][lane 32][reg 2] = 8192 floats
#define A_IDX(st,s,mt,lane,r)  (((((st)*4+(s))*8+(mt))*128) + (lane)*4 + (r))
#define B_IDX(st,s,nt,lane,r)  (8192 + ((((st)*4+(s))*16+(nt))*64) + (lane)*2 + (r))
#define GEMM_SMEM (16384*4)

// mma.sync m16n8k8 tf32: A row-major fragment, B col-major fragment
#define MMA_TF32(accp, af, bf) \
    asm volatile("mma.sync.aligned.m16n8k8.row.col.f32.tf32.tf32.f32 " \
        "{%0,%1,%2,%3},{%4,%5,%6,%7},{%8,%9},{%0,%1,%2,%3};" \
        : "+f"((accp)[0]), "+f"((accp)[1]), "+f"((accp)[2]), "+f"((accp)[3]) \
        : "r"((af)[0]), "r"((af)[1]), "r"((af)[2]), "r"((af)[3]), \
          "r"((bf)[0]), "r"((bf)[1]))

// =============== GEMM body: C[M,N] = A*B, tile 128x128, Kchunk 32 ===============
// ALOAD 0: A(i,k)=A[i*lda+k]   ALOAD 1: A(i,k)=A[k*lda+i]
// BLOAD 0: B(k,j)=Bp[k*ldb+j]  BLOAD 1: B(k,j)=Bp[j*ldb+k]  BLOAD 2: im2col(s0,s1,s2)
// EEXP: store exp(acc).  BSCALE: multiply B(k,j) by Sc[j].
template<int ALOAD, int BLOAD, int EEXP, int BSCALE>
__device__ __forceinline__ void mma_body(
    const float* __restrict__ Ap, const float* __restrict__ Bp,
    const float* __restrict__ s1, const float* __restrict__ s2,
    const float* __restrict__ Sc, float* __restrict__ Cp,
    int Md, int Nd, int Kd, int lda, int ldb, int ldc,
    int z, int m0, int n0, float* sm)
{
    const int tid = threadIdx.x;
    const int lane = tid & 31, wid = tid >> 5;
    const int wm = wid >> 2, wn = wid & 3;   // warp tile: 64 rows x 32 cols

    float acc[4][4][4];
#pragma unroll
    for (int a = 0; a < 4; a++)
#pragma unroll
        for (int b = 0; b < 4; b++)
#pragma unroll
            for (int c = 0; c < 4; c++) acc[a][b][c] = 0.f;

    const int NC = (Kd + 31) >> 5;

    auto load_chunk = [&](int c) {
        const int st = c & 1;
        const int k0 = c << 5;
        // ---------- A tile ----------
        if (ALOAD == 0) {
            int row = tid >> 1, kb = (tid & 1) << 4;
            int gi = m0 + row;
            int mt = row >> 4, mb = (row >> 3) & 1, l4 = (row & 7) << 2;
#pragma unroll
            for (int q = 0; q < 4; q++) {
                int k = kb + q * 4;
                float4 v = make_float4(0.f, 0.f, 0.f, 0.f);
                if (gi < Md && (k0 + k) < Kd)
                    v = *(const float4*)(Ap + (size_t)gi * lda + k0 + k);
#pragma unroll
                for (int u = 0; u < 4; u++) {
                    int kk = k + u;
                    int s = kk >> 3, k8 = kk & 7;
                    sm[A_IDX(st, s, mt, l4 | (k8 & 3), ((k8 >> 2) << 1) | mb)] =
                        __uint_as_float(f2tf32(((const float*)&v)[u]));
                }
            }
        } else {
            int kk = tid >> 3, ib = (tid & 7) << 4;
            int s = kk >> 3, k8 = kk & 7;
#pragma unroll
            for (int q = 0; q < 4; q++) {
                int i = ib + q * 4;
                int gi = m0 + i;
                float4 v = make_float4(0.f, 0.f, 0.f, 0.f);
                if ((k0 + kk) < Kd && gi < Md)
                    v = *(const float4*)(Ap + (size_t)(k0 + kk) * lda + gi);
#pragma unroll
                for (int u = 0; u < 4; u++) {
                    int m = i + u;
                    sm[A_IDX(st, s, m >> 4, ((m & 7) << 2) | (k8 & 3),
                             ((k8 >> 2) << 1) | ((m >> 3) & 1))] =
                        __uint_as_float(f2tf32(((const float*)&v)[u]));
                }
            }
        }
        // ---------- B tile ----------
        if (BLOAD == 0) {
            int kk = tid >> 3, jb = (tid & 7) << 4;
            int s = kk >> 3, k8 = kk & 7;
#pragma unroll
            for (int q = 0; q < 4; q++) {
                int j = jb + q * 4;
                int gj = n0 + j;
                float4 v = make_float4(0.f, 0.f, 0.f, 0.f);
                if ((k0 + kk) < Kd && gj < Nd)
                    v = *(const float4*)(Bp + (size_t)(k0 + kk) * ldb + gj);
                float4 scv = make_float4(1.f, 1.f, 1.f, 1.f);
                if (BSCALE && gj < Nd) scv = *(const float4*)(Sc + gj);
#pragma unroll
                for (int u = 0; u < 4; u++) {
                    int n = j + u;
                    float x = ((const float*)&v)[u];
                    if (BSCALE) x *= ((const float*)&scv)[u];
                    sm[B_IDX(st, s, n >> 3, ((n & 7) << 2) | (k8 & 3), k8 >> 2)] =
                        __uint_as_float(f2tf32(x));
                }
            }
        } else if (BLOAD == 1) {
            int j = tid >> 1, kb = (tid & 1) << 4;
            int gj = n0 + j;
            float scj = 1.f;
            if (BSCALE && gj < Nd) scj = Sc[gj];
            int nt = j >> 3, l4 = (j & 7) << 2;
#pragma unroll
            for (int q = 0; q < 4; q++) {
                int k = kb + q * 4;
                float4 v = make_float4(0.f, 0.f, 0.f, 0.f);
                if (gj < Nd && (k0 + k) < Kd)
                    v = *(const float4*)(Bp + (size_t)gj * ldb + k0 + k);
#pragma unroll
                for (int u = 0; u < 4; u++) {
                    int kk = k + u;
                    int s = kk >> 3, k8 = kk & 7;
                    float x = ((const float*)&v)[u];
                    if (BSCALE) x *= scj;
                    sm[B_IDX(st, s, nt, l4 | (k8 & 3), k8 >> 2)] =
                        __uint_as_float(f2tf32(x));
                }
            }
        } else {
            int j = tid >> 1, kb = (tid & 1) << 4;
            int gj = n0 + j;
            bool jok = gj < Nd;
            int h = gj / 60, w = gj - h * 60;
            int nt = j >> 3, l4 = (j & 7) << 2;
#pragma unroll
            for (int q = 0; q < 16; q++) {
                int kk = kb + q;
                int kg = k0 + kk;
                float x = 0.f;
                if (jok && kg < Kd) {
                    int ci = kg / 9;
                    int rr = kg - ci * 9;
                    int kh = rr / 3, kw = rr - kh * 3;
                    const float* sp = (ci < 256) ? Bp : ((ci < 512) ? s1 : s2);
                    int cl = ci & 255;
                    int ih = h + kh - 1, iw = w + kw - 1;
                    if ((unsigned)ih < 60u && (unsigned)iw < 60u)
                        x = sp[(size_t)(z * CC + cl) * NPix + ih * 60 + iw];
                }
                int s = kk >> 3, k8 = kk & 7;
                sm[B_IDX(st, s, nt, l4 | (k8 & 3), k8 >> 2)] =
                    __uint_as_float(f2tf32(x));
            }
        }
    };

    load_chunk(0);
    __syncthreads();
    for (int c = 0; c < NC; c++) {
        if (c + 1 < NC) load_chunk(c + 1);
        const int st = c & 1;
#pragma unroll
        for (int s = 0; s < 4; s++) {
            uint32_t af[4][4], bf[4][2];
#pragma unroll
            for (int mt = 0; mt < 4; mt++) {
                float4 v = *(const float4*)&sm[A_IDX(st, s, wm * 4 + mt, lane, 0)];
                af[mt][0] = __float_as_uint(v.x); af[mt][1] = __float_as_uint(v.y);
                af[mt][2] = __float_as_uint(v.z); af[mt][3] = __float_as_uint(v.w);
            }
#pragma unroll
            for (int nt = 0; nt < 4; nt++) {
                float2 v = *(const float2*)&sm[B_IDX(st, s, wn * 4 + nt, lane, 0)];
                bf[nt][0] = __float_as_uint(v.x); bf[nt][1] = __float_as_uint(v.y);
            }
#pragma unroll
            for (int mt = 0; mt < 4; mt++)
#pragma unroll
                for (int nt = 0; nt < 4; nt++)
                    MMA_TF32(acc[mt][nt], af[mt], bf[nt]);
        }
        __syncthreads();
    }

    // epilogue: direct float2 stores
#pragma unroll
    for (int mt = 0; mt < 4; mt++) {
        int r0 = m0 + wm * 64 + mt * 16 + (lane >> 2);
#pragma unroll
        for (int nt = 0; nt < 4; nt++) {
            int c0 = n0 + wn * 32 + nt * 8 + (lane & 3) * 2;
            if (c0 < Nd) {
                if (r0 < Md) {
                    float2 v = make_float2(acc[mt][nt][0], acc[mt][nt][1]);
                    if (EEXP) { v.x = __expf(v.x); v.y = __expf(v.y); }
                    *(float2*)&Cp[(size_t)r0 * ldc + c0] = v;
                }
                if (r0 + 8 < Md) {
                    float2 v = make_float2(acc[mt][nt][2], acc[mt][nt][3]);
                    if (EEXP) { v.x = __expf(v.x); v.y = __expf(v.y); }
                    *(float2*)&Cp[(size_t)(r0 + 8) * ldc + c0] = v;
                }
            }
        }
    }
}

template<int ALOAD, int BLOAD, int EEXP, int BSCALE>
__global__ void __launch_bounds__(256)
mma_gemm(const float* __restrict__ A, const float* __restrict__ B0,
         const float* __restrict__ Bsc, float* __restrict__ Cc,
         int Md, int Nd, int Kd, int lda, int ldb, int ldc,
         size_t sA, size_t sB, size_t sC, size_t sScale)
{
    extern __shared__ float sm[];
    int z = blockIdx.z;
    mma_body<ALOAD, BLOAD, EEXP, BSCALE>(
        A + (size_t)z * sA, B0 + (size_t)z * sB, nullptr, nullptr,
        BSCALE ? (Bsc + (size_t)z * sScale) : nullptr,
        Cc + (size_t)z * sC,
        Md, Nd, Kd, lda, ldb, ldc, z, blockIdx.y * 128, blockIdx.x * 128, sm);
}

// combined conv1+conv2 (blockIdx.z: 0,1 -> conv1 b=0,1 ; 2,3 -> conv2 b=0,1)
__global__ void __launch_bounds__(256)
conv_gemm(const float* __restrict__ W1, const float* __restrict__ W2,
          const float* __restrict__ att1, const float* __restrict__ va,
          const float* __restrict__ da,
          const float* __restrict__ att2, const float* __restrict__ vb,
          float* __restrict__ x1, float* __restrict__ x2)
{
    extern __shared__ float sm[];
    int zz = blockIdx.z, br = zz >> 1, b = zz & 1;
    const float* Wt = br ? W2 : W1;
    int Kd = br ? (2 * CC * 9) : (3 * CC * 9);
    const float* s0 = br ? att2 : att1;
    const float* s1 = br ? vb : va;
    const float* s2 = br ? vb : da;
    float* out = (br ? x2 : x1) + (size_t)b * CC * NPix;
    mma_body<0, 2, 0, 0>(Wt, s0, s1, s2, nullptr, out,
        CC, NPix, Kd, Kd, 0, NPix, b, blockIdx.y * 128, blockIdx.x * 128, sm);
}

// ---------------- sums of E ----------------
__global__ void rowsum_kernel()
{
    int row = blockIdx.x;
    const float* Er = g_E + (size_t)row * NPix;
    float s = 0.f;
    for (int j = threadIdx.x; j < NPix; j += 256) s += Er[j];
    __shared__ float ss[256];
    ss[threadIdx.x] = s;
    __syncthreads();
    for (int off = 128; off; off >>= 1) {
        if (threadIdx.x < off) ss[threadIdx.x] += ss[threadIdx.x + off];
        __syncthreads();
    }
    if (threadIdx.x == 0) g_rowinv[row] = 1.f / ss[0];
}

__global__ void colsum_part()
{
    int m = blockIdx.x * 256 + threadIdx.x;
    int ch = blockIdx.y, b = blockIdx.z;
    if (m >= NPix) return;
    const int rows = NPix / NCHUNK;     // 120
    const float* Ep = g_E + (size_t)b * NPix * NPix + (size_t)(ch * rows) * NPix + m;
    float s0 = 0.f, s1 = 0.f, s2 = 0.f, s3 = 0.f;
    for (int n = 0; n < rows; n += 4) {
        s0 += Ep[(size_t)(n + 0) * NPix];
        s1 += Ep[(size_t)(n + 1) * NPix];
        s2 += Ep[(size_t)(n + 2) * NPix];
        s3 += Ep[(size_t)(n + 3) * NPix];
    }
    g_colps[(size_t)(ch * BB + b) * NPix + m] = (s0 + s1) + (s2 + s3);
}

__global__ void colsum_comb()
{
    int m = blockIdx.x * 256 + threadIdx.x;
    int b = blockIdx.z;
    if (m >= NPix) return;
    float s = 0.f;
#pragma unroll
    for (int ch = 0; ch < NCHUNK; ch++)
        s += g_colps[(size_t)(ch * BB + b) * NPix + m];
    g_colinv[b * NPix + m] = 1.f / s;
}

// ---------------- gate ----------------
__global__ void gate_kernel(float* __restrict__ Z, const float* __restrict__ gw)
{
    int b = blockIdx.z;
    int pix = blockIdx.x * 256 + threadIdx.x;
    __shared__ float w[CC];
    for (int c = threadIdx.x; c < CC; c += 256) w[c] = gw[c];
    __syncthreads();
    if (pix >= NPix) return;
    float* zp = Z + (size_t)b * CC * NPix + pix;
    float g = 0.f;
    for (int c = 0; c < CC; c++) g += w[c] * zp[(size_t)c * NPix];
    float sg = 1.f / (1.f + __expf(-g));
    for (int c = 0; c < CC; c++) zp[(size_t)c * NPix] *= sg;
}

// ---------------- BN stats ----------------
__global__ void bnstats_kernel(const float* __restrict__ x,
                               const float* __restrict__ gam,
                               const float* __restrict__ bet,
                               float* __restrict__ scale, float* __restrict__ shift)
{
    int c = blockIdx.x;
    float s = 0.f, q = 0.f;
    for (int b = 0; b < BB; b++) {
        const float* xp = x + (size_t)(b * CC + c) * NPix;
        for (int i = threadIdx.x; i < NPix; i += 256) {
            float v = xp[i];
            s += v; q += v * v;
        }
    }
    __shared__ float rs[256], rq[256];
    rs[threadIdx.x] = s; rq[threadIdx.x] = q;
    __syncthreads();
    for (int off = 128; off; off >>= 1) {
        if (threadIdx.x < off) {
            rs[threadIdx.x] += rs[threadIdx.x + off];
            rq[threadIdx.x] += rq[threadIdx.x + off];
        }
        __syncthreads();
    }
    if (threadIdx.x == 0) {
        const float inv = 1.f / (BB * NPix);
        float mean = rs[0] * inv;
        float var  = rq[0] * inv - mean * mean;
        float sc = gam[c] * rsqrtf(var + 1e-5f);
        scale[c] = sc;
        shift[c] = bet[c] - mean * sc;
    }
}

// ---------------- fused BN + ReLU + 1x1 cls ----------------
__global__ void bncls_kernel(const float* __restrict__ x,
                             const float* __restrict__ scale, const float* __restrict__ shift,
                             const float* __restrict__ cw, const float* __restrict__ cb,
                             float* __restrict__ y)
{
    int b = blockIdx.z;
    int pix = blockIdx.x * 256 + threadIdx.x;
    __shared__ float sc[CC], sh[CC], w0[CC], w1[CC];
    for (int c = threadIdx.x; c < CC; c += 256) {
        sc[c] = scale[c]; sh[c] = shift[c];
        w0[c] = cw[c];    w1[c] = cw[CC + c];
    }
    __syncthreads();
    if (pix >= NPix) return;
    const float* xp = x + (size_t)b * CC * NPix + pix;
    float a0 = cb[0], a1 = cb[1];
    for (int c = 0; c < CC; c++) {
        float v = xp[(size_t)c * NPix] * sc[c] + sh[c];
        v = fmaxf(v, 0.f);
        a0 += v * w0[c];
        a1 += v * w1[c];
    }
    y[(size_t)(b * NCls + 0) * NPix + pix] = a0;
    y[(size_t)(b * NCls + 1) * NPix + pix] = a1;
}

// ---------------- bilinear resize + sigmoid ----------------
__global__ void resize_kernel(float* __restrict__ out)
{
    const size_t per = (size_t)BB * NCls * HOUT * WOUT;
    size_t idx = (size_t)blockIdx.x * 256 + threadIdx.x;
    if (idx >= 2 * per) return;
    int t = idx >= per;
    size_t r = idx - (size_t)t * per;
    int x = (int)(r % WOUT); r /= WOUT;
    int y = (int)(r % HOUT); r /= HOUT;
    int kc = (int)(r % NCls);
    int b  = (int)(r / NCls);
    const float* src = (t ? g_y2 : g_y1) + (size_t)(b * NCls + kc) * NPix;

    const float sc = 60.f / 473.f;
    float syf = (y + 0.5f) * sc - 0.5f;
    float sxf = (x + 0.5f) * sc - 0.5f;
    float fy0 = floorf(syf), fx0 = floorf(sxf);
    float fy = syf - fy0,    fx = sxf - fx0;
    int y0 = (int)fy0, x0 = (int)fx0;
    int y1i = min(y0 + 1, 59), x1i = min(x0 + 1, 59);
    y0 = max(y0, 0); x0 = max(x0, 0);

    float v00 = src[y0  * 60 + x0 ];
    float v01 = src[y0  * 60 + x1i];
    float v10 = src[y1i * 60 + x0 ];
    float v11 = src[y1i * 60 + x1i];
    float vt = v00 + (v01 - v00) * fx;
    float vb = v10 + (v11 - v10) * fx;
    float v  = vt + (vb - vt) * fy;

    out[idx] = 1.f / (1.f + __expf(-v));
}

// ---------------- orchestration ----------------
extern "C" void kernel_launch(void* const* d_in, const int* in_sizes, int n_in,
                              void* d_out, int out_size)
{
    const float* V_a     = (const float*)d_in[0];
    const float* V_b     = (const float*)d_in[1];
    const float* D_a     = (const float*)d_in[2];
    const float* W_e     = (const float*)d_in[3];
    const float* gate_w  = (const float*)d_in[4];
    const float* conv1_w = (const float*)d_in[5];
    const float* conv2_w = (const float*)d_in[6];
    const float* bn1_g   = (const float*)d_in[7];
    const float* bn1_b   = (const float*)d_in[8];
    const float* bn2_g   = (const float*)d_in[9];
    const float* bn2_b   = (const float*)d_in[10];
    const float* cls1_w  = (const float*)d_in[11];
    const float* cls1_b  = (const float*)d_in[12];
    const float* cls2_w  = (const float*)d_in[13];
    const float* cls2_b  = (const float*)d_in[14];
    float* out = (float*)d_out;

    float *E, *Wv, *att1, *att2, *x1, *x2, *y1, *y2;
    float *rowinv, *colinv, *bnsc1, *bnsh1, *bnsc2, *bnsh2;
    cudaGetSymbolAddress((void**)&E,      g_E);
    cudaGetSymbolAddress((void**)&Wv,     g_Wv);
    cudaGetSymbolAddress((void**)&att1,   g_att1);
    cudaGetSymbolAddress((void**)&att2,   g_att2);
    cudaGetSymbolAddress((void**)&x1,     g_x1);
    cudaGetSymbolAddress((void**)&x2,     g_x2);
    cudaGetSymbolAddress((void**)&y1,     g_y1);
    cudaGetSymbolAddress((void**)&y2,     g_y2);
    cudaGetSymbolAddress((void**)&rowinv, g_rowinv);
    cudaGetSymbolAddress((void**)&colinv, g_colinv);
    cudaGetSymbolAddress((void**)&bnsc1,  g_bnsc1);
    cudaGetSymbolAddress((void**)&bnsh1,  g_bnsh1);
    cudaGetSymbolAddress((void**)&bnsc2,  g_bnsc2);
    cudaGetSymbolAddress((void**)&bnsh2,  g_bnsh2);

    cudaFuncSetAttribute(mma_gemm<0,0,0,0>, cudaFuncAttributeMaxDynamicSharedMemorySize, GEMM_SMEM);
    cudaFuncSetAttribute(mma_gemm<1,0,1,0>, cudaFuncAttributeMaxDynamicSharedMemorySize, GEMM_SMEM);
    cudaFuncSetAttribute(mma_gemm<0,0,0,1>, cudaFuncAttributeMaxDynamicSharedMemorySize, GEMM_SMEM);
    cudaFuncSetAttribute(mma_gemm<0,1,0,1>, cudaFuncAttributeMaxDynamicSharedMemorySize, GEMM_SMEM);
    cudaFuncSetAttribute(conv_gemm,         cudaFuncAttributeMaxDynamicSharedMemorySize, GEMM_SMEM);

    const size_t CN = (size_t)CC * NPix;
    const size_t NN = (size_t)NPix * NPix;
    dim3 gSmall(29, 2, 2);
    dim3 gBig(29, 29, 2);
    dim3 gConv(29, 2, 4);

    // 1) Wv = W_e @ V_a
    mma_gemm<0,0,0,0><<<gSmall, 256, GEMM_SMEM>>>(W_e, V_a, nullptr, Wv,
        CC, NPix, CC, CC, NPix, NPix, 0, CN, CN, 0);
    // 2) E = exp(Wv^T @ V_b)   (exp fused into epilogue; no max-shift needed)
    mma_gemm<1,0,1,0><<<gBig, 256, GEMM_SMEM>>>(Wv, V_b, nullptr, E,
        NPix, NPix, CC, NPix, NPix, NPix, CN, CN, NN, 0);
    // 3) row/col sums of E
    rowsum_kernel<<<BB * NPix, 256>>>();
    colsum_part<<<dim3(15, NCHUNK, BB), 256>>>();
    colsum_comb<<<dim3(15, 1, BB), 256>>>();
    // 4) Z_b = V_a @ (E * colinv[j])  -> gate
    mma_gemm<0,0,0,1><<<gSmall, 256, GEMM_SMEM>>>(V_a, E, colinv, att2,
        CC, NPix, NPix, NPix, NPix, NPix, CN, NN, CN, NPix);
    gate_kernel<<<dim3(15, 1, BB), 256>>>(att2, gate_w);
    // 5) Z_a = V_b @ (E^T * rowinv[j]) -> gate
    mma_gemm<0,1,0,1><<<gSmall, 256, GEMM_SMEM>>>(V_b, E, rowinv, att1,
        CC, NPix, NPix, NPix, NPix, NPix, CN, NN, CN, NPix);
    gate_kernel<<<dim3(15, 1, BB), 256>>>(att1, gate_w);
    // 6) both convs in one launch
    conv_gemm<<<gConv, 256, GEMM_SMEM>>>(conv1_w, conv2_w,
        att1, V_a, D_a, att2, V_b, x1, x2);
    // 7) BN + cls
    bnstats_kernel<<<CC, 256>>>(x1, bn1_g, bn1_b, bnsc1, bnsh1);
    bnstats_kernel<<<CC, 256>>>(x2, bn2_g, bn2_b, bnsc2, bnsh2);
    bncls_kernel<<<dim3(15, 1, BB), 256>>>(x1, bnsc1, bnsh1, cls1_w, cls1_b, y1);
    bncls_kernel<<<dim3(15, 1, BB), 256>>>(x2, bnsc2, bnsh2, cls2_w, cls2_b, y2);
    // 8) resize + sigmoid
    const size_t total = 2ull * BB * NCls * HOUT * WOUT;
    resize_kernel<<<(int)((total + 255) / 256), 256>>>(out);
}

// round 5
// speedup vs baseline: 3.7398x; 3.7398x over previous
#include <cuda_runtime.h>
#include <cuda_bf16.h>
#include <cstdint>
#include <math.h>

#define BB 2
#define CC 256
#define NPix 3600
#define NCls 2
#define HOUT 473
#define WOUT 473
#define K1 6912
#define K2 4608
typedef __nv_bfloat16 bf16;
typedef __nv_bfloat162 bf162;

__device__ bf16 g_Vab[BB*CC*NPix], g_Vbb[BB*CC*NPix], g_Dab[BB*CC*NPix];
__device__ bf16 g_Web[CC*CC], g_w1b[CC*K1], g_w2b[CC*K2];
__device__ bf16 g_VaT[BB*NPix*CC], g_VbT[BB*NPix*CC], g_WvT[BB*NPix*CC];
__device__ bf16 g_E[(size_t)BB*NPix*NPix], g_ET[(size_t)BB*NPix*NPix];
__device__ bf16 g_att1b[BB*CC*NPix], g_att2b[BB*CC*NPix];
__device__ bf16 g_cb1[(size_t)BB*NPix*K1], g_cb2[(size_t)BB*NPix*K2];
__device__ float g_att1f[BB*CC*NPix], g_att2f[BB*CC*NPix];
__device__ float g_x1[BB*CC*NPix], g_x2[BB*CC*NPix];
__device__ float g_rowinv[BB*NPix], g_colinv[BB*NPix];
__device__ float g_bnsc1[CC], g_bnsh1[CC], g_bnsc2[CC], g_bnsh2[CC];
__device__ float g_y1[BB*NCls*NPix], g_y2[BB*NCls*NPix];

__device__ __forceinline__ uint32_t smem_u32(const void* p){
    uint32_t a; asm("{ .reg .u64 t; cvta.to.shared.u64 t, %1; cvt.u32.u64 %0, t; }":"=r"(a):"l"(p)); return a;
}
__device__ __forceinline__ void cpa16(uint32_t d, const void* s, bool v){
    asm volatile("cp.async.cg.shared.global [%0],[%1],16,%2;"::"r"(d),"l"(s),"r"(v?16:0));
}
__device__ __forceinline__ void ldmx4(uint32_t* r, uint32_t a){
    asm volatile("ldmatrix.sync.aligned.m8n8.x4.shared.b16 {%0,%1,%2,%3},[%4];"
        :"=r"(r[0]),"=r"(r[1]),"=r"(r[2]),"=r"(r[3]):"r"(a));
}
__device__ __forceinline__ void mma_bf16(float* c, const uint32_t* a, const uint32_t* b){
    asm volatile("mma.sync.aligned.m16n8k16.row.col.f32.bf16.bf16.f32 "
        "{%0,%1,%2,%3},{%4,%5,%6,%7},{%8,%9},{%0,%1,%2,%3};"
        :"+f"(c[0]),"+f"(c[1]),"+f"(c[2]),"+f"(c[3])
        :"r"(a[0]),"r"(a[1]),"r"(a[2]),"r"(a[3]),"r"(b[0]),"r"(b[1]));
}

#define STG 20480
#define GSMEM (4*STG)

// C[M,N] = A[M,K] * B^T  with A=[i][k], B=[j][k], bf16, OUTM: 0=f32, 1=bf16, 2=exp->bf16
template<int OUTM>
__global__ void __launch_bounds__(256)
bgemm(const bf16* __restrict__ A, const bf16* __restrict__ B, void* __restrict__ Cv,
      int Md, int Nd, int Kd, int lda, int ldb, int ldc, size_t sA, size_t sB, size_t sC)
{
    extern __shared__ char smc[];
    const int z = blockIdx.z;
    A += (size_t)z * sA; B += (size_t)z * sB;
    const int m0 = blockIdx.y * 128, n0 = blockIdx.x * 128;
    const int tid = threadIdx.x, lane = tid & 31, wid = tid >> 5;
    const int wm = wid >> 2, wn = wid & 3, g = lane >> 3, r = lane & 7;
    uint32_t sb = smem_u32(smc);
    float acc[4][4][4];
#pragma unroll
    for (int a = 0; a < 4; a++)
#pragma unroll
        for (int b = 0; b < 4; b++)
#pragma unroll
            for (int c = 0; c < 4; c++) acc[a][b][c] = 0.f;
    const int NC = (Kd + 31) >> 5;

    auto LD = [&](int c) {
        if (c < NC) {
            uint32_t st = sb + (c & 3) * STG;
            int k0 = c << 5;
#pragma unroll
            for (int q = 0; q < 2; q++) {
                int idx = tid * 2 + q, row = idx >> 2, sg = idx & 3;
                bool v = (m0 + row) < Md && (k0 + sg * 8) < Kd;
                cpa16(st + row * 80 + sg * 16, A + (v ? ((size_t)(m0 + row) * lda + k0 + sg * 8) : 0), v);
            }
#pragma unroll
            for (int q = 0; q < 2; q++) {
                int idx = tid * 2 + q, row = idx >> 2, sg = idx & 3;
                bool v = (n0 + row) < Nd && (k0 + sg * 8) < Kd;
                cpa16(st + 10240 + row * 80 + sg * 16, B + (v ? ((size_t)(n0 + row) * ldb + k0 + sg * 8) : 0), v);
            }
        }
        asm volatile("cp.async.commit_group;":::"memory");
    };
    LD(0); LD(1); LD(2);

    for (int c = 0; c < NC; c++) {
        asm volatile("cp.async.wait_group 2;":::"memory");
        __syncthreads();
        uint32_t ta = sb + (c & 3) * STG, tb = ta + 10240;
#pragma unroll
        for (int s = 0; s < 2; s++) {
            uint32_t af[4][4], bq[4][2];
#pragma unroll
            for (int mt = 0; mt < 4; mt++)
                ldmx4(af[mt], ta + (uint32_t)((wm * 64 + mt * 16 + (g & 1) * 8 + r) * 80 + (g >> 1) * 16 + s * 32));
#pragma unroll
            for (int np = 0; np < 2; np++) {
                uint32_t t4[4];
                ldmx4(t4, tb + (uint32_t)((wn * 32 + np * 16 + (g >> 1) * 8 + r) * 80 + (g & 1) * 16 + s * 32));
                bq[np*2][0] = t4[0]; bq[np*2][1] = t4[1];
                bq[np*2+1][0] = t4[2]; bq[np*2+1][1] = t4[3];
            }
#pragma unroll
            for (int mt = 0; mt < 4; mt++)
#pragma unroll
                for (int nt = 0; nt < 4; nt++)
                    mma_bf16(acc[mt][nt], af[mt], bq[nt]);
        }
        LD(c + 3);
    }

#pragma unroll
    for (int mt = 0; mt < 4; mt++) {
        int r0 = m0 + wm * 64 + mt * 16 + (lane >> 2);
#pragma unroll
        for (int nt = 0; nt < 4; nt++) {
            int c0 = n0 + wn * 32 + nt * 8 + (lane & 3) * 2;
            if (c0 >= Nd) continue;
            float x0 = acc[mt][nt][0], x1 = acc[mt][nt][1], x2 = acc[mt][nt][2], x3 = acc[mt][nt][3];
            if (OUTM == 2) { x0 = __expf(x0); x1 = __expf(x1); x2 = __expf(x2); x3 = __expf(x3); }
            if (OUTM == 0) {
                float* C = (float*)Cv + (size_t)z * sC;
                if (r0 < Md)     *(float2*)&C[(size_t)r0 * ldc + c0]       = make_float2(x0, x1);
                if (r0 + 8 < Md) *(float2*)&C[(size_t)(r0 + 8) * ldc + c0] = make_float2(x2, x3);
            } else {
                bf16* C = (bf16*)Cv + (size_t)z * sC;
                if (r0 < Md)     *(bf162*)&C[(size_t)r0 * ldc + c0]       = __floats2bfloat162_rn(x0, x1);
                if (r0 + 8 < Md) *(bf162*)&C[(size_t)(r0 + 8) * ldc + c0] = __floats2bfloat162_rn(x2, x3);
            }
        }
    }
}

__global__ void cvt_k(const float* __restrict__ in, bf16* __restrict__ out, int n)
{
    int i = (blockIdx.x * 256 + threadIdx.x) * 4;
    if (i >= n) return;
    float4 v = *(const float4*)(in + i);
    bf162 a = __floats2bfloat162_rn(v.x, v.y), b = __floats2bfloat162_rn(v.z, v.w);
    uint2 st; st.x = *(uint32_t*)&a; st.y = *(uint32_t*)&b;
    *(uint2*)(out + i) = st;
}

// fp32 [R][Cc] -> bf16 [Cc][R], batched over z
__global__ void trans_f2b(const float* __restrict__ in, bf16* __restrict__ out, int R, int Cc)
{
    __shared__ float t[32][33];
    size_t zo = (size_t)blockIdx.z * R * Cc;
    int c0 = blockIdx.x * 32, r0 = blockIdx.y * 32;
    int tx = threadIdx.x & 31, ty = threadIdx.x >> 5;
#pragma unroll
    for (int i = 0; i < 4; i++) {
        int rr = r0 + ty + i * 8, cc = c0 + tx;
        if (rr < R && cc < Cc) t[ty + i * 8][tx] = in[zo + (size_t)rr * Cc + cc];
    }
    __syncthreads();
#pragma unroll
    for (int i = 0; i < 4; i++) {
        int cc = c0 + ty + i * 8, rr = r0 + tx;
        if (cc < Cc && rr < R) out[zo + (size_t)cc * R + rr] = __float2bfloat16(t[tx][ty + i * 8]);
    }
}

// bf16 [R][Cc] -> bf16 [Cc][R], batched over z
__global__ void trans_b2b(const bf16* __restrict__ in, bf16* __restrict__ out, int R, int Cc)
{
    __shared__ bf16 t[32][34];
    size_t zo = (size_t)blockIdx.z * R * Cc;
    int c0 = blockIdx.x * 32, r0 = blockIdx.y * 32;
    int tx = threadIdx.x & 31, ty = threadIdx.x >> 5;
#pragma unroll
    for (int i = 0; i < 4; i++) {
        int rr = r0 + ty + i * 8, cc = c0 + tx;
        if (rr < R && cc < Cc) t[ty + i * 8][tx] = in[zo + (size_t)rr * Cc + cc];
    }
    __syncthreads();
#pragma unroll
    for (int i = 0; i < 4; i++) {
        int cc = c0 + ty + i * 8, rr = r0 + tx;
        if (cc < Cc && rr < R) out[zo + (size_t)cc * R + rr] = t[tx][ty + i * 8];
    }
}

__global__ void rowsum_k(const bf16* __restrict__ M, float* __restrict__ inv)
{
    int row = blockIdx.x;
    const bf162* p = (const bf162*)(M + (size_t)row * NPix);
    float s = 0.f;
    for (int j = threadIdx.x; j < NPix / 2; j += 256) {
        float2 v = __bfloat1622float2(p[j]);
        s += v.x + v.y;
    }
    __shared__ float ss[256];
    ss[threadIdx.x] = s; __syncthreads();
    for (int o = 128; o; o >>= 1) {
        if (threadIdx.x < o) ss[threadIdx.x] += ss[threadIdx.x + o];
        __syncthreads();
    }
    if (threadIdx.x == 0) inv[row] = 1.f / ss[0];
}

// Z_true = raw*iv ; gate = sigmoid(sum_c gw*Z_true) ; out = bf16(Z_true*gate)
__global__ void gate_k(const float* __restrict__ Z, const float* __restrict__ iv,
                       const float* __restrict__ gw, bf16* __restrict__ out)
{
    int b = blockIdx.z, pix = blockIdx.x * 256 + threadIdx.x;
    __shared__ float w[CC];
    for (int c = threadIdx.x; c < CC; c += 256) w[c] = gw[c];
    __syncthreads();
    if (pix >= NPix) return;
    const float* zp = Z + (size_t)b * CC * NPix + pix;
    bf16* op = out + (size_t)b * CC * NPix + pix;
    float gsum = 0.f;
    for (int c = 0; c < CC; c++) gsum += w[c] * zp[(size_t)c * NPix];
    float m = iv[b * NPix + pix];
    float mul = m / (1.f + __expf(-gsum * m));
    for (int c = 0; c < CC; c++) op[(size_t)c * NPix] = __float2bfloat16(zp[(size_t)c * NPix] * mul);
}

__global__ void im2col_k(const bf16* __restrict__ s0, const bf16* __restrict__ s1,
                         const bf16* __restrict__ s2, bf16* __restrict__ out, int Kd, int total)
{
    int idx = blockIdx.x * 256 + threadIdx.x;
    if (idx >= total) return;
    int segs = Kd >> 3;
    int ks = idx % segs, rest = idx / segs;
    int j = rest % NPix, b = rest / NPix;
    int h = j / 60, w = j - h * 60;
    alignas(16) bf16 v[8];
#pragma unroll
    for (int u = 0; u < 8; u++) {
        int k = ks * 8 + u;
        int ci = k / 9, rr = k - ci * 9;
        int kh = rr / 3, kw = rr - kh * 3;
        int ih = h + kh - 1, iw = w + kw - 1;
        bf16 x = __float2bfloat16(0.f);
        if ((unsigned)ih < 60u && (unsigned)iw < 60u) {
            int p = ih * 60 + iw;
            const bf16* sp = (ci < 256) ? s0 : ((ci < 512) ? s1 : s2);
            x = sp[(size_t)(b * CC + (ci & 255)) * NPix + p];
        }
        v[u] = x;
    }
    *(uint4*)(out + ((size_t)b * NPix + j) * Kd + ks * 8) = *(uint4*)v;
}

__global__ void bnstats_k(const float* __restrict__ x, const float* __restrict__ gam,
                          const float* __restrict__ bet, float* __restrict__ scale, float* __restrict__ shift)
{
    int c = blockIdx.x;
    float s = 0.f, q = 0.f;
    for (int b = 0; b < BB; b++) {
        const float* xp = x + (size_t)(b * CC + c) * NPix;
        for (int i = threadIdx.x; i < NPix; i += 256) { float v = xp[i]; s += v; q += v * v; }
    }
    __shared__ float rs[256], rq[256];
    rs[threadIdx.x] = s; rq[threadIdx.x] = q; __syncthreads();
    for (int o = 128; o; o >>= 1) {
        if (threadIdx.x < o) { rs[threadIdx.x] += rs[threadIdx.x + o]; rq[threadIdx.x] += rq[threadIdx.x + o]; }
        __syncthreads();
    }
    if (threadIdx.x == 0) {
        const float inv = 1.f / (BB * NPix);
        float mean = rs[0] * inv, var = rq[0] * inv - mean * mean;
        float sc = gam[c] * rsqrtf(var + 1e-5f);
        scale[c] = sc; shift[c] = bet[c] - mean * sc;
    }
}

__global__ void bncls_k(const float* __restrict__ x, const float* __restrict__ scale,
                        const float* __restrict__ shift, const float* __restrict__ cw,
                        const float* __restrict__ cb, float* __restrict__ y)
{
    int b = blockIdx.z, pix = blockIdx.x * 256 + threadIdx.x;
    __shared__ float sc[CC], sh[CC], w0[CC], w1[CC];
    for (int c = threadIdx.x; c < CC; c += 256) {
        sc[c] = scale[c]; sh[c] = shift[c]; w0[c] = cw[c]; w1[c] = cw[CC + c];
    }
    __syncthreads();
    if (pix >= NPix) return;
    const float* xp = x + (size_t)b * CC * NPix + pix;
    float a0 = cb[0], a1 = cb[1];
    for (int c = 0; c < CC; c++) {
        float v = fmaxf(xp[(size_t)c * NPix] * sc[c] + sh[c], 0.f);
        a0 += v * w0[c]; a1 += v * w1[c];
    }
    y[(size_t)(b * NCls + 0) * NPix + pix] = a0;
    y[(size_t)(b * NCls + 1) * NPix + pix] = a1;
}

__global__ void resize_k(float* __restrict__ out)
{
    const size_t per = (size_t)BB * NCls * HOUT * WOUT;
    size_t idx = (size_t)blockIdx.x * 256 + threadIdx.x;
    if (idx >= 2 * per) return;
    int t = idx >= per;
    size_t r = idx - (size_t)t * per;
    int x = (int)(r % WOUT); r /= WOUT;
    int y = (int)(r % HOUT); r /= HOUT;
    int kc = (int)(r % NCls); int b = (int)(r / NCls);
    const float* src = (t ? g_y2 : g_y1) + (size_t)(b * NCls + kc) * NPix;
    const float sc = 60.f / 473.f;
    float syf = (y + 0.5f) * sc - 0.5f, sxf = (x + 0.5f) * sc - 0.5f;
    float fy0 = floorf(syf), fx0 = floorf(sxf);
    float fy = syf - fy0, fx = sxf - fx0;
    int y0 = max((int)fy0, 0), x0 = max((int)fx0, 0);
    int y1i = min((int)fy0 + 1, 59), x1i = min((int)fx0 + 1, 59);
    float v00 = src[y0*60+x0], v01 = src[y0*60+x1i], v10 = src[y1i*60+x0], v11 = src[y1i*60+x1i];
    float vt = v00 + (v01 - v00) * fx, vb = v10 + (v11 - v10) * fx;
    out[idx] = 1.f / (1.f + __expf(-(vt + (vb - vt) * fy)));
}

extern "C" void kernel_launch(void* const* d_in, const int* in_sizes, int n_in,
                              void* d_out, int out_size)
{
    const float *V_a=(const float*)d_in[0], *V_b=(const float*)d_in[1], *D_a=(const float*)d_in[2];
    const float *W_e=(const float*)d_in[3], *gate_w=(const float*)d_in[4];
    const float *c1w=(const float*)d_in[5], *c2w=(const float*)d_in[6];
    const float *bn1g=(const float*)d_in[7], *bn1b=(const float*)d_in[8];
    const float *bn2g=(const float*)d_in[9], *bn2b=(const float*)d_in[10];
    const float *cl1w=(const float*)d_in[11], *cl1b=(const float*)d_in[12];
    const float *cl2w=(const float*)d_in[13], *cl2b=(const float*)d_in[14];
    float* out = (float*)d_out;

    bf16 *Vab,*Vbb,*Dab,*Web,*w1b,*w2b,*VaT,*VbT,*WvT,*E,*ET,*a1b,*a2b,*cb1,*cb2;
    float *a1f,*a2f,*x1,*x2,*ri,*ci,*s1,*h1,*s2,*h2,*y1,*y2;
    cudaGetSymbolAddress((void**)&Vab,g_Vab); cudaGetSymbolAddress((void**)&Vbb,g_Vbb);
    cudaGetSymbolAddress((void**)&Dab,g_Dab); cudaGetSymbolAddress((void**)&Web,g_Web);
    cudaGetSymbolAddress((void**)&w1b,g_w1b); cudaGetSymbolAddress((void**)&w2b,g_w2b);
    cudaGetSymbolAddress((void**)&VaT,g_VaT); cudaGetSymbolAddress((void**)&VbT,g_VbT);
    cudaGetSymbolAddress((void**)&WvT,g_WvT); cudaGetSymbolAddress((void**)&E,g_E);
    cudaGetSymbolAddress((void**)&ET,g_ET);   cudaGetSymbolAddress((void**)&a1b,g_att1b);
    cudaGetSymbolAddress((void**)&a2b,g_att2b); cudaGetSymbolAddress((void**)&cb1,g_cb1);
    cudaGetSymbolAddress((void**)&cb2,g_cb2); cudaGetSymbolAddress((void**)&a1f,g_att1f);
    cudaGetSymbolAddress((void**)&a2f,g_att2f); cudaGetSymbolAddress((void**)&x1,g_x1);
    cudaGetSymbolAddress((void**)&x2,g_x2);   cudaGetSymbolAddress((void**)&ri,g_rowinv);
    cudaGetSymbolAddress((void**)&ci,g_colinv); cudaGetSymbolAddress((void**)&s1,g_bnsc1);
    cudaGetSymbolAddress((void**)&h1,g_bnsh1); cudaGetSymbolAddress((void**)&s2,g_bnsc2);
    cudaGetSymbolAddress((void**)&h2,g_bnsh2); cudaGetSymbolAddress((void**)&y1,g_y1);
    cudaGetSymbolAddress((void**)&y2,g_y2);

    cudaFuncSetAttribute(bgemm<0>, cudaFuncAttributeMaxDynamicSharedMemorySize, GSMEM);
    cudaFuncSetAttribute(bgemm<1>, cudaFuncAttributeMaxDynamicSharedMemorySize, GSMEM);
    cudaFuncSetAttribute(bgemm<2>, cudaFuncAttributeMaxDynamicSharedMemorySize, GSMEM);

    const size_t CN = (size_t)CC * NPix, NN = (size_t)NPix * NPix, NCn = (size_t)NPix * CC;
    auto cg = [](int n){ return (n / 4 + 255) / 256; };

    // converts + transposes
    cvt_k<<<cg(BB*CC*NPix),256>>>(V_a, Vab, BB*CC*NPix);
    cvt_k<<<cg(BB*CC*NPix),256>>>(V_b, Vbb, BB*CC*NPix);
    cvt_k<<<cg(BB*CC*NPix),256>>>(D_a, Dab, BB*CC*NPix);
    cvt_k<<<cg(CC*CC),256>>>(W_e, Web, CC*CC);
    cvt_k<<<cg(CC*K1),256>>>(c1w, w1b, CC*K1);
    cvt_k<<<cg(CC*K2),256>>>(c2w, w2b, CC*K2);
    trans_f2b<<<dim3(113,8,BB),256>>>(V_a, VaT, CC, NPix);
    trans_f2b<<<dim3(113,8,BB),256>>>(V_b, VbT, CC, NPix);
    // WvT[n][d] = sum_c V_aT[n][c] * W_e[d][c]
    bgemm<1><<<dim3(2,29,BB),256,GSMEM>>>(VaT, Web, WvT, NPix, CC, CC, CC, CC, CC, NCn, 0, NCn);
    // E[n][m] = exp(sum_d WvT[n][d] * V_bT[m][d])
    bgemm<2><<<dim3(29,29,BB),256,GSMEM>>>(WvT, VbT, E, NPix, NPix, CC, CC, CC, NPix, NCn, NCn, NN);
    trans_b2b<<<dim3(113,113,BB),256>>>(E, ET, NPix, NPix);
    rowsum_k<<<BB*NPix,256>>>(E, ri);
    rowsum_k<<<BB*NPix,256>>>(ET, ci);
    // att2_raw[c][m] = sum_n V_a[c][n] * E[n][m]   (B = ET[m][n])
    bgemm<0><<<dim3(29,2,BB),256,GSMEM>>>(Vab, ET, a2f, CC, NPix, NPix, NPix, NPix, NPix, CN, NN, CN);
    // att1_raw[c][j] = sum_n V_b[c][n] * E[j][n]   (B = E[j][n])
    bgemm<0><<<dim3(29,2,BB),256,GSMEM>>>(Vbb, E, a1f, CC, NPix, NPix, NPix, NPix, NPix, CN, NN, CN);
    gate_k<<<dim3(15,1,BB),256>>>(a1f, ri, gate_w, a1b);
    gate_k<<<dim3(15,1,BB),256>>>(a2f, ci, gate_w, a2b);
    // im2col + convs
    int t1 = BB * NPix * (K1 / 8), t2 = BB * NPix * (K2 / 8);
    im2col_k<<<(t1+255)/256,256>>>(a1b, Vab, Dab, cb1, K1, t1);
    im2col_k<<<(t2+255)/256,256>>>(a2b, Vbb, Vbb, cb2, K2, t2);
    bgemm<0><<<dim3(29,2,BB),256,GSMEM>>>(w1b, cb1, x1, CC, NPix, K1, K1, K1, NPix, 0, (size_t)NPix*K1, CN);
    bgemm<0><<<dim3(29,2,BB),256,GSMEM>>>(w2b, cb2, x2, CC, NPix, K2, K2, K2, NPix, 0, (size_t)NPix*K2, CN);
    // BN + cls + resize
    bnstats_k<<<CC,256>>>(x1, bn1g, bn1b, s1, h1);
    bnstats_k<<<CC,256>>>(x2, bn2g, bn2b, s2, h2);
    bncls_k<<<dim3(15,1,BB),256>>>(x1, s1, h1, cl1w, cl1b, y1);
    bncls_k<<<dim3(15,1,BB),256>>>(x2, s2, h2, cl2w, cl2b, y2);
    const size_t total = 2ull * BB * NCls * HOUT * WOUT;
    resize_k<<<(int)((total+255)/256),256>>>(out);
}

// round 6
// speedup vs baseline: 4.6177x; 1.2348x over previous
#include <cuda_runtime.h>
#include <cuda_bf16.h>
#include <cstdint>
#include <math.h>

#define BB 2
#define CC 256
#define NPix 3600
#define NCls 2
#define HOUT 473
#define WOUT 473
typedef __nv_bfloat16 bf16;
typedef __nv_bfloat162 bf162;

__device__ bf16 g_Vab[BB*CC*NPix], g_Vbb[BB*CC*NPix];
__device__ bf16 g_Web[CC*CC];
__device__ bf16 g_wr1[9*CC*768], g_wr2[9*CC*512];
__device__ bf16 g_VaT[BB*NPix*CC], g_VbT[BB*NPix*CC], g_DaT[BB*NPix*CC], g_WvT[BB*NPix*CC];
__device__ bf16 g_E[(size_t)BB*NPix*NPix], g_ET[(size_t)BB*NPix*NPix];
__device__ bf16 g_a1Tb[BB*NPix*CC], g_a2Tb[BB*NPix*CC];
__device__ float g_a1Tf[BB*NPix*CC], g_a2Tf[BB*NPix*CC];
__device__ float g_x1T[BB*NPix*CC], g_x2T[BB*NPix*CC];
__device__ float g_rowinv[BB*NPix], g_colinv[BB*NPix];
__device__ float g_bp1[58*CC], g_bq1[58*CC], g_bp2[58*CC], g_bq2[58*CC];
__device__ float g_bnsc1[CC], g_bnsh1[CC], g_bnsc2[CC], g_bnsh2[CC];
__device__ float g_y1[BB*NCls*NPix], g_y2[BB*NCls*NPix];

__device__ __forceinline__ uint32_t smem_u32(const void* p){
    uint32_t a; asm("{ .reg .u64 t; cvta.to.shared.u64 t, %1; cvt.u32.u64 %0, t; }":"=r"(a):"l"(p)); return a;
}
__device__ __forceinline__ void cpa16(uint32_t d, const void* s, bool v){
    asm volatile("cp.async.cg.shared.global [%0],[%1],16,%2;"::"r"(d),"l"(s),"r"(v?16:0));
}
__device__ __forceinline__ void ldmx4(uint32_t* r, uint32_t a){
    asm volatile("ldmatrix.sync.aligned.m8n8.x4.shared.b16 {%0,%1,%2,%3},[%4];"
        :"=r"(r[0]),"=r"(r[1]),"=r"(r[2]),"=r"(r[3]):"r"(a));
}
__device__ __forceinline__ void mma_bf16(float* c, const uint32_t* a, const uint32_t* b){
    asm volatile("mma.sync.aligned.m16n8k16.row.col.f32.bf16.bf16.f32 "
        "{%0,%1,%2,%3},{%4,%5,%6,%7},{%8,%9},{%0,%1,%2,%3};"
        :"+f"(c[0]),"+f"(c[1]),"+f"(c[2]),"+f"(c[3])
        :"r"(a[0]),"r"(a[1]),"r"(a[2]),"r"(a[3]),"r"(b[0]),"r"(b[1]));
}

#define STG 20480
#define GSMEM (4*STG)

#define MMA_COMPUTE(ta, tb) \
    _Pragma("unroll") \
    for (int s = 0; s < 2; s++) { \
        uint32_t af[4][4], bq[4][2]; \
        _Pragma("unroll") \
        for (int mt = 0; mt < 4; mt++) \
            ldmx4(af[mt], (ta) + (uint32_t)((wm*64+mt*16+(g&1)*8+r8)*80 + (g>>1)*16 + s*32)); \
        _Pragma("unroll") \
        for (int np = 0; np < 2; np++) { \
            uint32_t t4[4]; \
            ldmx4(t4, (tb) + (uint32_t)((wn*32+np*16+(g>>1)*8+r8)*80 + (g&1)*16 + s*32)); \
            bq[np*2][0]=t4[0]; bq[np*2][1]=t4[1]; bq[np*2+1][0]=t4[2]; bq[np*2+1][1]=t4[3]; \
        } \
        _Pragma("unroll") \
        for (int mt = 0; mt < 4; mt++) \
            _Pragma("unroll") \
            for (int nt = 0; nt < 4; nt++) \
                mma_bf16(acc[mt][nt], af[mt], bq[nt]); \
    }

// C[M,N] = A[M,K]*B^T, A=[i][k], B=[j][k]. OUTM: 0=f32, 2=exp->bf16, 1=bf16
template<int OUTM>
__global__ void __launch_bounds__(256)
bgemm(const bf16* __restrict__ A, const bf16* __restrict__ B, void* __restrict__ Cv,
      int Md, int Nd, int Kd, int lda, int ldb, int ldc, size_t sA, size_t sB, size_t sC)
{
    extern __shared__ char smc[];
    const int z = blockIdx.z;
    A += (size_t)z*sA; B += (size_t)z*sB;
    const int m0 = blockIdx.y*128, n0 = blockIdx.x*128;
    const int tid = threadIdx.x, lane = tid&31, wid = tid>>5;
    const int wm = wid>>2, wn = wid&3, g = lane>>3, r8 = lane&7;
    uint32_t sb = smem_u32(smc);
    float acc[4][4][4];
#pragma unroll
    for (int a=0;a<4;a++)
#pragma unroll
        for (int b=0;b<4;b++)
#pragma unroll
            for (int c=0;c<4;c++) acc[a][b][c]=0.f;
    const int NC = (Kd+31)>>5;

    auto LD = [&](int c){
        if (c < NC) {
            uint32_t st = sb + (c&3)*STG;
            int k0 = c<<5;
#pragma unroll
            for (int q=0;q<2;q++){
                int idx=tid*2+q, row=idx>>2, sg=idx&3;
                bool v = (m0+row)<Md && (k0+sg*8)<Kd;
                cpa16(st+row*80+sg*16, A + (v?((size_t)(m0+row)*lda+k0+sg*8):0), v);
            }
#pragma unroll
            for (int q=0;q<2;q++){
                int idx=tid*2+q, row=idx>>2, sg=idx&3;
                bool v = (n0+row)<Nd && (k0+sg*8)<Kd;
                cpa16(st+10240+row*80+sg*16, B + (v?((size_t)(n0+row)*ldb+k0+sg*8):0), v);
            }
        }
        asm volatile("cp.async.commit_group;":::"memory");
    };
    LD(0); LD(1); LD(2);
    for (int c=0;c<NC;c++){
        asm volatile("cp.async.wait_group 2;":::"memory");
        __syncthreads();
        uint32_t ta = sb+(c&3)*STG, tb = ta+10240;
        MMA_COMPUTE(ta, tb);
        LD(c+3);
    }
#pragma unroll
    for (int mt=0;mt<4;mt++){
        int r0 = m0+wm*64+mt*16+(lane>>2);
#pragma unroll
        for (int nt=0;nt<4;nt++){
            int c0 = n0+wn*32+nt*8+(lane&3)*2;
            if (c0 >= Nd) continue;
            float x0=acc[mt][nt][0],x1=acc[mt][nt][1],x2=acc[mt][nt][2],x3=acc[mt][nt][3];
            if (OUTM==2){x0=__expf(x0);x1=__expf(x1);x2=__expf(x2);x3=__expf(x3);}
            if (OUTM==0){
                float* C=(float*)Cv+(size_t)z*sC;
                if (r0<Md)     *(float2*)&C[(size_t)r0*ldc+c0]     = make_float2(x0,x1);
                if (r0+8<Md)   *(float2*)&C[(size_t)(r0+8)*ldc+c0] = make_float2(x2,x3);
            } else {
                bf16* C=(bf16*)Cv+(size_t)z*sC;
                if (r0<Md)     *(bf162*)&C[(size_t)r0*ldc+c0]     = __floats2bfloat162_rn(x0,x1);
                if (r0+8<Md)   *(bf162*)&C[(size_t)(r0+8)*ldc+c0] = __floats2bfloat162_rn(x2,x3);
            }
        }
    }
}

// 3x3 conv as 9 accumulated shifted GEMMs. C[j][co] += srcT[j+off][ci]*Wr[co][ci]
template<int SRCS>
__global__ void __launch_bounds__(256)
convg(const bf16* __restrict__ s0, const bf16* __restrict__ s1, const bf16* __restrict__ s2,
      const bf16* __restrict__ W, float* __restrict__ Cout)
{
    extern __shared__ char smc[];
    const int b = blockIdx.z;
    const size_t so = (size_t)b*NPix*CC;
    const int m0 = blockIdx.y*128, n0 = blockIdx.x*128;
    const int tid = threadIdx.x, lane = tid&31, wid = tid>>5;
    const int wm = wid>>2, wn = wid&3, g = lane>>3, r8 = lane&7;
    uint32_t sb = smem_u32(smc);
    const int LDB = SRCS*256, KPC = SRCS*8, NC = 9*KPC;
    float acc[4][4][4];
#pragma unroll
    for (int a=0;a<4;a++)
#pragma unroll
        for (int bq2=0;bq2<4;bq2++)
#pragma unroll
            for (int c=0;c<4;c++) acc[a][bq2][c]=0.f;

    auto LD = [&](int vc){
        if (vc < NC) {
            uint32_t st = sb + (vc&3)*STG;
            int rr = vc/KPC, kc = vc - rr*KPC;
            int dh = rr/3 - 1, dw = rr - (rr/3)*3 - 1;
            int off = dh*60 + dw;
            int srcSel = kc>>3, cil = (kc&7)*32, cig = kc*32;
            const bf16* sp = (srcSel==0)?s0:((srcSel==1)?s1:s2);
#pragma unroll
            for (int q=0;q<2;q++){
                int idx=tid*2+q, row=idx>>2, sg=idx&3;
                int j=m0+row, h=j/60, w=j-h*60;
                bool v = (j<NPix) && ((unsigned)(h+dh)<60u) && ((unsigned)(w+dw)<60u);
                const bf16* ap = sp + so + (size_t)(j+off)*CC + cil + sg*8;
                cpa16(st+row*80+sg*16, v?ap:(sp+so), v);
            }
#pragma unroll
            for (int q=0;q<2;q++){
                int idx=tid*2+q, row=idx>>2, sg=idx&3;
                const bf16* bp = W + (size_t)rr*CC*LDB + (size_t)(n0+row)*LDB + cig + sg*8;
                cpa16(st+10240+row*80+sg*16, bp, true);
            }
        }
        asm volatile("cp.async.commit_group;":::"memory");
    };
    LD(0); LD(1); LD(2);
    for (int c=0;c<NC;c++){
        asm volatile("cp.async.wait_group 2;":::"memory");
        __syncthreads();
        uint32_t ta = sb+(c&3)*STG, tb = ta+10240;
        MMA_COMPUTE(ta, tb);
        LD(c+3);
    }
    float* C = Cout + so;
#pragma unroll
    for (int mt=0;mt<4;mt++){
        int r0 = m0+wm*64+mt*16+(lane>>2);
#pragma unroll
        for (int nt=0;nt<4;nt++){
            int c0 = n0+wn*32+nt*8+(lane&3)*2;
            if (r0<NPix)   *(float2*)&C[(size_t)r0*CC+c0]     = make_float2(acc[mt][nt][0],acc[mt][nt][1]);
            if (r0+8<NPix) *(float2*)&C[(size_t)(r0+8)*CC+c0] = make_float2(acc[mt][nt][2],acc[mt][nt][3]);
        }
    }
}

__global__ void cvt_k(const float* __restrict__ in, bf16* __restrict__ out, int n)
{
    int i = (blockIdx.x*256+threadIdx.x)*4;
    if (i >= n) return;
    float4 v = *(const float4*)(in+i);
    bf162 a = __floats2bfloat162_rn(v.x,v.y), b = __floats2bfloat162_rn(v.z,v.w);
    uint2 st; st.x=*(uint32_t*)&a; st.y=*(uint32_t*)&b;
    *(uint2*)(out+i) = st;
}

__global__ void trans_f2b(const float* __restrict__ in, bf16* __restrict__ out, int R, int Cc)
{
    __shared__ float t[32][33];
    size_t zo = (size_t)blockIdx.z*R*Cc;
    int c0 = blockIdx.x*32, r0 = blockIdx.y*32;
    int tx = threadIdx.x&31, ty = threadIdx.x>>5;
#pragma unroll
    for (int i=0;i<4;i++){
        int rr=r0+ty+i*8, cc=c0+tx;
        if (rr<R && cc<Cc) t[ty+i*8][tx] = in[zo+(size_t)rr*Cc+cc];
    }
    __syncthreads();
#pragma unroll
    for (int i=0;i<4;i++){
        int cc=c0+ty+i*8, rr=r0+tx;
        if (cc<Cc && rr<R) out[zo+(size_t)cc*R+rr] = __float2bfloat16(t[tx][ty+i*8]);
    }
}

__global__ void trans_b2b(const bf16* __restrict__ in, bf16* __restrict__ out, int R, int Cc)
{
    __shared__ bf16 t[32][34];
    size_t zo = (size_t)blockIdx.z*R*Cc;
    int c0 = blockIdx.x*32, r0 = blockIdx.y*32;
    int tx = threadIdx.x&31, ty = threadIdx.x>>5;
#pragma unroll
    for (int i=0;i<4;i++){
        int rr=r0+ty+i*8, cc=c0+tx;
        if (rr<R && cc<Cc) t[ty+i*8][tx] = in[zo+(size_t)rr*Cc+cc];
    }
    __syncthreads();
#pragma unroll
    for (int i=0;i<4;i++){
        int cc=c0+ty+i*8, rr=r0+tx;
        if (cc<Cc && rr<R) out[zo+(size_t)cc*R+rr] = t[tx][ty+i*8];
    }
}

__global__ void repack_k(const float* __restrict__ w, bf16* __restrict__ out, int CI, int total)
{
    int idx = blockIdx.x*256+threadIdx.x;
    if (idx >= total) return;
    int r = idx/(CC*CI), rem = idx - r*(CC*CI);
    int co = rem/CI, ci = rem - co*CI;
    out[idx] = __float2bfloat16(w[(size_t)co*CI*9 + ci*9 + r]);
}

__global__ void rowsum_k(const bf16* __restrict__ M, float* __restrict__ inv)
{
    int row = blockIdx.x;
    const bf162* p = (const bf162*)(M + (size_t)row*NPix);
    float s = 0.f;
    for (int j=threadIdx.x; j<NPix/2; j+=256){ float2 v=__bfloat1622float2(p[j]); s+=v.x+v.y; }
    __shared__ float ss[256];
    ss[threadIdx.x]=s; __syncthreads();
    for (int o=128;o;o>>=1){ if (threadIdx.x<o) ss[threadIdx.x]+=ss[threadIdx.x+o]; __syncthreads(); }
    if (threadIdx.x==0) inv[row] = 1.f/ss[0];
}

__global__ void gatew_k(const float* __restrict__ Z, const float* __restrict__ iv,
                        const float* __restrict__ gw, bf16* __restrict__ out)
{
    __shared__ float w[CC];
    int tid = threadIdx.x;
    for (int c=tid;c<CC;c+=256) w[c]=gw[c];
    __syncthreads();
    int lane=tid&31, wid=tid>>5;
    int p = blockIdx.x*8+wid, b = blockIdx.y;
    const float* zp = Z + ((size_t)b*NPix+p)*CC + lane*8;
    float4 u0=*(const float4*)zp, u1=*(const float4*)(zp+4);
    float vv[8]={u0.x,u0.y,u0.z,u0.w,u1.x,u1.y,u1.z,u1.w};
    int c8=lane*8;
    float d=0.f;
#pragma unroll
    for (int u=0;u<8;u++) d += vv[u]*w[c8+u];
#pragma unroll
    for (int o=16;o;o>>=1) d += __shfl_xor_sync(~0u,d,o);
    float m = iv[b*NPix+p];
    float mul = m/(1.f+__expf(-d*m));
    bf162 o0=__floats2bfloat162_rn(vv[0]*mul,vv[1]*mul), o1=__floats2bfloat162_rn(vv[2]*mul,vv[3]*mul);
    bf162 o2=__floats2bfloat162_rn(vv[4]*mul,vv[5]*mul), o3=__floats2bfloat162_rn(vv[6]*mul,vv[7]*mul);
    uint4 st; st.x=*(uint32_t*)&o0; st.y=*(uint32_t*)&o1; st.z=*(uint32_t*)&o2; st.w=*(uint32_t*)&o3;
    *(uint4*)(out + ((size_t)b*NPix+p)*CC + c8) = st;
}

__global__ void bnpart_k(const float* __restrict__ x, float* __restrict__ ps, float* __restrict__ pq)
{
    int c = threadIdx.x, b = blockIdx.y, blk = blockIdx.x;
    int n0 = blk*128, nend = min(n0+128, NPix);
    const float* xp = x + (size_t)b*NPix*CC + c;
    float s=0.f, q=0.f;
    for (int n=n0;n<nend;n++){ float v=xp[(size_t)n*CC]; s+=v; q+=v*v; }
    int p = b*29+blk;
    ps[p*CC+c]=s; pq[p*CC+c]=q;
}

__global__ void bncomb_k(const float* __restrict__ ps, const float* __restrict__ pq,
                         const float* __restrict__ gam, const float* __restrict__ bet,
                         float* __restrict__ sc, float* __restrict__ sh)
{
    int c = threadIdx.x;
    float s=0.f, q=0.f;
    for (int p=0;p<58;p++){ s+=ps[p*CC+c]; q+=pq[p*CC+c]; }
    const float inv = 1.f/(BB*NPix);
    float mean=s*inv, var=q*inv-mean*mean;
    float k = gam[c]*rsqrtf(var+1e-5f);
    sc[c]=k; sh[c]=bet[c]-mean*k;
}

__global__ void bncls_k(const float* __restrict__ x, const float* __restrict__ sc,
                        const float* __restrict__ sh, const float* __restrict__ cw,
                        const float* __restrict__ cb, float* __restrict__ y)
{
    __shared__ float ssc[CC], ssh[CC], w0[CC], w1[CC];
    int tid = threadIdx.x;
    for (int c=tid;c<CC;c+=256){ ssc[c]=sc[c]; ssh[c]=sh[c]; w0[c]=cw[c]; w1[c]=cw[CC+c]; }
    __syncthreads();
    int lane=tid&31, wid=tid>>5;
    int p = blockIdx.x*8+wid, b = blockIdx.y;
    const float* xp = x + ((size_t)b*NPix+p)*CC + lane*8;
    float4 u0=*(const float4*)xp, u1=*(const float4*)(xp+4);
    float vv[8]={u0.x,u0.y,u0.z,u0.w,u1.x,u1.y,u1.z,u1.w};
    int c8=lane*8;
    float a0=0.f, a1=0.f;
#pragma unroll
    for (int u=0;u<8;u++){
        float v = fmaxf(vv[u]*ssc[c8+u]+ssh[c8+u], 0.f);
        a0 += v*w0[c8+u]; a1 += v*w1[c8+u];
    }
#pragma unroll
    for (int o=16;o;o>>=1){ a0+=__shfl_xor_sync(~0u,a0,o); a1+=__shfl_xor_sync(~0u,a1,o); }
    if (lane==0){
        y[(size_t)(b*NCls+0)*NPix+p] = a0+cb[0];
        y[(size_t)(b*NCls+1)*NPix+p] = a1+cb[1];
    }
}

__global__ void resize_k(float* __restrict__ out)
{
    const size_t per = (size_t)BB*NCls*HOUT*WOUT;
    size_t idx = (size_t)blockIdx.x*256+threadIdx.x;
    if (idx >= 2*per) return;
    int t = idx >= per;
    size_t r = idx - (size_t)t*per;
    int x=(int)(r%WOUT); r/=WOUT;
    int y=(int)(r%HOUT); r/=HOUT;
    int kc=(int)(r%NCls); int b=(int)(r/NCls);
    const float* src = (t?g_y2:g_y1) + (size_t)(b*NCls+kc)*NPix;
    const float sc = 60.f/473.f;
    float syf=(y+0.5f)*sc-0.5f, sxf=(x+0.5f)*sc-0.5f;
    float fy0=floorf(syf), fx0=floorf(sxf);
    float fy=syf-fy0, fx=sxf-fx0;
    int y0=max((int)fy0,0), x0=max((int)fx0,0);
    int y1i=min((int)fy0+1,59), x1i=min((int)fx0+1,59);
    float v00=src[y0*60+x0], v01=src[y0*60+x1i], v10=src[y1i*60+x0], v11=src[y1i*60+x1i];
    float vt=v00+(v01-v00)*fx, vb=v10+(v11-v10)*fx;
    out[idx] = 1.f/(1.f+__expf(-(vt+(vb-vt)*fy)));
}

extern "C" void kernel_launch(void* const* d_in, const int* in_sizes, int n_in,
                              void* d_out, int out_size)
{
    const float *V_a=(const float*)d_in[0], *V_b=(const float*)d_in[1], *D_a=(const float*)d_in[2];
    const float *W_e=(const float*)d_in[3], *gate_w=(const float*)d_in[4];
    const float *c1w=(const float*)d_in[5], *c2w=(const float*)d_in[6];
    const float *bn1g=(const float*)d_in[7], *bn1b=(const float*)d_in[8];
    const float *bn2g=(const float*)d_in[9], *bn2b=(const float*)d_in[10];
    const float *cl1w=(const float*)d_in[11], *cl1b=(const float*)d_in[12];
    const float *cl2w=(const float*)d_in[13], *cl2b=(const float*)d_in[14];
    float* out = (float*)d_out;

    bf16 *Vab,*Vbb,*Web,*wr1,*wr2,*VaT,*VbT,*DaT,*WvT,*E,*ET,*a1b,*a2b;
    float *a1f,*a2f,*x1T,*x2T,*ri,*ci,*bp1,*bq1,*bp2,*bq2,*s1,*h1,*s2,*h2,*y1,*y2;
    cudaGetSymbolAddress((void**)&Vab,g_Vab);  cudaGetSymbolAddress((void**)&Vbb,g_Vbb);
    cudaGetSymbolAddress((void**)&Web,g_Web);  cudaGetSymbolAddress((void**)&wr1,g_wr1);
    cudaGetSymbolAddress((void**)&wr2,g_wr2);  cudaGetSymbolAddress((void**)&VaT,g_VaT);
    cudaGetSymbolAddress((void**)&VbT,g_VbT);  cudaGetSymbolAddress((void**)&DaT,g_DaT);
    cudaGetSymbolAddress((void**)&WvT,g_WvT);  cudaGetSymbolAddress((void**)&E,g_E);
    cudaGetSymbolAddress((void**)&ET,g_ET);
    cudaGetSymbolAddress((void**)&a1b,g_a1Tb); cudaGetSymbolAddress((void**)&a2b,g_a2Tb);
    cudaGetSymbolAddress((void**)&a1f,g_a1Tf); cudaGetSymbolAddress((void**)&a2f,g_a2Tf);
    cudaGetSymbolAddress((void**)&x1T,g_x1T);  cudaGetSymbolAddress((void**)&x2T,g_x2T);
    cudaGetSymbolAddress((void**)&ri,g_rowinv);cudaGetSymbolAddress((void**)&ci,g_colinv);
    cudaGetSymbolAddress((void**)&bp1,g_bp1);  cudaGetSymbolAddress((void**)&bq1,g_bq1);
    cudaGetSymbolAddress((void**)&bp2,g_bp2);  cudaGetSymbolAddress((void**)&bq2,g_bq2);
    cudaGetSymbolAddress((void**)&s1,g_bnsc1); cudaGetSymbolAddress((void**)&h1,g_bnsh1);
    cudaGetSymbolAddress((void**)&s2,g_bnsc2); cudaGetSymbolAddress((void**)&h2,g_bnsh2);
    cudaGetSymbolAddress((void**)&y1,g_y1);    cudaGetSymbolAddress((void**)&y2,g_y2);

    cudaFuncSetAttribute(bgemm<0>, cudaFuncAttributeMaxDynamicSharedMemorySize, GSMEM);
    cudaFuncSetAttribute(bgemm<1>, cudaFuncAttributeMaxDynamicSharedMemorySize, GSMEM);
    cudaFuncSetAttribute(bgemm<2>, cudaFuncAttributeMaxDynamicSharedMemorySize, GSMEM);
    cudaFuncSetAttribute(convg<3>, cudaFuncAttributeMaxDynamicSharedMemorySize, GSMEM);
    cudaFuncSetAttribute(convg<2>, cudaFuncAttributeMaxDynamicSharedMemorySize, GSMEM);

    const size_t CN=(size_t)CC*NPix, NN=(size_t)NPix*NPix, NCn=(size_t)NPix*CC;
    auto cg = [](int n){ return (n/4+255)/256; };

    cvt_k<<<cg(BB*CC*NPix),256>>>(V_a, Vab, BB*CC*NPix);
    cvt_k<<<cg(BB*CC*NPix),256>>>(V_b, Vbb, BB*CC*NPix);
    cvt_k<<<cg(CC*CC),256>>>(W_e, Web, CC*CC);
    trans_f2b<<<dim3(113,8,BB),256>>>(V_a, VaT, CC, NPix);
    trans_f2b<<<dim3(113,8,BB),256>>>(V_b, VbT, CC, NPix);
    trans_f2b<<<dim3(113,8,BB),256>>>(D_a, DaT, CC, NPix);
    repack_k<<<(9*CC*768+255)/256,256>>>(c1w, wr1, 768, 9*CC*768);
    repack_k<<<(9*CC*512+255)/256,256>>>(c2w, wr2, 512, 9*CC*512);
    // WvT[n][d] = sum_c VaT[n][c]*W_e[d][c]
    bgemm<1><<<dim3(2,29,BB),256,GSMEM>>>(VaT, Web, WvT, NPix, CC, CC, CC, CC, CC, NCn, 0, NCn);
    // E[n][m] = exp(sum_d WvT[n][d]*VbT[m][d])
    bgemm<2><<<dim3(29,29,BB),256,GSMEM>>>(WvT, VbT, E, NPix, NPix, CC, CC, CC, NPix, NCn, NCn, NN);
    trans_b2b<<<dim3(113,113,BB),256>>>(E, ET, NPix, NPix);
    rowsum_k<<<BB*NPix,256>>>(E, ri);
    rowsum_k<<<BB*NPix,256>>>(ET, ci);
    // att1T[j][c] = sum_m E[j][m]*Vb[c][m] ; att2T[m][c] = sum_n ET[m][n]*Va[c][n]
    bgemm<0><<<dim3(2,29,BB),256,GSMEM>>>(E,  Vbb, a1f, NPix, CC, NPix, NPix, NPix, CC, NN, CN, NCn);
    bgemm<0><<<dim3(2,29,BB),256,GSMEM>>>(ET, Vab, a2f, NPix, CC, NPix, NPix, NPix, CC, NN, CN, NCn);
    gatew_k<<<dim3(450,BB),256>>>(a1f, ri, gate_w, a1b);
    gatew_k<<<dim3(450,BB),256>>>(a2f, ci, gate_w, a2b);
    // convs: 9 shifted accumulated GEMMs, sources [n][c]
    convg<3><<<dim3(2,29,BB),256,GSMEM>>>(a1b, VaT, DaT, wr1, x1T);
    convg<2><<<dim3(2,29,BB),256,GSMEM>>>(a2b, VbT, VbT, wr2, x2T);
    // BN + cls
    bnpart_k<<<dim3(29,BB),256>>>(x1T, bp1, bq1);
    bnpart_k<<<dim3(29,BB),256>>>(x2T, bp2, bq2);
    bncomb_k<<<1,256>>>(bp1, bq1, bn1g, bn1b, s1, h1);
    bncomb_k<<<1,256>>>(bp2, bq2, bn2g, bn2b, s2, h2);
    bncls_k<<<dim3(450,BB),256>>>(x1T, s1, h1, cl1w, cl1b, y1);
    bncls_k<<<dim3(450,BB),256>>>(x2T, s2, h2, cl2w, cl2b, y2);
    const size_t total = 2ull*BB*NCls*HOUT*WOUT;
    resize_k<<<(int)((total+255)/256),256>>>(out);
}

// round 7
// speedup vs baseline: 5.7925x; 1.2544x over previous
#include <cuda_runtime.h>
#include <cuda_bf16.h>
#include <cstdint>
#include <math.h>

#define BB 2
#define CC 256
#define NPix 3600
#define NCls 2
#define HOUT 473
#define WOUT 473
typedef __nv_bfloat16 bf16;
typedef __nv_bfloat162 bf162;

static const size_t CN = (size_t)CC*NPix, NN = (size_t)NPix*NPix, NCn = (size_t)NPix*CC;

__device__ bf16 g_Vab[BB*CC*NPix], g_Vbb[BB*CC*NPix];
__device__ bf16 g_Web[CC*CC];
__device__ bf16 g_wr1[9*CC*768], g_wr2[9*CC*512];
__device__ bf16 g_VaT[BB*NPix*CC], g_VbT[BB*NPix*CC], g_DaT[BB*NPix*CC], g_WvT[BB*NPix*CC];
__device__ bf16 g_E[(size_t)BB*NPix*NPix], g_ET[(size_t)BB*NPix*NPix];
__device__ bf16 g_a1Tb[BB*NPix*CC], g_a2Tb[BB*NPix*CC];
__device__ float g_a1Tf[BB*NPix*CC], g_a2Tf[BB*NPix*CC];
__device__ float g_x1T[BB*NPix*CC], g_x2T[BB*NPix*CC];
__device__ float g_rowinv[BB*NPix], g_colinv[BB*NPix];
__device__ float g_bp[2*58*CC], g_bq[2*58*CC];
__device__ float g_bnsc[2*CC], g_bnsh[2*CC];
__device__ float g_y1[BB*NCls*NPix], g_y2[BB*NCls*NPix];

__device__ __forceinline__ uint32_t smem_u32(const void* p){
    uint32_t a; asm("{ .reg .u64 t; cvta.to.shared.u64 t, %1; cvt.u32.u64 %0, t; }":"=r"(a):"l"(p)); return a;
}
__device__ __forceinline__ void cpa16(uint32_t d, const void* s, bool v){
    asm volatile("cp.async.cg.shared.global [%0],[%1],16,%2;"::"r"(d),"l"(s),"r"(v?16:0));
}
__device__ __forceinline__ void ldmx4(uint32_t* r, uint32_t a){
    asm volatile("ldmatrix.sync.aligned.m8n8.x4.shared.b16 {%0,%1,%2,%3},[%4];"
        :"=r"(r[0]),"=r"(r[1]),"=r"(r[2]),"=r"(r[3]):"r"(a));
}
__device__ __forceinline__ void mma_bf16(float* c, const uint32_t* a, const uint32_t* b){
    asm volatile("mma.sync.aligned.m16n8k16.row.col.f32.bf16.bf16.f32 "
        "{%0,%1,%2,%3},{%4,%5,%6,%7},{%8,%9},{%0,%1,%2,%3};"
        :"+f"(c[0]),"+f"(c[1]),"+f"(c[2]),"+f"(c[3])
        :"r"(a[0]),"r"(a[1]),"r"(a[2]),"r"(a[3]),"r"(b[0]),"r"(b[1]));
}

#define STG 20480
#define GSMEM (4*STG)

#define MMA_COMPUTE(ta, tb) \
    _Pragma("unroll") \
    for (int s = 0; s < 2; s++) { \
        uint32_t af[4][4], bq[4][2]; \
        _Pragma("unroll") \
        for (int mt = 0; mt < 4; mt++) \
            ldmx4(af[mt], (ta) + (uint32_t)((wm*64+mt*16+(g&1)*8+r8)*80 + (g>>1)*16 + s*32)); \
        _Pragma("unroll") \
        for (int np = 0; np < 2; np++) { \
            uint32_t t4[4]; \
            ldmx4(t4, (tb) + (uint32_t)((wn*32+np*16+(g>>1)*8+r8)*80 + (g&1)*16 + s*32)); \
            bq[np*2][0]=t4[0]; bq[np*2][1]=t4[1]; bq[np*2+1][0]=t4[2]; bq[np*2+1][1]=t4[3]; \
        } \
        _Pragma("unroll") \
        for (int mt = 0; mt < 4; mt++) \
            _Pragma("unroll") \
            for (int nt = 0; nt < 4; nt++) \
                mma_bf16(acc[mt][nt], af[mt], bq[nt]); \
    }

// generic body: C[M,N]=A[M,K]*B^T, A=[i][k], B=[j][k]. OUTM: 0=f32, 1=bf16, 2=exp->bf16
template<int OUTM>
__device__ __forceinline__ void gbody(const bf16* __restrict__ A, const bf16* __restrict__ B,
    void* __restrict__ Cv, int Md, int Nd, int Kd, int lda, int ldb, int ldc, int m0, int n0)
{
    extern __shared__ char smc[];
    const int tid = threadIdx.x, lane = tid&31, wid = tid>>5;
    const int wm = wid>>2, wn = wid&3, g = lane>>3, r8 = lane&7;
    uint32_t sb = smem_u32(smc);
    float acc[4][4][4];
#pragma unroll
    for (int a=0;a<4;a++)
#pragma unroll
        for (int b=0;b<4;b++)
#pragma unroll
            for (int c=0;c<4;c++) acc[a][b][c]=0.f;
    const int NC = (Kd+31)>>5;

    auto LD = [&](int c){
        if (c < NC) {
            uint32_t st = sb + (c&3)*STG;
            int k0 = c<<5;
#pragma unroll
            for (int q=0;q<2;q++){
                int idx=tid*2+q, row=idx>>2, sg=idx&3;
                bool v = (m0+row)<Md && (k0+sg*8)<Kd;
                cpa16(st+row*80+sg*16, A + (v?((size_t)(m0+row)*lda+k0+sg*8):0), v);
            }
#pragma unroll
            for (int q=0;q<2;q++){
                int idx=tid*2+q, row=idx>>2, sg=idx&3;
                bool v = (n0+row)<Nd && (k0+sg*8)<Kd;
                cpa16(st+10240+row*80+sg*16, B + (v?((size_t)(n0+row)*ldb+k0+sg*8):0), v);
            }
        }
        asm volatile("cp.async.commit_group;":::"memory");
    };
    LD(0); LD(1); LD(2);
    for (int c=0;c<NC;c++){
        asm volatile("cp.async.wait_group 2;":::"memory");
        __syncthreads();
        uint32_t ta = sb+(c&3)*STG, tb = ta+10240;
        MMA_COMPUTE(ta, tb);
        LD(c+3);
    }
#pragma unroll
    for (int mt=0;mt<4;mt++){
        int r0 = m0+wm*64+mt*16+(lane>>2);
#pragma unroll
        for (int nt=0;nt<4;nt++){
            int c0 = n0+wn*32+nt*8+(lane&3)*2;
            if (c0 >= Nd) continue;
            float x0=acc[mt][nt][0],x1=acc[mt][nt][1],x2=acc[mt][nt][2],x3=acc[mt][nt][3];
            if (OUTM==2){x0=__expf(x0);x1=__expf(x1);x2=__expf(x2);x3=__expf(x3);}
            if (OUTM==0){
                float* C=(float*)Cv;
                if (r0<Md)   *(float2*)&C[(size_t)r0*ldc+c0]     = make_float2(x0,x1);
                if (r0+8<Md) *(float2*)&C[(size_t)(r0+8)*ldc+c0] = make_float2(x2,x3);
            } else {
                bf16* C=(bf16*)Cv;
                if (r0<Md)   *(bf162*)&C[(size_t)r0*ldc+c0]     = __floats2bfloat162_rn(x0,x1);
                if (r0+8<Md) *(bf162*)&C[(size_t)(r0+8)*ldc+c0] = __floats2bfloat162_rn(x2,x3);
            }
        }
    }
}

template<int OUTM>
__global__ void __launch_bounds__(256,2)
bgemm(const bf16* __restrict__ A, const bf16* __restrict__ B, void* __restrict__ Cv,
      int Md, int Nd, int Kd, int lda, int ldb, int ldc, size_t sA, size_t sB, size_t sC)
{
    const int z = blockIdx.z;
    void* C = (OUTM==0) ? (void*)((float*)Cv+(size_t)z*sC) : (void*)((bf16*)Cv+(size_t)z*sC);
    gbody<OUTM>(A+(size_t)z*sA, B+(size_t)z*sB, C, Md, Nd, Kd, lda, ldb, ldc,
                blockIdx.y*128, blockIdx.x*128);
}

// both Z GEMMs in one launch: z=0,1 -> att1 (A=E,B=Vbb), z=2,3 -> att2 (A=ET,B=Vab)
__global__ void __launch_bounds__(256,2)
zpair(const bf16* __restrict__ E, const bf16* __restrict__ ET,
      const bf16* __restrict__ Vab, const bf16* __restrict__ Vbb,
      float* __restrict__ a1f, float* __restrict__ a2f)
{
    int z = blockIdx.z, br = z>>1, b = z&1;
    const bf16* A = (br?ET:E) + (size_t)b*(size_t)NPix*NPix;
    const bf16* B = (br?Vab:Vbb) + (size_t)b*(size_t)CC*NPix;
    float* C = (br?a2f:a1f) + (size_t)b*(size_t)NPix*CC;
    gbody<0>(A, B, C, NPix, CC, NPix, NPix, NPix, CC, blockIdx.y*128, blockIdx.x*128);
}

// both convs in one launch: z=0,1 conv1 (3 srcs), z=2,3 conv2 (2 srcs)
__global__ void __launch_bounds__(256,2)
convpair(const bf16* __restrict__ a1b, const bf16* __restrict__ a2b,
         const bf16* __restrict__ VaT, const bf16* __restrict__ VbT, const bf16* __restrict__ DaT,
         const bf16* __restrict__ wr1, const bf16* __restrict__ wr2,
         float* __restrict__ x1T, float* __restrict__ x2T)
{
    extern __shared__ char smc[];
    int zz = blockIdx.z, br = zz>>1, b = zz&1;
    const bf16 *s0 = br?a2b:a1b, *s1 = br?VbT:VaT, *s2 = br?VbT:DaT;
    const bf16 *W = br?wr2:wr1;
    float* out = br?x2T:x1T;
    const int SR = br?2:3;
    const int LDB = SR*256, KPC = SR*8, NC = 9*KPC;
    const size_t so = (size_t)b*(size_t)NPix*CC;
    const int m0 = blockIdx.y*128, n0 = blockIdx.x*128;
    const int tid = threadIdx.x, lane = tid&31, wid = tid>>5;
    const int wm = wid>>2, wn = wid&3, g = lane>>3, r8 = lane&7;
    uint32_t sb = smem_u32(smc);
    float acc[4][4][4];
#pragma unroll
    for (int a=0;a<4;a++)
#pragma unroll
        for (int bb=0;bb<4;bb++)
#pragma unroll
            for (int c=0;c<4;c++) acc[a][bb][c]=0.f;

    int ld_vc = 0, ld_rr = 0, ld_kc = 0;
    auto LD = [&](){
        if (ld_vc < NC) {
            uint32_t st = sb + (ld_vc&3)*STG;
            int dh = ld_rr/3 - 1, dw = ld_rr - (ld_rr/3)*3 - 1;
            int off = dh*60 + dw;
            int srcSel = ld_kc>>3, cil = (ld_kc&7)*256, cig = ld_kc*32;
            const bf16* sp = (srcSel==0)?s0:((srcSel==1)?s1:s2);
#pragma unroll
            for (int q=0;q<2;q++){
                int idx=tid*2+q, row=idx>>2, sg=idx&3;
                int j=m0+row, h=j/60, w=j-h*60;
                bool v = (j<NPix) && ((unsigned)(h+dh)<60u) && ((unsigned)(w+dw)<60u);
                const bf16* ap = sp + so + (size_t)(j+off)*CC + cil/8*8 + sg*8;  // cil is ci*... see below
                // note: cil = (kc&7)*32 channels -> offset in elements
                ap = sp + so + (size_t)(j+off)*CC + (ld_kc&7)*32 + sg*8;
                cpa16(st+row*80+sg*16, v?ap:(sp+so), v);
            }
#pragma unroll
            for (int q=0;q<2;q++){
                int idx=tid*2+q, row=idx>>2, sg=idx&3;
                const bf16* bp = W + (size_t)ld_rr*CC*LDB + (size_t)(n0+row)*LDB + cig + sg*8;
                cpa16(st+10240+row*80+sg*16, bp, true);
            }
            ld_vc++; ld_kc++;
            if (ld_kc == KPC) { ld_kc = 0; ld_rr++; }
        }
        asm volatile("cp.async.commit_group;":::"memory");
    };
    LD(); LD(); LD();
    for (int c=0;c<NC;c++){
        asm volatile("cp.async.wait_group 2;":::"memory");
        __syncthreads();
        uint32_t ta = sb+(c&3)*STG, tb = ta+10240;
        MMA_COMPUTE(ta, tb);
        LD();
    }
    float* C = out + so;
#pragma unroll
    for (int mt=0;mt<4;mt++){
        int r0 = m0+wm*64+mt*16+(lane>>2);
#pragma unroll
        for (int nt=0;nt<4;nt++){
            int c0 = n0+wn*32+nt*8+(lane&3)*2;
            if (r0<NPix)   *(float2*)&C[(size_t)r0*CC+c0]     = make_float2(acc[mt][nt][0],acc[mt][nt][1]);
            if (r0+8<NPix) *(float2*)&C[(size_t)(r0+8)*CC+c0] = make_float2(acc[mt][nt][2],acc[mt][nt][3]);
        }
    }
}

__global__ void cvt_k(const float* __restrict__ in, bf16* __restrict__ out, int n)
{
    int i = (blockIdx.x*256+threadIdx.x)*4;
    if (i >= n) return;
    float4 v = *(const float4*)(in+i);
    bf162 a = __floats2bfloat162_rn(v.x,v.y), b = __floats2bfloat162_rn(v.z,v.w);
    uint2 st; st.x=*(uint32_t*)&a; st.y=*(uint32_t*)&b;
    *(uint2*)(out+i) = st;
}

// fp32 [CC][NPix] -> bf16 transposed [NPix][CC] (outT) and bf16 same-layout copy (outN, optional)
__global__ void trans_dual(const float* __restrict__ in, bf16* __restrict__ outT,
                           bf16* __restrict__ outN)
{
    __shared__ float t[32][33];
    size_t zo = (size_t)blockIdx.z*CN;
    int c0 = blockIdx.x*32, r0 = blockIdx.y*32;
    int tx = threadIdx.x&31, ty = threadIdx.x>>5;
#pragma unroll
    for (int i=0;i<4;i++){
        int rr=r0+ty+i*8, cc=c0+tx;
        if (cc<NPix){
            float v = in[zo+(size_t)rr*NPix+cc];
            t[ty+i*8][tx] = v;
            if (outN) outN[zo+(size_t)rr*NPix+cc] = __float2bfloat16(v);
        }
    }
    __syncthreads();
#pragma unroll
    for (int i=0;i<4;i++){
        int cc=c0+ty+i*8, rr=r0+tx;
        if (cc<NPix) outT[zo+(size_t)cc*CC+rr] = __float2bfloat16(t[tx][ty+i*8]);
    }
}

__global__ void trans_b2b(const bf16* __restrict__ in, bf16* __restrict__ out, int R, int Cc)
{
    __shared__ bf16 t[32][34];
    size_t zo = (size_t)blockIdx.z*R*Cc;
    int c0 = blockIdx.x*32, r0 = blockIdx.y*32;
    int tx = threadIdx.x&31, ty = threadIdx.x>>5;
#pragma unroll
    for (int i=0;i<4;i++){
        int rr=r0+ty+i*8, cc=c0+tx;
        if (rr<R && cc<Cc) t[ty+i*8][tx] = in[zo+(size_t)rr*Cc+cc];
    }
    __syncthreads();
#pragma unroll
    for (int i=0;i<4;i++){
        int cc=c0+ty+i*8, rr=r0+tx;
        if (cc<Cc && rr<R) out[zo+(size_t)cc*R+rr] = t[tx][ty+i*8];
    }
}

__global__ void repack_k(const float* __restrict__ w, bf16* __restrict__ out, int CI, int total)
{
    int idx = blockIdx.x*256+threadIdx.x;
    if (idx >= total) return;
    int r = idx/(CC*CI), rem = idx - r*(CC*CI);
    int co = rem/CI, ci = rem - co*CI;
    out[idx] = __float2bfloat16(w[(size_t)co*CI*9 + ci*9 + r]);
}

// z=0: rowsum of E -> rowinv ; z=1: rowsum of ET -> colinv
__global__ void rowsum_k(const bf16* __restrict__ E, const bf16* __restrict__ ET,
                         float* __restrict__ ri, float* __restrict__ ci)
{
    int row = blockIdx.x, z = blockIdx.y;
    const bf162* p = (const bf162*)((z?ET:E) + (size_t)row*NPix);
    float s = 0.f;
    for (int j=threadIdx.x; j<NPix/2; j+=256){ float2 v=__bfloat1622float2(p[j]); s+=v.x+v.y; }
    __shared__ float ss[256];
    ss[threadIdx.x]=s; __syncthreads();
    for (int o=128;o;o>>=1){ if (threadIdx.x<o) ss[threadIdx.x]+=ss[threadIdx.x+o]; __syncthreads(); }
    if (threadIdx.x==0) (z?ci:ri)[row] = 1.f/ss[0];
}

__global__ void gatew_k(const float* __restrict__ a1f, const float* __restrict__ a2f,
                        const float* __restrict__ ri, const float* __restrict__ ci,
                        const float* __restrict__ gw,
                        bf16* __restrict__ a1b, bf16* __restrict__ a2b)
{
    int z = blockIdx.z;
    const float* Z = z?a2f:a1f;
    const float* iv = z?ci:ri;
    bf16* out = z?a2b:a1b;
    __shared__ float w[CC];
    int tid = threadIdx.x;
    for (int c=tid;c<CC;c+=256) w[c]=gw[c];
    __syncthreads();
    int lane=tid&31, wid=tid>>5;
    int p = blockIdx.x*8+wid, b = blockIdx.y;
    const float* zp = Z + ((size_t)b*NPix+p)*CC + lane*8;
    float4 u0=*(const float4*)zp, u1=*(const float4*)(zp+4);
    float vv[8]={u0.x,u0.y,u0.z,u0.w,u1.x,u1.y,u1.z,u1.w};
    int c8=lane*8;
    float d=0.f;
#pragma unroll
    for (int u=0;u<8;u++) d += vv[u]*w[c8+u];
#pragma unroll
    for (int o=16;o;o>>=1) d += __shfl_xor_sync(~0u,d,o);
    float m = iv[b*NPix+p];
    float mul = m/(1.f+__expf(-d*m));
    bf162 o0=__floats2bfloat162_rn(vv[0]*mul,vv[1]*mul), o1=__floats2bfloat162_rn(vv[2]*mul,vv[3]*mul);
    bf162 o2=__floats2bfloat162_rn(vv[4]*mul,vv[5]*mul), o3=__floats2bfloat162_rn(vv[6]*mul,vv[7]*mul);
    uint4 st; st.x=*(uint32_t*)&o0; st.y=*(uint32_t*)&o1; st.z=*(uint32_t*)&o2; st.w=*(uint32_t*)&o3;
    *(uint4*)(out + ((size_t)b*NPix+p)*CC + c8) = st;
}

__global__ void bnpart_k(const float* __restrict__ x1T, const float* __restrict__ x2T,
                         float* __restrict__ ps, float* __restrict__ pq)
{
    int z = blockIdx.z;
    const float* x = z?x2T:x1T;
    int c = threadIdx.x, b = blockIdx.y, blk = blockIdx.x;
    int n0 = blk*128, nend = min(n0+128, NPix);
    const float* xp = x + (size_t)b*NPix*CC + c;
    float s=0.f, q=0.f;
    for (int n=n0;n<nend;n++){ float v=xp[(size_t)n*CC]; s+=v; q+=v*v; }
    int p = z*58 + b*29 + blk;
    ps[p*CC+c]=s; pq[p*CC+c]=q;
}

__global__ void bncomb_k(const float* __restrict__ ps, const float* __restrict__ pq,
                         const float* __restrict__ g1, const float* __restrict__ b1,
                         const float* __restrict__ g2, const float* __restrict__ b2,
                         float* __restrict__ sc, float* __restrict__ sh)
{
    int c = threadIdx.x, z = blockIdx.x;
    float s=0.f, q=0.f;
    for (int p=z*58;p<z*58+58;p++){ s+=ps[p*CC+c]; q+=pq[p*CC+c]; }
    const float inv = 1.f/(BB*NPix);
    float mean=s*inv, var=q*inv-mean*mean;
    float k = (z?g2:g1)[c]*rsqrtf(var+1e-5f);
    sc[z*CC+c]=k; sh[z*CC+c]=(z?b2:b1)[c]-mean*k;
}

__global__ void bncls_k(const float* __restrict__ x1T, const float* __restrict__ x2T,
                        const float* __restrict__ sc, const float* __restrict__ sh,
                        const float* __restrict__ c1w, const float* __restrict__ c1b,
                        const float* __restrict__ c2w, const float* __restrict__ c2b,
                        float* __restrict__ y1, float* __restrict__ y2)
{
    int z = blockIdx.z;
    const float* x = z?x2T:x1T;
    const float* cw = z?c2w:c1w;
    const float* cb = z?c2b:c1b;
    float* y = z?y2:y1;
    __shared__ float ssc[CC], ssh[CC], w0[CC], w1[CC];
    int tid = threadIdx.x;
    for (int c=tid;c<CC;c+=256){ ssc[c]=sc[z*CC+c]; ssh[c]=sh[z*CC+c]; w0[c]=cw[c]; w1[c]=cw[CC+c]; }
    __syncthreads();
    int lane=tid&31, wid=tid>>5;
    int p = blockIdx.x*8+wid, b = blockIdx.y;
    const float* xp = x + ((size_t)b*NPix+p)*CC + lane*8;
    float4 u0=*(const float4*)xp, u1=*(const float4*)(xp+4);
    float vv[8]={u0.x,u0.y,u0.z,u0.w,u1.x,u1.y,u1.z,u1.w};
    int c8=lane*8;
    float a0=0.f, a1=0.f;
#pragma unroll
    for (int u=0;u<8;u++){
        float v = fmaxf(vv[u]*ssc[c8+u]+ssh[c8+u], 0.f);
        a0 += v*w0[c8+u]; a1 += v*w1[c8+u];
    }
#pragma unroll
    for (int o=16;o;o>>=1){ a0+=__shfl_xor_sync(~0u,a0,o); a1+=__shfl_xor_sync(~0u,a1,o); }
    if (lane==0){
        y[(size_t)(b*NCls+0)*NPix+p] = a0+cb[0];
        y[(size_t)(b*NCls+1)*NPix+p] = a1+cb[1];
    }
}

__global__ void resize_k(float* __restrict__ out)
{
    const size_t per = (size_t)BB*NCls*HOUT*WOUT;
    size_t idx = (size_t)blockIdx.x*256+threadIdx.x;
    if (idx >= 2*per) return;
    int t = idx >= per;
    size_t r = idx - (size_t)t*per;
    int x=(int)(r%WOUT); r/=WOUT;
    int y=(int)(r%HOUT); r/=HOUT;
    int kc=(int)(r%NCls); int b=(int)(r/NCls);
    const float* src = (t?g_y2:g_y1) + (size_t)(b*NCls+kc)*NPix;
    const float sc = 60.f/473.f;
    float syf=(y+0.5f)*sc-0.5f, sxf=(x+0.5f)*sc-0.5f;
    float fy0=floorf(syf), fx0=floorf(sxf);
    float fy=syf-fy0, fx=sxf-fx0;
    int y0=max((int)fy0,0), x0=max((int)fx0,0);
    int y1i=min((int)fy0+1,59), x1i=min((int)fx0+1,59);
    float v00=src[y0*60+x0], v01=src[y0*60+x1i], v10=src[y1i*60+x0], v11=src[y1i*60+x1i];
    float vt=v00+(v01-v00)*fx, vb=v10+(v11-v10)*fx;
    out[idx] = 1.f/(1.f+__expf(-(vt+(vb-vt)*fy)));
}

extern "C" void kernel_launch(void* const* d_in, const int* in_sizes, int n_in,
                              void* d_out, int out_size)
{
    const float *V_a=(const float*)d_in[0], *V_b=(const float*)d_in[1], *D_a=(const float*)d_in[2];
    const float *W_e=(const float*)d_in[3], *gate_w=(const float*)d_in[4];
    const float *c1w=(const float*)d_in[5], *c2w=(const float*)d_in[6];
    const float *bn1g=(const float*)d_in[7], *bn1b=(const float*)d_in[8];
    const float *bn2g=(const float*)d_in[9], *bn2b=(const float*)d_in[10];
    const float *cl1w=(const float*)d_in[11], *cl1b=(const float*)d_in[12];
    const float *cl2w=(const float*)d_in[13], *cl2b=(const float*)d_in[14];
    float* out = (float*)d_out;

    bf16 *Vab,*Vbb,*Web,*wr1,*wr2,*VaT,*VbT,*DaT,*WvT,*E,*ET,*a1b,*a2b;
    float *a1f,*a2f,*x1T,*x2T,*ri,*ci,*bp,*bq,*bsc,*bsh,*y1,*y2;
    cudaGetSymbolAddress((void**)&Vab,g_Vab);  cudaGetSymbolAddress((void**)&Vbb,g_Vbb);
    cudaGetSymbolAddress((void**)&Web,g_Web);  cudaGetSymbolAddress((void**)&wr1,g_wr1);
    cudaGetSymbolAddress((void**)&wr2,g_wr2);  cudaGetSymbolAddress((void**)&VaT,g_VaT);
    cudaGetSymbolAddress((void**)&VbT,g_VbT);  cudaGetSymbolAddress((void**)&DaT,g_DaT);
    cudaGetSymbolAddress((void**)&WvT,g_WvT);  cudaGetSymbolAddress((void**)&E,g_E);
    cudaGetSymbolAddress((void**)&ET,g_ET);
    cudaGetSymbolAddress((void**)&a1b,g_a1Tb); cudaGetSymbolAddress((void**)&a2b,g_a2Tb);
    cudaGetSymbolAddress((void**)&a1f,g_a1Tf); cudaGetSymbolAddress((void**)&a2f,g_a2Tf);
    cudaGetSymbolAddress((void**)&x1T,g_x1T);  cudaGetSymbolAddress((void**)&x2T,g_x2T);
    cudaGetSymbolAddress((void**)&ri,g_rowinv);cudaGetSymbolAddress((void**)&ci,g_colinv);
    cudaGetSymbolAddress((void**)&bp,g_bp);    cudaGetSymbolAddress((void**)&bq,g_bq);
    cudaGetSymbolAddress((void**)&bsc,g_bnsc); cudaGetSymbolAddress((void**)&bsh,g_bnsh);
    cudaGetSymbolAddress((void**)&y1,g_y1);    cudaGetSymbolAddress((void**)&y2,g_y2);

    cudaFuncSetAttribute(bgemm<1>, cudaFuncAttributeMaxDynamicSharedMemorySize, GSMEM);
    cudaFuncSetAttribute(bgemm<2>, cudaFuncAttributeMaxDynamicSharedMemorySize, GSMEM);
    cudaFuncSetAttribute(zpair,    cudaFuncAttributeMaxDynamicSharedMemorySize, GSMEM);
    cudaFuncSetAttribute(convpair, cudaFuncAttributeMaxDynamicSharedMemorySize, GSMEM);

    cvt_k<<<(CC*CC/4+255)/256,256>>>(W_e, Web, CC*CC);
    trans_dual<<<dim3(113,8,BB),256>>>(V_a, VaT, Vab);
    trans_dual<<<dim3(113,8,BB),256>>>(V_b, VbT, Vbb);
    trans_dual<<<dim3(113,8,BB),256>>>(D_a, DaT, nullptr);
    repack_k<<<(9*CC*768+255)/256,256>>>(c1w, wr1, 768, 9*CC*768);
    repack_k<<<(9*CC*512+255)/256,256>>>(c2w, wr2, 512, 9*CC*512);
    // WvT[n][d] = sum_c VaT[n][c]*W_e[d][c]
    bgemm<1><<<dim3(2,29,BB),256,GSMEM>>>(VaT, Web, WvT, NPix, CC, CC, CC, CC, CC, NCn, 0, NCn);
    // E[n][m] = exp(sum_d WvT[n][d]*VbT[m][d])
    bgemm<2><<<dim3(29,29,BB),256,GSMEM>>>(WvT, VbT, E, NPix, NPix, CC, CC, CC, NPix, NCn, NCn, NN);
    trans_b2b<<<dim3(113,113,BB),256>>>(E, ET, NPix, NPix);
    rowsum_k<<<dim3(BB*NPix,2),256>>>(E, ET, ri, ci);
    zpair<<<dim3(2,29,4),256,GSMEM>>>(E, ET, Vab, Vbb, a1f, a2f);
    gatew_k<<<dim3(450,BB,2),256>>>(a1f, a2f, ri, ci, gate_w, a1b, a2b);
    convpair<<<dim3(2,29,4),256,GSMEM>>>(a1b, a2b, VaT, VbT, DaT, wr1, wr2, x1T, x2T);
    bnpart_k<<<dim3(29,BB,2),256>>>(x1T, x2T, bp, bq);
    bncomb_k<<<2,256>>>(bp, bq, bn1g, bn1b, bn2g, bn2b, bsc, bsh);
    bncls_k<<<dim3(450,BB,2),256>>>(x1T, x2T, bsc, bsh, cl1w, cl1b, cl2w, cl2b, y1, y2);
    const size_t total = 2ull*BB*NCls*HOUT*WOUT;
    resize_k<<<(int)((total+255)/256),256>>>(out);
}

// round 8
// speedup vs baseline: 6.1036x; 1.0537x over previous
#include <cuda_runtime.h>
#include <cuda_bf16.h>
#include <cstdint>
#include <math.h>

#define BB 2
#define CC 256
#define NPix 3600
#define NCls 2
#define HOUT 473
#define WOUT 473
typedef __nv_bfloat16 bf16;
typedef __nv_bfloat162 bf162;

static const size_t CN = (size_t)CC*NPix, NN = (size_t)NPix*NPix, NCn = (size_t)NPix*CC;

__device__ bf16 g_Vab[BB*CC*NPix], g_Vbb[BB*CC*NPix];
__device__ bf16 g_Web[CC*CC];
__device__ bf16 g_wr1[9*CC*768], g_wr2[9*CC*512];
__device__ bf16 g_VaT[BB*NPix*CC], g_VbT[BB*NPix*CC], g_DaT[BB*NPix*CC], g_WvT[BB*NPix*CC];
__device__ bf16 g_E[(size_t)BB*NPix*NPix], g_ET[(size_t)BB*NPix*NPix];
__device__ bf16 g_a1Tb[BB*NPix*CC], g_a2Tb[BB*NPix*CC];
__device__ float g_a1Tf[BB*NPix*CC], g_a2Tf[BB*NPix*CC];
__device__ float g_x1T[BB*NPix*CC], g_x2T[BB*NPix*CC];
__device__ float g_rowinv[BB*NPix], g_colinv[BB*NPix];
__device__ float g_bp[2*58*CC], g_bq[2*58*CC];
__device__ float g_bnsc[2*CC], g_bnsh[2*CC];
__device__ float g_y1[BB*NCls*NPix], g_y2[BB*NCls*NPix];

__device__ __forceinline__ uint32_t smem_u32(const void* p){
    uint32_t a; asm("{ .reg .u64 t; cvta.to.shared.u64 t, %1; cvt.u32.u64 %0, t; }":"=r"(a):"l"(p)); return a;
}
__device__ __forceinline__ void cpa16(uint32_t d, const void* s, bool v){
    asm volatile("cp.async.cg.shared.global [%0],[%1],16,%2;"::"r"(d),"l"(s),"r"(v?16:0));
}
__device__ __forceinline__ void ldmx4(uint32_t* r, uint32_t a){
    asm volatile("ldmatrix.sync.aligned.m8n8.x4.shared.b16 {%0,%1,%2,%3},[%4];"
        :"=r"(r[0]),"=r"(r[1]),"=r"(r[2]),"=r"(r[3]):"r"(a));
}
__device__ __forceinline__ void mma_bf16(float* c, const uint32_t* a, const uint32_t* b){
    asm volatile("mma.sync.aligned.m16n8k16.row.col.f32.bf16.bf16.f32 "
        "{%0,%1,%2,%3},{%4,%5,%6,%7},{%8,%9},{%0,%1,%2,%3};"
        :"+f"(c[0]),"+f"(c[1]),"+f"(c[2]),"+f"(c[3])
        :"r"(a[0]),"r"(a[1]),"r"(a[2]),"r"(a[3]),"r"(b[0]),"r"(b[1]));
}

#define STG 20480
#define GSMEM (4*STG)

#define MMA_COMPUTE(ta, tb) \
    _Pragma("unroll") \
    for (int s = 0; s < 2; s++) { \
        uint32_t af[4][4], bq[4][2]; \
        _Pragma("unroll") \
        for (int mt = 0; mt < 4; mt++) \
            ldmx4(af[mt], (ta) + (uint32_t)((wm*64+mt*16+(g&1)*8+r8)*80 + (g>>1)*16 + s*32)); \
        _Pragma("unroll") \
        for (int np = 0; np < 2; np++) { \
            uint32_t t4[4]; \
            ldmx4(t4, (tb) + (uint32_t)((wn*32+np*16+(g>>1)*8+r8)*80 + (g&1)*16 + s*32)); \
            bq[np*2][0]=t4[0]; bq[np*2][1]=t4[1]; bq[np*2+1][0]=t4[2]; bq[np*2+1][1]=t4[3]; \
        } \
        _Pragma("unroll") \
        for (int mt = 0; mt < 4; mt++) \
            _Pragma("unroll") \
            for (int nt = 0; nt < 4; nt++) \
                mma_bf16(acc[mt][nt], af[mt], bq[nt]); \
    }

#define GEMM_MAINLOOP(Aptr, Bptr, MMd, NNd, KKd, llda, lldb) \
    auto LD = [&](int c){ \
        if (c < NC) { \
            uint32_t st = sb + (c&3)*STG; \
            int k0 = c<<5; \
            _Pragma("unroll") \
            for (int q=0;q<2;q++){ \
                int idx=tid*2+q, row=idx>>2, sg=idx&3; \
                bool v = (m0+row)<(MMd) && (k0+sg*8)<(KKd); \
                cpa16(st+row*80+sg*16, (Aptr) + (v?((size_t)(m0+row)*(llda)+k0+sg*8):0), v); \
            } \
            _Pragma("unroll") \
            for (int q=0;q<2;q++){ \
                int idx=tid*2+q, row=idx>>2, sg=idx&3; \
                bool v = (n0+row)<(NNd) && (k0+sg*8)<(KKd); \
                cpa16(st+10240+row*80+sg*16, (Bptr) + (v?((size_t)(n0+row)*(lldb)+k0+sg*8):0), v); \
            } \
        } \
        asm volatile("cp.async.commit_group;":::"memory"); \
    }; \
    LD(0); LD(1); LD(2); \
    for (int c=0;c<NC;c++){ \
        asm volatile("cp.async.wait_group 2;":::"memory"); \
        __syncthreads(); \
        uint32_t ta = sb+(c&3)*STG, tb = ta+10240; \
        MMA_COMPUTE(ta, tb); \
        LD(c+3); \
    }

// generic body: C[M,N]=A[M,K]*B^T, A=[i][k], B=[j][k]. OUTM: 0=f32, 1=bf16
template<int OUTM>
__device__ __forceinline__ void gbody(const bf16* __restrict__ A, const bf16* __restrict__ B,
    void* __restrict__ Cv, int Md, int Nd, int Kd, int lda, int ldb, int ldc, int m0, int n0)
{
    extern __shared__ char smc[];
    const int tid = threadIdx.x, lane = tid&31, wid = tid>>5;
    const int wm = wid>>2, wn = wid&3, g = lane>>3, r8 = lane&7;
    uint32_t sb = smem_u32(smc);
    float acc[4][4][4];
#pragma unroll
    for (int a=0;a<4;a++)
#pragma unroll
        for (int b=0;b<4;b++)
#pragma unroll
            for (int c=0;c<4;c++) acc[a][b][c]=0.f;
    const int NC = (Kd+31)>>5;
    GEMM_MAINLOOP(A, B, Md, Nd, Kd, lda, ldb)
#pragma unroll
    for (int mt=0;mt<4;mt++){
        int r0 = m0+wm*64+mt*16+(lane>>2);
#pragma unroll
        for (int nt=0;nt<4;nt++){
            int c0 = n0+wn*32+nt*8+(lane&3)*2;
            if (c0 >= Nd) continue;
            float x0=acc[mt][nt][0],x1=acc[mt][nt][1],x2=acc[mt][nt][2],x3=acc[mt][nt][3];
            if (OUTM==0){
                float* C=(float*)Cv;
                if (r0<Md)   *(float2*)&C[(size_t)r0*ldc+c0]     = make_float2(x0,x1);
                if (r0+8<Md) *(float2*)&C[(size_t)(r0+8)*ldc+c0] = make_float2(x2,x3);
            } else {
                bf16* C=(bf16*)Cv;
                if (r0<Md)   *(bf162*)&C[(size_t)r0*ldc+c0]     = __floats2bfloat162_rn(x0,x1);
                if (r0+8<Md) *(bf162*)&C[(size_t)(r0+8)*ldc+c0] = __floats2bfloat162_rn(x2,x3);
            }
        }
    }
}

template<int OUTM>
__global__ void __launch_bounds__(256,2)
bgemm(const bf16* __restrict__ A, const bf16* __restrict__ B, void* __restrict__ Cv,
      int Md, int Nd, int Kd, int lda, int ldb, int ldc, size_t sA, size_t sB, size_t sC)
{
    const int z = blockIdx.z;
    void* C = (OUTM==0) ? (void*)((float*)Cv+(size_t)z*sC) : (void*)((bf16*)Cv+(size_t)z*sC);
    gbody<OUTM>(A+(size_t)z*sA, B+(size_t)z*sB, C, Md, Nd, Kd, lda, ldb, ldc,
                blockIdx.y*128, blockIdx.x*128);
}

// S GEMM: E[n][m]=exp(WvT[n]·VbT[m]) AND ET[m][n], transposed via swizzled smem staging
__global__ void __launch_bounds__(256,2)
sgemm(const bf16* __restrict__ WvT, const bf16* __restrict__ VbT,
      bf16* __restrict__ Ep, bf16* __restrict__ ETp)
{
    extern __shared__ char smc[];
    const int z = blockIdx.z;
    const bf16* A = WvT + (size_t)z*NCn;
    const bf16* B = VbT + (size_t)z*NCn;
    bf16* Eb  = Ep  + (size_t)z*NN;
    bf16* ETb = ETp + (size_t)z*NN;
    const int m0 = blockIdx.y*128, n0 = blockIdx.x*128;
    const int tid = threadIdx.x, lane = tid&31, wid = tid>>5;
    const int wm = wid>>2, wn = wid&3, g = lane>>3, r8 = lane&7;
    uint32_t sb = smem_u32(smc);
    float acc[4][4][4];
#pragma unroll
    for (int a=0;a<4;a++)
#pragma unroll
        for (int b=0;b<4;b++)
#pragma unroll
            for (int c=0;c<4;c++) acc[a][b][c]=0.f;
    const int NC = 8;  // K=256
    GEMM_MAINLOOP(A, B, NPix, NPix, CC, CC, CC)

    __syncthreads();   // stage smem free now; reuse for transpose
    bf16* sh = (bf16*)smc;
#pragma unroll
    for (int mt=0;mt<4;mt++){
        int rl0 = wm*64+mt*16+(lane>>2);
        int r0 = m0+rl0;
#pragma unroll
        for (int nt=0;nt<4;nt++){
            int cl0 = wn*32+nt*8+(lane&3)*2;
            int c0 = n0+cl0;
            float x0=__expf(acc[mt][nt][0]),x1=__expf(acc[mt][nt][1]);
            float x2=__expf(acc[mt][nt][2]),x3=__expf(acc[mt][nt][3]);
            if (c0 < NPix) {
                if (r0 < NPix)   *(bf162*)&Eb[(size_t)r0*NPix+c0]     = __floats2bfloat162_rn(x0,x1);
                if (r0+8 < NPix) *(bf162*)&Eb[(size_t)(r0+8)*NPix+c0] = __floats2bfloat162_rn(x2,x3);
            }
            // swizzled transposed smem store: sh[c][r], pitch 136, block-XOR swizzle
#define TST(rr,cc,xx) sh[(cc)*136 + (((((rr)>>3)^((cc)>>3))&15)<<3) + ((rr)&7)] = __float2bfloat16(xx)
            TST(rl0,   cl0,   x0); TST(rl0,   cl0+1, x1);
            TST(rl0+8, cl0,   x2); TST(rl0+8, cl0+1, x3);
#undef TST
        }
    }
    __syncthreads();
    // warp w writes ET rows n0+w*16 .. +15 (coalesced 256B per row)
#pragma unroll
    for (int rr=0; rr<16; rr++){
        int cp = wid*16 + rr;
        int mg = n0 + cp;
        if (mg >= NPix) continue;
        int cb = cp>>3;
        int rb = lane>>1, half = lane&1;
        int ng = m0 + rb*8 + half*4;
        if (ng >= NPix) continue;
        uint2 v = *(uint2*)(sh + cp*136 + (((rb^cb)&15)<<3) + half*4);
        *(uint2*)&ETb[(size_t)mg*NPix + ng] = v;
    }
}

// both Z GEMMs in one launch: z=0,1 -> att1 (A=E,B=Vbb), z=2,3 -> att2 (A=ET,B=Vab)
__global__ void __launch_bounds__(256,2)
zpair(const bf16* __restrict__ E, const bf16* __restrict__ ET,
      const bf16* __restrict__ Vab, const bf16* __restrict__ Vbb,
      float* __restrict__ a1f, float* __restrict__ a2f)
{
    int z = blockIdx.z, br = z>>1, b = z&1;
    const bf16* A = (br?ET:E) + (size_t)b*NN;
    const bf16* B = (br?Vab:Vbb) + (size_t)b*CN;
    float* C = (br?a2f:a1f) + (size_t)b*NCn;
    gbody<0>(A, B, C, NPix, CC, NPix, NPix, NPix, CC, blockIdx.y*128, blockIdx.x*128);
}

// both convs: z=0,1 conv1 (3 srcs), z=2,3 conv2 (2 srcs); 9 shifted accumulated GEMMs
__global__ void __launch_bounds__(256,2)
convpair(const bf16* __restrict__ a1b, const bf16* __restrict__ a2b,
         const bf16* __restrict__ VaT, const bf16* __restrict__ VbT, const bf16* __restrict__ DaT,
         const bf16* __restrict__ wr1, const bf16* __restrict__ wr2,
         float* __restrict__ x1T, float* __restrict__ x2T)
{
    extern __shared__ char smc[];
    int zz = blockIdx.z, br = zz>>1, b = zz&1;
    const bf16 *s0 = br?a2b:a1b, *s1 = br?VbT:VaT, *s2 = br?VbT:DaT;
    const bf16 *W = br?wr2:wr1;
    float* out = br?x2T:x1T;
    const int SR = br?2:3;
    const int LDB = SR*256, KPC = SR*8, NC = 9*KPC;
    const size_t so = (size_t)b*NCn;
    const int m0 = blockIdx.y*128, n0 = blockIdx.x*128;
    const int tid = threadIdx.x, lane = tid&31, wid = tid>>5;
    const int wm = wid>>2, wn = wid&3, g = lane>>3, r8 = lane&7;
    uint32_t sb = smem_u32(smc);
    float acc[4][4][4];
#pragma unroll
    for (int a=0;a<4;a++)
#pragma unroll
        for (int bb=0;bb<4;bb++)
#pragma unroll
            for (int c=0;c<4;c++) acc[a][bb][c]=0.f;

    int ld_vc = 0, ld_rr = 0, ld_kc = 0;
    auto LD = [&](){
        if (ld_vc < NC) {
            uint32_t st = sb + (ld_vc&3)*STG;
            int dh = ld_rr/3 - 1, dw = ld_rr - (ld_rr/3)*3 - 1;
            int off = dh*60 + dw;
            int srcSel = ld_kc>>3, cig = ld_kc*32;
            const bf16* sp = (srcSel==0)?s0:((srcSel==1)?s1:s2);
#pragma unroll
            for (int q=0;q<2;q++){
                int idx=tid*2+q, row=idx>>2, sg=idx&3;
                int j=m0+row, h=j/60, w=j-h*60;
                bool v = (j<NPix) && ((unsigned)(h+dh)<60u) && ((unsigned)(w+dw)<60u);
                const bf16* ap = sp + so + (size_t)(j+off)*CC + (ld_kc&7)*32 + sg*8;
                cpa16(st+row*80+sg*16, v?ap:(sp+so), v);
            }
#pragma unroll
            for (int q=0;q<2;q++){
                int idx=tid*2+q, row=idx>>2, sg=idx&3;
                const bf16* bp = W + (size_t)ld_rr*CC*LDB + (size_t)(n0+row)*LDB + cig + sg*8;
                cpa16(st+10240+row*80+sg*16, bp, true);
            }
            ld_vc++; ld_kc++;
            if (ld_kc == KPC) { ld_kc = 0; ld_rr++; }
        }
        asm volatile("cp.async.commit_group;":::"memory");
    };
    LD(); LD(); LD();
    for (int c=0;c<NC;c++){
        asm volatile("cp.async.wait_group 2;":::"memory");
        __syncthreads();
        uint32_t ta = sb+(c&3)*STG, tb = ta+10240;
        MMA_COMPUTE(ta, tb);
        LD();
    }
    float* C = out + so;
#pragma unroll
    for (int mt=0;mt<4;mt++){
        int r0 = m0+wm*64+mt*16+(lane>>2);
#pragma unroll
        for (int nt=0;nt<4;nt++){
            int c0 = n0+wn*32+nt*8+(lane&3)*2;
            if (r0<NPix)   *(float2*)&C[(size_t)r0*CC+c0]     = make_float2(acc[mt][nt][0],acc[mt][nt][1]);
            if (r0+8<NPix) *(float2*)&C[(size_t)(r0+8)*CC+c0] = make_float2(acc[mt][nt][2],acc[mt][nt][3]);
        }
    }
}

// fused weight prep: W_e cvt + conv weight repacks
__global__ void wprep(const float* __restrict__ W_e, const float* __restrict__ c1w,
                      const float* __restrict__ c2w, bf16* __restrict__ Web,
                      bf16* __restrict__ wr1, bf16* __restrict__ wr2)
{
    int idx = blockIdx.x*256+threadIdx.x;
    const int N0 = CC*CC, N1 = 9*CC*768, N2 = 9*CC*512;
    if (idx < N0) { Web[idx] = __float2bfloat16(W_e[idx]); return; }
    idx -= N0;
    if (idx < N1) {
        int r = idx/(CC*768), rem = idx - r*(CC*768);
        int co = rem/768, ci = rem - co*768;
        wr1[idx] = __float2bfloat16(c1w[(size_t)co*768*9 + ci*9 + r]);
        return;
    }
    idx -= N1;
    if (idx < N2) {
        int r = idx/(CC*512), rem = idx - r*(CC*512);
        int co = rem/512, ci = rem - co*512;
        wr2[idx] = __float2bfloat16(c2w[(size_t)co*512*9 + ci*9 + r]);
    }
}

// fp32 [CC][NPix] -> bf16 [NPix][CC] (+ optional bf16 same-layout copy); z selects src/batch
__global__ void trans3(const float* __restrict__ Va, const float* __restrict__ Vb,
                       const float* __restrict__ Da,
                       bf16* __restrict__ VaT, bf16* __restrict__ VbT, bf16* __restrict__ DaT,
                       bf16* __restrict__ Vab, bf16* __restrict__ Vbb)
{
    __shared__ float t[32][33];
    int z = blockIdx.z, src = z>>1, b = z&1;
    const float* in = (src==0?Va:(src==1?Vb:Da)) + (size_t)b*CN;
    bf16* outT = (src==0?VaT:(src==1?VbT:DaT)) + (size_t)b*NCn;
    bf16* outN = (src==0?Vab:(src==1?Vbb:(bf16*)nullptr));
    if (outN) outN += (size_t)b*CN;
    int c0 = blockIdx.x*32, r0 = blockIdx.y*32;
    int tx = threadIdx.x&31, ty = threadIdx.x>>5;
#pragma unroll
    for (int i=0;i<4;i++){
        int rr=r0+ty+i*8, cc=c0+tx;
        if (cc<NPix){
            float v = in[(size_t)rr*NPix+cc];
            t[ty+i*8][tx] = v;
            if (outN) outN[(size_t)rr*NPix+cc] = __float2bfloat16(v);
        }
    }
    __syncthreads();
#pragma unroll
    for (int i=0;i<4;i++){
        int cc=c0+ty+i*8, rr=r0+tx;
        if (cc<NPix) outT[(size_t)cc*CC+rr] = __float2bfloat16(t[tx][ty+i*8]);
    }
}

// z=0: rowsum of E -> rowinv ; z=1: rowsum of ET -> colinv
__global__ void rowsum_k(const bf16* __restrict__ E, const bf16* __restrict__ ET,
                         float* __restrict__ ri, float* __restrict__ ci)
{
    int row = blockIdx.x, z = blockIdx.y;
    const bf162* p = (const bf162*)((z?ET:E) + (size_t)row*NPix);
    float s = 0.f;
    for (int j=threadIdx.x; j<NPix/2; j+=256){ float2 v=__bfloat1622float2(p[j]); s+=v.x+v.y; }
    __shared__ float ss[256];
    ss[threadIdx.x]=s; __syncthreads();
    for (int o=128;o;o>>=1){ if (threadIdx.x<o) ss[threadIdx.x]+=ss[threadIdx.x+o]; __syncthreads(); }
    if (threadIdx.x==0) (z?ci:ri)[row] = 1.f/ss[0];
}

__global__ void gatew_k(const float* __restrict__ a1f, const float* __restrict__ a2f,
                        const float* __restrict__ ri, const float* __restrict__ ci,
                        const float* __restrict__ gw,
                        bf16* __restrict__ a1b, bf16* __restrict__ a2b)
{
    int z = blockIdx.z;
    const float* Z = z?a2f:a1f;
    const float* iv = z?ci:ri;
    bf16* out = z?a2b:a1b;
    __shared__ float w[CC];
    int tid = threadIdx.x;
    for (int c=tid;c<CC;c+=256) w[c]=gw[c];
    __syncthreads();
    int lane=tid&31, wid=tid>>5;
    int p = blockIdx.x*8+wid, b = blockIdx.y;
    const float* zp = Z + ((size_t)b*NPix+p)*CC + lane*8;
    float4 u0=*(const float4*)zp, u1=*(const float4*)(zp+4);
    float vv[8]={u0.x,u0.y,u0.z,u0.w,u1.x,u1.y,u1.z,u1.w};
    int c8=lane*8;
    float d=0.f;
#pragma unroll
    for (int u=0;u<8;u++) d += vv[u]*w[c8+u];
#pragma unroll
    for (int o=16;o;o>>=1) d += __shfl_xor_sync(~0u,d,o);
    float m = iv[b*NPix+p];
    float mul = m/(1.f+__expf(-d*m));
    bf162 o0=__floats2bfloat162_rn(vv[0]*mul,vv[1]*mul), o1=__floats2bfloat162_rn(vv[2]*mul,vv[3]*mul);
    bf162 o2=__floats2bfloat162_rn(vv[4]*mul,vv[5]*mul), o3=__floats2bfloat162_rn(vv[6]*mul,vv[7]*mul);
    uint4 st; st.x=*(uint32_t*)&o0; st.y=*(uint32_t*)&o1; st.z=*(uint32_t*)&o2; st.w=*(uint32_t*)&o3;
    *(uint4*)(out + ((size_t)b*NPix+p)*CC + c8) = st;
}

__global__ void bnpart_k(const float* __restrict__ x1T, const float* __restrict__ x2T,
                         float* __restrict__ ps, float* __restrict__ pq)
{
    int z = blockIdx.z;
    const float* x = z?x2T:x1T;
    int c = threadIdx.x, b = blockIdx.y, blk = blockIdx.x;
    int n0 = blk*128, nend = min(n0+128, NPix);
    const float* xp = x + (size_t)b*NCn + c;
    float s=0.f, q=0.f;
    for (int n=n0;n<nend;n++){ float v=xp[(size_t)n*CC]; s+=v; q+=v*v; }
    int p = z*58 + b*29 + blk;
    ps[p*CC+c]=s; pq[p*CC+c]=q;
}

__global__ void bncomb_k(const float* __restrict__ ps, const float* __restrict__ pq,
                         const float* __restrict__ g1, const float* __restrict__ b1,
                         const float* __restrict__ g2, const float* __restrict__ b2,
                         float* __restrict__ sc, float* __restrict__ sh)
{
    int c = threadIdx.x, z = blockIdx.x;
    float s=0.f, q=0.f;
    for (int p=z*58;p<z*58+58;p++){ s+=ps[p*CC+c]; q+=pq[p*CC+c]; }
    const float inv = 1.f/(BB*NPix);
    float mean=s*inv, var=q*inv-mean*mean;
    float k = (z?g2:g1)[c]*rsqrtf(var+1e-5f);
    sc[z*CC+c]=k; sh[z*CC+c]=(z?b2:b1)[c]-mean*k;
}

__global__ void bncls_k(const float* __restrict__ x1T, const float* __restrict__ x2T,
                        const float* __restrict__ sc, const float* __restrict__ sh,
                        const float* __restrict__ c1w, const float* __restrict__ c1b,
                        const float* __restrict__ c2w, const float* __restrict__ c2b,
                        float* __restrict__ y1, float* __restrict__ y2)
{
    int z = blockIdx.z;
    const float* x = z?x2T:x1T;
    const float* cw = z?c2w:c1w;
    const float* cb = z?c2b:c1b;
    float* y = z?y2:y1;
    __shared__ float ssc[CC], ssh[CC], w0[CC], w1[CC];
    int tid = threadIdx.x;
    for (int c=tid;c<CC;c+=256){ ssc[c]=sc[z*CC+c]; ssh[c]=sh[z*CC+c]; w0[c]=cw[c]; w1[c]=cw[CC+c]; }
    __syncthreads();
    int lane=tid&31, wid=tid>>5;
    int p = blockIdx.x*8+wid, b = blockIdx.y;
    const float* xp = x + ((size_t)b*NPix+p)*CC + lane*8;
    float4 u0=*(const float4*)xp, u1=*(const float4*)(xp+4);
    float vv[8]={u0.x,u0.y,u0.z,u0.w,u1.x,u1.y,u1.z,u1.w};
    int c8=lane*8;
    float a0=0.f, a1=0.f;
#pragma unroll
    for (int u=0;u<8;u++){
        float v = fmaxf(vv[u]*ssc[c8+u]+ssh[c8+u], 0.f);
        a0 += v*w0[c8+u]; a1 += v*w1[c8+u];
    }
#pragma unroll
    for (int o=16;o;o>>=1){ a0+=__shfl_xor_sync(~0u,a0,o); a1+=__shfl_xor_sync(~0u,a1,o); }
    if (lane==0){
        y[(size_t)(b*NCls+0)*NPix+p] = a0+cb[0];
        y[(size_t)(b*NCls+1)*NPix+p] = a1+cb[1];
    }
}

__global__ void resize_k(float* __restrict__ out)
{
    const size_t per = (size_t)BB*NCls*HOUT*WOUT;
    size_t idx = (size_t)blockIdx.x*256+threadIdx.x;
    if (idx >= 2*per) return;
    int t = idx >= per;
    size_t r = idx - (size_t)t*per;
    int x=(int)(r%WOUT); r/=WOUT;
    int y=(int)(r%HOUT); r/=HOUT;
    int kc=(int)(r%NCls); int b=(int)(r/NCls);
    const float* src = (t?g_y2:g_y1) + (size_t)(b*NCls+kc)*NPix;
    const float sc = 60.f/473.f;
    float syf=(y+0.5f)*sc-0.5f, sxf=(x+0.5f)*sc-0.5f;
    float fy0=floorf(syf), fx0=floorf(sxf);
    float fy=syf-fy0, fx=sxf-fx0;
    int y0=max((int)fy0,0), x0=max((int)fx0,0);
    int y1i=min((int)fy0+1,59), x1i=min((int)fx0+1,59);
    float v00=src[y0*60+x0], v01=src[y0*60+x1i], v10=src[y1i*60+x0], v11=src[y1i*60+x1i];
    float vt=v00+(v01-v00)*fx, vb=v10+(v11-v10)*fx;
    out[idx] = 1.f/(1.f+__expf(-(vt+(vb-vt)*fy)));
}

extern "C" void kernel_launch(void* const* d_in, const int* in_sizes, int n_in,
                              void* d_out, int out_size)
{
    const float *V_a=(const float*)d_in[0], *V_b=(const float*)d_in[1], *D_a=(const float*)d_in[2];
    const float *W_e=(const float*)d_in[3], *gate_w=(const float*)d_in[4];
    const float *c1w=(const float*)d_in[5], *c2w=(const float*)d_in[6];
    const float *bn1g=(const float*)d_in[7], *bn1b=(const float*)d_in[8];
    const float *bn2g=(const float*)d_in[9], *bn2b=(const float*)d_in[10];
    const float *cl1w=(const float*)d_in[11], *cl1b=(const float*)d_in[12];
    const float *cl2w=(const float*)d_in[13], *cl2b=(const float*)d_in[14];
    float* out = (float*)d_out;

    bf16 *Vab,*Vbb,*Web,*wr1,*wr2,*VaT,*VbT,*DaT,*WvT,*E,*ET,*a1b,*a2b;
    float *a1f,*a2f,*x1T,*x2T,*ri,*ci,*bp,*bq,*bsc,*bsh,*y1,*y2;
    cudaGetSymbolAddress((void**)&Vab,g_Vab);  cudaGetSymbolAddress((void**)&Vbb,g_Vbb);
    cudaGetSymbolAddress((void**)&Web,g_Web);  cudaGetSymbolAddress((void**)&wr1,g_wr1);
    cudaGetSymbolAddress((void**)&wr2,g_wr2);  cudaGetSymbolAddress((void**)&VaT,g_VaT);
    cudaGetSymbolAddress((void**)&VbT,g_VbT);  cudaGetSymbolAddress((void**)&DaT,g_DaT);
    cudaGetSymbolAddress((void**)&WvT,g_WvT);  cudaGetSymbolAddress((void**)&E,g_E);
    cudaGetSymbolAddress((void**)&ET,g_ET);
    cudaGetSymbolAddress((void**)&a1b,g_a1Tb); cudaGetSymbolAddress((void**)&a2b,g_a2Tb);
    cudaGetSymbolAddress((void**)&a1f,g_a1Tf); cudaGetSymbolAddress((void**)&a2f,g_a2Tf);
    cudaGetSymbolAddress((void**)&x1T,g_x1T);  cudaGetSymbolAddress((void**)&x2T,g_x2T);
    cudaGetSymbolAddress((void**)&ri,g_rowinv);cudaGetSymbolAddress((void**)&ci,g_colinv);
    cudaGetSymbolAddress((void**)&bp,g_bp);    cudaGetSymbolAddress((void**)&bq,g_bq);
    cudaGetSymbolAddress((void**)&bsc,g_bnsc); cudaGetSymbolAddress((void**)&bsh,g_bnsh);
    cudaGetSymbolAddress((void**)&y1,g_y1);    cudaGetSymbolAddress((void**)&y2,g_y2);

    cudaFuncSetAttribute(bgemm<1>, cudaFuncAttributeMaxDynamicSharedMemorySize, GSMEM);
    cudaFuncSetAttribute(sgemm,    cudaFuncAttributeMaxDynamicSharedMemorySize, GSMEM);
    cudaFuncSetAttribute(zpair,    cudaFuncAttributeMaxDynamicSharedMemorySize, GSMEM);
    cudaFuncSetAttribute(convpair, cudaFuncAttributeMaxDynamicSharedMemorySize, GSMEM);

    const int WTOT = CC*CC + 9*CC*768 + 9*CC*512;
    wprep<<<(WTOT+255)/256,256>>>(W_e, c1w, c2w, Web, wr1, wr2);
    trans3<<<dim3(113,8,6),256>>>(V_a, V_b, D_a, VaT, VbT, DaT, Vab, Vbb);
    // WvT[n][d] = sum_c VaT[n][c]*W_e[d][c]
    bgemm<1><<<dim3(2,29,BB),256,GSMEM>>>(VaT, Web, WvT, NPix, CC, CC, CC, CC, CC, NCn, 0, NCn);
    // E + ET fused
    sgemm<<<dim3(29,29,BB),256,GSMEM>>>(WvT, VbT, E, ET);
    rowsum_k<<<dim3(BB*NPix,2),256>>>(E, ET, ri, ci);
    zpair<<<dim3(2,29,4),256,GSMEM>>>(E, ET, Vab, Vbb, a1f, a2f);
    gatew_k<<<dim3(450,BB,2),256>>>(a1f, a2f, ri, ci, gate_w, a1b, a2b);
    convpair<<<dim3(2,29,4),256,GSMEM>>>(a1b, a2b, VaT, VbT, DaT, wr1, wr2, x1T, x2T);
    bnpart_k<<<dim3(29,BB,2),256>>>(x1T, x2T, bp, bq);
    bncomb_k<<<2,256>>>(bp, bq, bn1g, bn1b, bn2g, bn2b, bsc, bsh);
    bncls_k<<<dim3(450,BB,2),256>>>(x1T, x2T, bsc, bsh, cl1w, cl1b, cl2w, cl2b, y1, y2);
    const size_t total = 2ull*BB*NCls*HOUT*WOUT;
    resize_k<<<(int)((total+255)/256),256>>>(out);
}

// round 9
// speedup vs baseline: 6.4906x; 1.0634x over previous
#include <cuda_runtime.h>
#include <cuda_bf16.h>
#include <cstdint>
#include <math.h>

#define BB 2
#define CC 256
#define NPix 3600
#define NCls 2
#define HOUT 473
#define WOUT 473
typedef __nv_bfloat16 bf16;
typedef __nv_bfloat162 bf162;

static const size_t CN = (size_t)CC*NPix, NN = (size_t)NPix*NPix, NCn = (size_t)NPix*CC;

__device__ bf16 g_Vab[BB*CC*NPix], g_Vbb[BB*CC*NPix];
__device__ bf16 g_Web[CC*CC];
__device__ bf16 g_wr1[9*CC*768], g_wr2[9*CC*512];
__device__ bf16 g_VaT[BB*NPix*CC], g_VbT[BB*NPix*CC], g_DaT[BB*NPix*CC], g_WvT[BB*NPix*CC];
__device__ bf16 g_E[(size_t)BB*NPix*NPix], g_ET[(size_t)BB*NPix*NPix];
__device__ bf16 g_a1Tb[BB*NPix*CC], g_a2Tb[BB*NPix*CC];
__device__ float g_a1Tf[BB*NPix*CC], g_a2Tf[BB*NPix*CC];
__device__ float g_x1T[BB*NPix*CC], g_x2T[BB*NPix*CC];
__device__ float g_rps[(size_t)BB*116*NPix], g_cps[(size_t)BB*116*NPix];
__device__ float g_rowinv[BB*NPix], g_colinv[BB*NPix];
__device__ float g_bp[2*58*CC], g_bq[2*58*CC];
__device__ float g_bnsc[2*CC], g_bnsh[2*CC];
__device__ float g_y1[BB*NCls*NPix], g_y2[BB*NCls*NPix];

__device__ __forceinline__ uint32_t smem_u32(const void* p){
    uint32_t a; asm("{ .reg .u64 t; cvta.to.shared.u64 t, %1; cvt.u32.u64 %0, t; }":"=r"(a):"l"(p)); return a;
}
__device__ __forceinline__ void cpa16(uint32_t d, const void* s, bool v){
    asm volatile("cp.async.cg.shared.global [%0],[%1],16,%2;"::"r"(d),"l"(s),"r"(v?16:0));
}
__device__ __forceinline__ void ldmx4(uint32_t* r, uint32_t a){
    asm volatile("ldmatrix.sync.aligned.m8n8.x4.shared.b16 {%0,%1,%2,%3},[%4];"
        :"=r"(r[0]),"=r"(r[1]),"=r"(r[2]),"=r"(r[3]):"r"(a));
}
__device__ __forceinline__ void mma_bf16(float* c, const uint32_t* a, const uint32_t* b){
    asm volatile("mma.sync.aligned.m16n8k16.row.col.f32.bf16.bf16.f32 "
        "{%0,%1,%2,%3},{%4,%5,%6,%7},{%8,%9},{%0,%1,%2,%3};"
        :"+f"(c[0]),"+f"(c[1]),"+f"(c[2]),"+f"(c[3])
        :"r"(a[0]),"r"(a[1]),"r"(a[2]),"r"(a[3]),"r"(b[0]),"r"(b[1]));
}

#define STG 20480
#define GSMEM (4*STG)

#define MMA_COMPUTE(ta, tb) \
    _Pragma("unroll") \
    for (int s = 0; s < 2; s++) { \
        uint32_t af[4][4], bq[4][2]; \
        _Pragma("unroll") \
        for (int mt = 0; mt < 4; mt++) \
            ldmx4(af[mt], (ta) + (uint32_t)((wm*64+mt*16+(g&1)*8+r8)*80 + (g>>1)*16 + s*32)); \
        _Pragma("unroll") \
        for (int np = 0; np < 2; np++) { \
            uint32_t t4[4]; \
            ldmx4(t4, (tb) + (uint32_t)((wn*32+np*16+(g>>1)*8+r8)*80 + (g&1)*16 + s*32)); \
            bq[np*2][0]=t4[0]; bq[np*2][1]=t4[1]; bq[np*2+1][0]=t4[2]; bq[np*2+1][1]=t4[3]; \
        } \
        _Pragma("unroll") \
        for (int mt = 0; mt < 4; mt++) \
            _Pragma("unroll") \
            for (int nt = 0; nt < 4; nt++) \
                mma_bf16(acc[mt][nt], af[mt], bq[nt]); \
    }

// hoisted-address mainloop: per-thread row pointers fixed, per-chunk offset = c<<5
#define GEMM_MAINLOOP(Aptr, Bptr, MMd, NNd, KKd, llda, lldb) \
    const int rowL = tid>>1, sgA = (tid&1)*2; \
    const bool vA = (m0+rowL)<(MMd), vB = (n0+rowL)<(NNd); \
    const bf16* pA = (Aptr) + (vA?((size_t)(m0+rowL)*(llda)):0) + sgA*8; \
    const bf16* pB = (Bptr) + (vB?((size_t)(n0+rowL)*(lldb)):0) + sgA*8; \
    const uint32_t dA = rowL*80+sgA*16, dB = 10240+rowL*80+sgA*16; \
    auto LD = [&](int c){ \
        if (c < NC) { \
            uint32_t st = sb + (c&3)*STG; \
            int k0 = c<<5; \
            bool k0ok = (k0+sgA*8)<(KKd), k1ok = (k0+sgA*8+8)<(KKd); \
            cpa16(st+dA,    pA+k0,   vA&&k0ok); \
            cpa16(st+dA+16, pA+k0+8, vA&&k1ok); \
            cpa16(st+dB,    pB+k0,   vB&&k0ok); \
            cpa16(st+dB+16, pB+k0+8, vB&&k1ok); \
        } \
        asm volatile("cp.async.commit_group;":::"memory"); \
    }; \
    LD(0); LD(1); LD(2); \
    for (int c=0;c<NC;c++){ \
        asm volatile("cp.async.wait_group 2;":::"memory"); \
        __syncthreads(); \
        uint32_t ta = sb+(c&3)*STG, tb = ta+10240; \
        MMA_COMPUTE(ta, tb); \
        LD(c+3); \
    }

// generic body: C[M,N]=A[M,K]*B^T, A=[i][k], B=[j][k]. OUTM: 0=f32, 1=bf16
template<int OUTM>
__device__ __forceinline__ void gbody(const bf16* __restrict__ A, const bf16* __restrict__ B,
    void* __restrict__ Cv, int Md, int Nd, int Kd, int lda, int ldb, int ldc, int m0, int n0)
{
    extern __shared__ char smc[];
    const int tid = threadIdx.x, lane = tid&31, wid = tid>>5;
    const int wm = wid>>2, wn = wid&3, g = lane>>3, r8 = lane&7;
    uint32_t sb = smem_u32(smc);
    float acc[4][4][4];
#pragma unroll
    for (int a=0;a<4;a++)
#pragma unroll
        for (int b=0;b<4;b++)
#pragma unroll
            for (int c=0;c<4;c++) acc[a][b][c]=0.f;
    const int NC = (Kd+31)>>5;
    GEMM_MAINLOOP(A, B, Md, Nd, Kd, lda, ldb)
#pragma unroll
    for (int mt=0;mt<4;mt++){
        int r0 = m0+wm*64+mt*16+(lane>>2);
#pragma unroll
        for (int nt=0;nt<4;nt++){
            int c0 = n0+wn*32+nt*8+(lane&3)*2;
            if (c0 >= Nd) continue;
            float x0=acc[mt][nt][0],x1=acc[mt][nt][1],x2=acc[mt][nt][2],x3=acc[mt][nt][3];
            if (OUTM==0){
                float* C=(float*)Cv;
                if (r0<Md)   *(float2*)&C[(size_t)r0*ldc+c0]     = make_float2(x0,x1);
                if (r0+8<Md) *(float2*)&C[(size_t)(r0+8)*ldc+c0] = make_float2(x2,x3);
            } else {
                bf16* C=(bf16*)Cv;
                if (r0<Md)   *(bf162*)&C[(size_t)r0*ldc+c0]     = __floats2bfloat162_rn(x0,x1);
                if (r0+8<Md) *(bf162*)&C[(size_t)(r0+8)*ldc+c0] = __floats2bfloat162_rn(x2,x3);
            }
        }
    }
}

template<int OUTM>
__global__ void __launch_bounds__(256,2)
bgemm(const bf16* __restrict__ A, const bf16* __restrict__ B, void* __restrict__ Cv,
      int Md, int Nd, int Kd, int lda, int ldb, int ldc, size_t sA, size_t sB, size_t sC)
{
    const int z = blockIdx.z;
    void* C = (OUTM==0) ? (void*)((float*)Cv+(size_t)z*sC) : (void*)((bf16*)Cv+(size_t)z*sC);
    gbody<OUTM>(A+(size_t)z*sA, B+(size_t)z*sB, C, Md, Nd, Kd, lda, ldb, ldc,
                blockIdx.y*128, blockIdx.x*128);
}

// S GEMM: E=exp(WvT·VbT^T), ET via swizzled smem, + per-warp row/col partial sums
__global__ void __launch_bounds__(256,2)
sgemm(const bf16* __restrict__ WvT, const bf16* __restrict__ VbT,
      bf16* __restrict__ Ep, bf16* __restrict__ ETp,
      float* __restrict__ rps, float* __restrict__ cps)
{
    extern __shared__ char smc[];
    const int z = blockIdx.z;
    const bf16* A = WvT + (size_t)z*NCn;
    const bf16* B = VbT + (size_t)z*NCn;
    bf16* Eb  = Ep  + (size_t)z*NN;
    bf16* ETb = ETp + (size_t)z*NN;
    const int m0 = blockIdx.y*128, n0 = blockIdx.x*128;
    const int tid = threadIdx.x, lane = tid&31, wid = tid>>5;
    const int wm = wid>>2, wn = wid&3, g = lane>>3, r8 = lane&7;
    uint32_t sb = smem_u32(smc);
    float acc[4][4][4];
#pragma unroll
    for (int a=0;a<4;a++)
#pragma unroll
        for (int b=0;b<4;b++)
#pragma unroll
            for (int c=0;c<4;c++) acc[a][b][c]=0.f;
    const int NC = 8;
    GEMM_MAINLOOP(A, B, NPix, NPix, CC, CC, CC)

    __syncthreads();
    bf16* sh = (bf16*)smc;
    float rp0[4]={0,0,0,0}, rp1[4]={0,0,0,0};
    float cq0[4]={0,0,0,0}, cq1[4]={0,0,0,0};
#pragma unroll
    for (int mt=0;mt<4;mt++){
        int rl0 = wm*64+mt*16+(lane>>2);
        int r0 = m0+rl0;
        bool rok0 = r0<NPix, rok1 = (r0+8)<NPix;
#pragma unroll
        for (int nt=0;nt<4;nt++){
            int cl0 = wn*32+nt*8+(lane&3)*2;
            int c0 = n0+cl0;
            bool cok = c0<NPix;
            float x0=__expf(acc[mt][nt][0]),x1=__expf(acc[mt][nt][1]);
            float x2=__expf(acc[mt][nt][2]),x3=__expf(acc[mt][nt][3]);
            if (cok) {
                if (rok0) *(bf162*)&Eb[(size_t)r0*NPix+c0]     = __floats2bfloat162_rn(x0,x1);
                if (rok1) *(bf162*)&Eb[(size_t)(r0+8)*NPix+c0] = __floats2bfloat162_rn(x2,x3);
                rp0[mt]+=x0+x1; rp1[mt]+=x2+x3;
            }
            if (rok0){ cq0[nt]+=x0; cq1[nt]+=x1; }
            if (rok1){ cq0[nt]+=x2; cq1[nt]+=x3; }
#define TST(rr,cc,xx) sh[(cc)*136 + (((((rr)>>3)^((cc)>>3))&15)<<3) + ((rr)&7)] = __float2bfloat16(xx)
            TST(rl0,   cl0,   x0); TST(rl0,   cl0+1, x1);
            TST(rl0+8, cl0,   x2); TST(rl0+8, cl0+1, x3);
#undef TST
        }
    }
    // row partials: reduce across the 4 column-lanes
#pragma unroll
    for (int mt=0;mt<4;mt++){
#pragma unroll
        for (int o=1;o<=2;o<<=1){
            rp0[mt]+=__shfl_xor_sync(~0u,rp0[mt],o);
            rp1[mt]+=__shfl_xor_sync(~0u,rp1[mt],o);
        }
    }
    if ((lane&3)==0){
        float* rp = rps + ((size_t)z*116 + blockIdx.x*4 + wn)*NPix;
#pragma unroll
        for (int mt=0;mt<4;mt++){
            int r0 = m0+wm*64+mt*16+(lane>>2);
            if (r0<NPix)   rp[r0]   = rp0[mt];
            if (r0+8<NPix) rp[r0+8] = rp1[mt];
        }
    }
    // col partials: reduce across the 8 row-lanes
#pragma unroll
    for (int nt=0;nt<4;nt++){
#pragma unroll
        for (int o=4;o<=16;o<<=1){
            cq0[nt]+=__shfl_xor_sync(~0u,cq0[nt],o);
            cq1[nt]+=__shfl_xor_sync(~0u,cq1[nt],o);
        }
    }
    if (lane<4){
        float* cp = cps + ((size_t)z*116 + blockIdx.y*4 + wm)*NPix;
#pragma unroll
        for (int nt=0;nt<4;nt++){
            int c0 = n0+wn*32+nt*8+(lane&3)*2;
            if (c0<NPix){ cp[c0]=cq0[nt]; cp[c0+1]=cq1[nt]; }
        }
    }
    __syncthreads();
#pragma unroll
    for (int rr=0; rr<16; rr++){
        int cp2 = wid*16 + rr;
        int mg = n0 + cp2;
        if (mg >= NPix) continue;
        int cb = cp2>>3;
        int rb = lane>>1, half = lane&1;
        int ng = m0 + rb*8 + half*4;
        if (ng >= NPix) continue;
        uint2 v = *(uint2*)(sh + cp2*136 + (((rb^cb)&15)<<3) + half*4);
        *(uint2*)&ETb[(size_t)mg*NPix + ng] = v;
    }
}

// both Z GEMMs: z=0,1 -> att1 (A=E,B=Vbb), z=2,3 -> att2 (A=ET,B=Vab)
__global__ void __launch_bounds__(256,2)
zpair(const bf16* __restrict__ E, const bf16* __restrict__ ET,
      const bf16* __restrict__ Vab, const bf16* __restrict__ Vbb,
      float* __restrict__ a1f, float* __restrict__ a2f)
{
    int z = blockIdx.z, br = z>>1, b = z&1;
    const bf16* A = (br?ET:E) + (size_t)b*NN;
    const bf16* B = (br?Vab:Vbb) + (size_t)b*CN;
    float* C = (br?a2f:a1f) + (size_t)b*NCn;
    gbody<0>(A, B, C, NPix, CC, NPix, NPix, NPix, CC, blockIdx.y*128, blockIdx.x*128);
}

// both convs: z=0,1 conv1 (3 srcs), z=2,3 conv2 (2 srcs); 9 shifted accumulated GEMMs
__global__ void __launch_bounds__(256,2)
convpair(const bf16* __restrict__ a1b, const bf16* __restrict__ a2b,
         const bf16* __restrict__ VaT, const bf16* __restrict__ VbT, const bf16* __restrict__ DaT,
         const bf16* __restrict__ wr1, const bf16* __restrict__ wr2,
         float* __restrict__ x1T, float* __restrict__ x2T)
{
    extern __shared__ char smc[];
    int zz = blockIdx.z, br = zz>>1, b = zz&1;
    const bf16 *s0 = br?a2b:a1b, *s1 = br?VbT:VaT, *s2 = br?VbT:DaT;
    const bf16 *W = br?wr2:wr1;
    float* out = br?x2T:x1T;
    const int SR = br?2:3;
    const int LDB = SR*256, KPC = SR*8, NC = 9*KPC;
    const size_t so = (size_t)b*NCn;
    const int m0 = blockIdx.y*128, n0 = blockIdx.x*128;
    const int tid = threadIdx.x, lane = tid&31, wid = tid>>5;
    const int wm = wid>>2, wn = wid&3, g = lane>>3, r8 = lane&7;
    uint32_t sb = smem_u32(smc);
    float acc[4][4][4];
#pragma unroll
    for (int a=0;a<4;a++)
#pragma unroll
        for (int bb=0;bb<4;bb++)
#pragma unroll
            for (int c=0;c<4;c++) acc[a][bb][c]=0.f;

    // per-thread precompute
    const int rowL = tid>>1, sgA = (tid&1)*2;
    const int j = m0+rowL;
    const bool jv = j<NPix;
    const int h = (jv?j:0)/60, w = (jv?j:0) - ((jv?j:0)/60)*60;
    uint32_t vmask = 0;
#pragma unroll
    for (int rr=0;rr<9;rr++){
        int dh = rr/3-1, dw = rr-(rr/3)*3-1;
        if (jv && (unsigned)(h+dh)<60u && (unsigned)(w+dw)<60u) vmask |= 1u<<rr;
    }
    const size_t jb = (size_t)(jv?j:0)*CC + sgA*8;
    const bf16 *pS0 = s0+so+jb, *pS1 = s1+so+jb, *pS2 = s2+so+jb;
    const bf16 *pW = W + (size_t)(n0+rowL)*LDB + sgA*8;
    const uint32_t dAs = rowL*80+sgA*16, dBs = 10240+rowL*80+sgA*16;

    int ld_vc = 0, ld_rr = 0, ld_kc = 0, ld_dh = -1, ld_dw = -1;
    size_t woff = 0;
    auto LD = [&](){
        if (ld_vc < NC) {
            uint32_t st = sb + (ld_vc&3)*STG;
            bool vv = (vmask>>ld_rr)&1;
            int off = ld_dh*60 + ld_dw;
            int srcSel = ld_kc>>3;
            const bf16* sp = (srcSel==0)?pS0:((srcSel==1)?pS1:pS2);
            const bf16* ap = sp + (intptr_t)off*CC + (ld_kc&7)*32;
            cpa16(st+dAs,    vv?ap:s0,     vv);
            cpa16(st+dAs+16, vv?(ap+8):s0, vv);
            cpa16(st+dBs,    pW+woff,   true);
            cpa16(st+dBs+16, pW+woff+8, true);
            ld_vc++; ld_kc++; woff += 32;
            if (ld_kc == KPC) {
                ld_kc = 0; ld_rr++;
                woff += (size_t)(CC-1)*LDB;
                ld_dw++; if (ld_dw==2){ ld_dw=-1; ld_dh++; }
            }
        }
        asm volatile("cp.async.commit_group;":::"memory");
    };
    LD(); LD(); LD();
    for (int c=0;c<NC;c++){
        asm volatile("cp.async.wait_group 2;":::"memory");
        __syncthreads();
        uint32_t ta = sb+(c&3)*STG, tb = ta+10240;
        MMA_COMPUTE(ta, tb);
        LD();
    }
    float* C = out + so;
#pragma unroll
    for (int mt=0;mt<4;mt++){
        int r0 = m0+wm*64+mt*16+(lane>>2);
#pragma unroll
        for (int nt=0;nt<4;nt++){
            int c0 = n0+wn*32+nt*8+(lane&3)*2;
            if (r0<NPix)   *(float2*)&C[(size_t)r0*CC+c0]     = make_float2(acc[mt][nt][0],acc[mt][nt][1]);
            if (r0+8<NPix) *(float2*)&C[(size_t)(r0+8)*CC+c0] = make_float2(acc[mt][nt][2],acc[mt][nt][3]);
        }
    }
}

__global__ void wprep(const float* __restrict__ W_e, const float* __restrict__ c1w,
                      const float* __restrict__ c2w, bf16* __restrict__ Web,
                      bf16* __restrict__ wr1, bf16* __restrict__ wr2)
{
    int idx = blockIdx.x*256+threadIdx.x;
    const int N0 = CC*CC, N1 = 9*CC*768, N2 = 9*CC*512;
    if (idx < N0) { Web[idx] = __float2bfloat16(W_e[idx]); return; }
    idx -= N0;
    if (idx < N1) {
        int r = idx/(CC*768), rem = idx - r*(CC*768);
        int co = rem/768, ci = rem - co*768;
        wr1[idx] = __float2bfloat16(c1w[(size_t)co*768*9 + ci*9 + r]);
        return;
    }
    idx -= N1;
    if (idx < N2) {
        int r = idx/(CC*512), rem = idx - r*(CC*512);
        int co = rem/512, ci = rem - co*512;
        wr2[idx] = __float2bfloat16(c2w[(size_t)co*512*9 + ci*9 + r]);
    }
}

__global__ void trans3(const float* __restrict__ Va, const float* __restrict__ Vb,
                       const float* __restrict__ Da,
                       bf16* __restrict__ VaT, bf16* __restrict__ VbT, bf16* __restrict__ DaT,
                       bf16* __restrict__ Vab, bf16* __restrict__ Vbb)
{
    __shared__ float t[32][33];
    int z = blockIdx.z, src = z>>1, b = z&1;
    const float* in = (src==0?Va:(src==1?Vb:Da)) + (size_t)b*CN;
    bf16* outT = (src==0?VaT:(src==1?VbT:DaT)) + (size_t)b*NCn;
    bf16* outN = (src==0?Vab:(src==1?Vbb:(bf16*)nullptr));
    if (outN) outN += (size_t)b*CN;
    int c0 = blockIdx.x*32, r0 = blockIdx.y*32;
    int tx = threadIdx.x&31, ty = threadIdx.x>>5;
#pragma unroll
    for (int i=0;i<4;i++){
        int rr=r0+ty+i*8, cc=c0+tx;
        if (cc<NPix){
            float v = in[(size_t)rr*NPix+cc];
            t[ty+i*8][tx] = v;
            if (outN) outN[(size_t)rr*NPix+cc] = __float2bfloat16(v);
        }
    }
    __syncthreads();
#pragma unroll
    for (int i=0;i<4;i++){
        int cc=c0+ty+i*8, rr=r0+tx;
        if (cc<NPix) outT[(size_t)cc*CC+rr] = __float2bfloat16(t[tx][ty+i*8]);
    }
}

// combine per-tile partials -> 1/rowsum, 1/colsum
__global__ void sumcomb_k(const float* __restrict__ rps, const float* __restrict__ cps,
                          float* __restrict__ ri, float* __restrict__ ci)
{
    int i = blockIdx.x*256+threadIdx.x;
    int zz = blockIdx.y;
    if (i >= BB*NPix) return;
    int b = i/NPix, r = i - b*NPix;
    const float* p = (zz?cps:rps) + (size_t)b*116*NPix + r;
    float s = 0.f;
#pragma unroll 4
    for (int t=0;t<116;t++) s += p[(size_t)t*NPix];
    (zz?ci:ri)[i] = 1.f/s;
}

__global__ void gatew_k(const float* __restrict__ a1f, const float* __restrict__ a2f,
                        const float* __restrict__ ri, const float* __restrict__ ci,
                        const float* __restrict__ gw,
                        bf16* __restrict__ a1b, bf16* __restrict__ a2b)
{
    int z = blockIdx.z;
    const float* Z = z?a2f:a1f;
    const float* iv = z?ci:ri;
    bf16* out = z?a2b:a1b;
    __shared__ float w[CC];
    int tid = threadIdx.x;
    for (int c=tid;c<CC;c+=256) w[c]=gw[c];
    __syncthreads();
    int lane=tid&31, wid=tid>>5;
    int p = blockIdx.x*8+wid, b = blockIdx.y;
    const float* zp = Z + ((size_t)b*NPix+p)*CC + lane*8;
    float4 u0=*(const float4*)zp, u1=*(const float4*)(zp+4);
    float vv[8]={u0.x,u0.y,u0.z,u0.w,u1.x,u1.y,u1.z,u1.w};
    int c8=lane*8;
    float d=0.f;
#pragma unroll
    for (int u=0;u<8;u++) d += vv[u]*w[c8+u];
#pragma unroll
    for (int o=16;o;o>>=1) d += __shfl_xor_sync(~0u,d,o);
    float m = iv[b*NPix+p];
    float mul = m/(1.f+__expf(-d*m));
    bf162 o0=__floats2bfloat162_rn(vv[0]*mul,vv[1]*mul), o1=__floats2bfloat162_rn(vv[2]*mul,vv[3]*mul);
    bf162 o2=__floats2bfloat162_rn(vv[4]*mul,vv[5]*mul), o3=__floats2bfloat162_rn(vv[6]*mul,vv[7]*mul);
    uint4 st; st.x=*(uint32_t*)&o0; st.y=*(uint32_t*)&o1; st.z=*(uint32_t*)&o2; st.w=*(uint32_t*)&o3;
    *(uint4*)(out + ((size_t)b*NPix+p)*CC + c8) = st;
}

__global__ void bnpart_k(const float* __restrict__ x1T, const float* __restrict__ x2T,
                         float* __restrict__ ps, float* __restrict__ pq)
{
    int z = blockIdx.z;
    const float* x = z?x2T:x1T;
    int c = threadIdx.x, b = blockIdx.y, blk = blockIdx.x;
    int n0 = blk*128, nend = min(n0+128, NPix);
    const float* xp = x + (size_t)b*NCn + c;
    float s=0.f, q=0.f;
    for (int n=n0;n<nend;n++){ float v=xp[(size_t)n*CC]; s+=v; q+=v*v; }
    int p = z*58 + b*29 + blk;
    ps[p*CC+c]=s; pq[p*CC+c]=q;
}

__global__ void bncomb_k(const float* __restrict__ ps, const float* __restrict__ pq,
                         const float* __restrict__ g1, const float* __restrict__ b1,
                         const float* __restrict__ g2, const float* __restrict__ b2,
                         float* __restrict__ sc, float* __restrict__ sh)
{
    int c = threadIdx.x, z = blockIdx.x;
    float s=0.f, q=0.f;
    for (int p=z*58;p<z*58+58;p++){ s+=ps[p*CC+c]; q+=pq[p*CC+c]; }
    const float inv = 1.f/(BB*NPix);
    float mean=s*inv, var=q*inv-mean*mean;
    float k = (z?g2:g1)[c]*rsqrtf(var+1e-5f);
    sc[z*CC+c]=k; sh[z*CC+c]=(z?b2:b1)[c]-mean*k;
}

__global__ void bncls_k(const float* __restrict__ x1T, const float* __restrict__ x2T,
                        const float* __restrict__ sc, const float* __restrict__ sh,
                        const float* __restrict__ c1w, const float* __restrict__ c1b,
                        const float* __restrict__ c2w, const float* __restrict__ c2b,
                        float* __restrict__ y1, float* __restrict__ y2)
{
    int z = blockIdx.z;
    const float* x = z?x2T:x1T;
    const float* cw = z?c2w:c1w;
    const float* cb = z?c2b:c1b;
    float* y = z?y2:y1;
    __shared__ float ssc[CC], ssh[CC], w0[CC], w1[CC];
    int tid = threadIdx.x;
    for (int c=tid;c<CC;c+=256){ ssc[c]=sc[z*CC+c]; ssh[c]=sh[z*CC+c]; w0[c]=cw[c]; w1[c]=cw[CC+c]; }
    __syncthreads();
    int lane=tid&31, wid=tid>>5;
    int p = blockIdx.x*8+wid, b = blockIdx.y;
    const float* xp = x + ((size_t)b*NPix+p)*CC + lane*8;
    float4 u0=*(const float4*)xp, u1=*(const float4*)(xp+4);
    float vv[8]={u0.x,u0.y,u0.z,u0.w,u1.x,u1.y,u1.z,u1.w};
    int c8=lane*8;
    float a0=0.f, a1=0.f;
#pragma unroll
    for (int u=0;u<8;u++){
        float v = fmaxf(vv[u]*ssc[c8+u]+ssh[c8+u], 0.f);
        a0 += v*w0[c8+u]; a1 += v*w1[c8+u];
    }
#pragma unroll
    for (int o=16;o;o>>=1){ a0+=__shfl_xor_sync(~0u,a0,o); a1+=__shfl_xor_sync(~0u,a1,o); }
    if (lane==0){
        y[(size_t)(b*NCls+0)*NPix+p] = a0+cb[0];
        y[(size_t)(b*NCls+1)*NPix+p] = a1+cb[1];
    }
}

__global__ void resize_k(float* __restrict__ out)
{
    const size_t per = (size_t)BB*NCls*HOUT*WOUT;
    size_t idx = (size_t)blockIdx.x*256+threadIdx.x;
    if (idx >= 2*per) return;
    int t = idx >= per;
    size_t r = idx - (size_t)t*per;
    int x=(int)(r%WOUT); r/=WOUT;
    int y=(int)(r%HOUT); r/=HOUT;
    int kc=(int)(r%NCls); int b=(int)(r/NCls);
    const float* src = (t?g_y2:g_y1) + (size_t)(b*NCls+kc)*NPix;
    const float sc = 60.f/473.f;
    float syf=(y+0.5f)*sc-0.5f, sxf=(x+0.5f)*sc-0.5f;
    float fy0=floorf(syf), fx0=floorf(sxf);
    float fy=syf-fy0, fx=sxf-fx0;
    int y0=max((int)fy0,0), x0=max((int)fx0,0);
    int y1i=min((int)fy0+1,59), x1i=min((int)fx0+1,59);
    float v00=src[y0*60+x0], v01=src[y0*60+x1i], v10=src[y1i*60+x0], v11=src[y1i*60+x1i];
    float vt=v00+(v01-v00)*fx, vb=v10+(v11-v10)*fx;
    out[idx] = 1.f/(1.f+__expf(-(vt+(vb-vt)*fy)));
}

extern "C" void kernel_launch(void* const* d_in, const int* in_sizes, int n_in,
                              void* d_out, int out_size)
{
    const float *V_a=(const float*)d_in[0], *V_b=(const float*)d_in[1], *D_a=(const float*)d_in[2];
    const float *W_e=(const float*)d_in[3], *gate_w=(const float*)d_in[4];
    const float *c1w=(const float*)d_in[5], *c2w=(const float*)d_in[6];
    const float *bn1g=(const float*)d_in[7], *bn1b=(const float*)d_in[8];
    const float *bn2g=(const float*)d_in[9], *bn2b=(const float*)d_in[10];
    const float *cl1w=(const float*)d_in[11], *cl1b=(const float*)d_in[12];
    const float *cl2w=(const float*)d_in[13], *cl2b=(const float*)d_in[14];
    float* out = (float*)d_out;

    bf16 *Vab,*Vbb,*Web,*wr1,*wr2,*VaT,*VbT,*DaT,*WvT,*E,*ET,*a1b,*a2b;
    float *a1f,*a2f,*x1T,*x2T,*ri,*ci,*bp,*bq,*bsc,*bsh,*y1,*y2,*rps,*cps;
    cudaGetSymbolAddress((void**)&Vab,g_Vab);  cudaGetSymbolAddress((void**)&Vbb,g_Vbb);
    cudaGetSymbolAddress((void**)&Web,g_Web);  cudaGetSymbolAddress((void**)&wr1,g_wr1);
    cudaGetSymbolAddress((void**)&wr2,g_wr2);  cudaGetSymbolAddress((void**)&VaT,g_VaT);
    cudaGetSymbolAddress((void**)&VbT,g_VbT);  cudaGetSymbolAddress((void**)&DaT,g_DaT);
    cudaGetSymbolAddress((void**)&WvT,g_WvT);  cudaGetSymbolAddress((void**)&E,g_E);
    cudaGetSymbolAddress((void**)&ET,g_ET);
    cudaGetSymbolAddress((void**)&a1b,g_a1Tb); cudaGetSymbolAddress((void**)&a2b,g_a2Tb);
    cudaGetSymbolAddress((void**)&a1f,g_a1Tf); cudaGetSymbolAddress((void**)&a2f,g_a2Tf);
    cudaGetSymbolAddress((void**)&x1T,g_x1T);  cudaGetSymbolAddress((void**)&x2T,g_x2T);
    cudaGetSymbolAddress((void**)&ri,g_rowinv);cudaGetSymbolAddress((void**)&ci,g_colinv);
    cudaGetSymbolAddress((void**)&bp,g_bp);    cudaGetSymbolAddress((void**)&bq,g_bq);
    cudaGetSymbolAddress((void**)&bsc,g_bnsc); cudaGetSymbolAddress((void**)&bsh,g_bnsh);
    cudaGetSymbolAddress((void**)&y1,g_y1);    cudaGetSymbolAddress((void**)&y2,g_y2);
    cudaGetSymbolAddress((void**)&rps,g_rps);  cudaGetSymbolAddress((void**)&cps,g_cps);

    cudaFuncSetAttribute(bgemm<1>, cudaFuncAttributeMaxDynamicSharedMemorySize, GSMEM);
    cudaFuncSetAttribute(sgemm,    cudaFuncAttributeMaxDynamicSharedMemorySize, GSMEM);
    cudaFuncSetAttribute(zpair,    cudaFuncAttributeMaxDynamicSharedMemorySize, GSMEM);
    cudaFuncSetAttribute(convpair, cudaFuncAttributeMaxDynamicSharedMemorySize, GSMEM);

    const int WTOT = CC*CC + 9*CC*768 + 9*CC*512;
    wprep<<<(WTOT+255)/256,256>>>(W_e, c1w, c2w, Web, wr1, wr2);
    trans3<<<dim3(113,8,6),256>>>(V_a, V_b, D_a, VaT, VbT, DaT, Vab, Vbb);
    bgemm<1><<<dim3(2,29,BB),256,GSMEM>>>(VaT, Web, WvT, NPix, CC, CC, CC, CC, CC, NCn, 0, NCn);
    sgemm<<<dim3(29,29,BB),256,GSMEM>>>(WvT, VbT, E, ET, rps, cps);
    sumcomb_k<<<dim3((BB*NPix+255)/256,2),256>>>(rps, cps, ri, ci);
    zpair<<<dim3(2,29,4),256,GSMEM>>>(E, ET, Vab, Vbb, a1f, a2f);
    gatew_k<<<dim3(450,BB,2),256>>>(a1f, a2f, ri, ci, gate_w, a1b, a2b);
    convpair<<<dim3(2,29,4),256,GSMEM>>>(a1b, a2b, VaT, VbT, DaT, wr1, wr2, x1T, x2T);
    bnpart_k<<<dim3(29,BB,2),256>>>(x1T, x2T, bp, bq);
    bncomb_k<<<2,256>>>(bp, bq, bn1g, bn1b, bn2g, bn2b, bsc, bsh);
    bncls_k<<<dim3(450,BB,2),256>>>(x1T, x2T, bsc, bsh, cl1w, cl1b, cl2w, cl2b, y1, y2);
    const size_t total = 2ull*BB*NCls*HOUT*WOUT;
    resize_k<<<(int)((total+255)/256),256>>>(out);
}

// round 10
// speedup vs baseline: 6.5586x; 1.0105x over previous
#include <cuda_runtime.h>
#include <cuda_bf16.h>
#include <cstdint>
#include <math.h>

#define BB 2
#define CC 256
#define NPix 3600
#define NCls 2
#define HOUT 473
#define WOUT 473
typedef __nv_bfloat16 bf16;
typedef __nv_bfloat162 bf162;

static const size_t CN = (size_t)CC*NPix, NN = (size_t)NPix*NPix, NCn = (size_t)NPix*CC;

__device__ bf16 g_Vab[BB*CC*NPix], g_Vbb[BB*CC*NPix];
__device__ bf16 g_Web[CC*CC];
__device__ bf16 g_wr1[9*CC*768], g_wr2[9*CC*512];
__device__ bf16 g_VaT[BB*NPix*CC], g_VbT[BB*NPix*CC], g_DaT[BB*NPix*CC], g_WvT[BB*NPix*CC];
__device__ bf16 g_E[(size_t)BB*NPix*NPix], g_ET[(size_t)BB*NPix*NPix];
__device__ bf16 g_a1Tb[BB*NPix*CC], g_a2Tb[BB*NPix*CC];
__device__ float g_x1T[BB*NPix*CC], g_x2T[BB*NPix*CC];
__device__ float g_rps[(size_t)BB*116*NPix], g_cps[(size_t)BB*116*NPix];
__device__ float g_rowinv[BB*NPix], g_colinv[BB*NPix];
__device__ float g_bp[2*58*CC], g_bq[2*58*CC];
__device__ float g_bnsc[2*CC], g_bnsh[2*CC];
__device__ float g_y1[BB*NCls*NPix], g_y2[BB*NCls*NPix];

__device__ __forceinline__ uint32_t smem_u32(const void* p){
    uint32_t a; asm("{ .reg .u64 t; cvta.to.shared.u64 t, %1; cvt.u32.u64 %0, t; }":"=r"(a):"l"(p)); return a;
}
__device__ __forceinline__ void cpa16(uint32_t d, const void* s, bool v){
    asm volatile("cp.async.cg.shared.global [%0],[%1],16,%2;"::"r"(d),"l"(s),"r"(v?16:0));
}
__device__ __forceinline__ void ldmx4(uint32_t* r, uint32_t a){
    asm volatile("ldmatrix.sync.aligned.m8n8.x4.shared.b16 {%0,%1,%2,%3},[%4];"
        :"=r"(r[0]),"=r"(r[1]),"=r"(r[2]),"=r"(r[3]):"r"(a));
}
__device__ __forceinline__ void mma_bf16(float* c, const uint32_t* a, const uint32_t* b){
    asm volatile("mma.sync.aligned.m16n8k16.row.col.f32.bf16.bf16.f32 "
        "{%0,%1,%2,%3},{%4,%5,%6,%7},{%8,%9},{%0,%1,%2,%3};"
        :"+f"(c[0]),"+f"(c[1]),"+f"(c[2]),"+f"(c[3])
        :"r"(a[0]),"r"(a[1]),"r"(a[2]),"r"(a[3]),"r"(b[0]),"r"(b[1]));
}

#define STG 20480
#define GSMEM (4*STG)

#define MMA_COMPUTE(ta, tb) \
    _Pragma("unroll") \
    for (int s = 0; s < 2; s++) { \
        uint32_t af[4][4], bq[4][2]; \
        _Pragma("unroll") \
        for (int mt = 0; mt < 4; mt++) \
            ldmx4(af[mt], (ta) + (uint32_t)((wm*64+mt*16+(g&1)*8+r8)*80 + (g>>1)*16 + s*32)); \
        _Pragma("unroll") \
        for (int np = 0; np < 2; np++) { \
            uint32_t t4[4]; \
            ldmx4(t4, (tb) + (uint32_t)((wn*32+np*16+(g>>1)*8+r8)*80 + (g&1)*16 + s*32)); \
            bq[np*2][0]=t4[0]; bq[np*2][1]=t4[1]; bq[np*2+1][0]=t4[2]; bq[np*2+1][1]=t4[3]; \
        } \
        _Pragma("unroll") \
        for (int mt = 0; mt < 4; mt++) \
            _Pragma("unroll") \
            for (int nt = 0; nt < 4; nt++) \
                mma_bf16(acc[mt][nt], af[mt], bq[nt]); \
    }

#define GEMM_MAINLOOP(Aptr, Bptr, MMd, NNd, KKd, llda, lldb) \
    const int rowL = tid>>1, sgA = (tid&1)*2; \
    const bool vA = (m0+rowL)<(MMd), vB = (n0+rowL)<(NNd); \
    const bf16* pA = (Aptr) + (vA?((size_t)(m0+rowL)*(llda)):0) + sgA*8; \
    const bf16* pB = (Bptr) + (vB?((size_t)(n0+rowL)*(lldb)):0) + sgA*8; \
    const uint32_t dA = rowL*80+sgA*16, dB = 10240+rowL*80+sgA*16; \
    auto LD = [&](int c){ \
        if (c < NC) { \
            uint32_t st = sb + (c&3)*STG; \
            int k0 = c<<5; \
            bool k0ok = (k0+sgA*8)<(KKd), k1ok = (k0+sgA*8+8)<(KKd); \
            cpa16(st+dA,    pA+k0,   vA&&k0ok); \
            cpa16(st+dA+16, pA+k0+8, vA&&k1ok); \
            cpa16(st+dB,    pB+k0,   vB&&k0ok); \
            cpa16(st+dB+16, pB+k0+8, vB&&k1ok); \
        } \
        asm volatile("cp.async.commit_group;":::"memory"); \
    }; \
    LD(0); LD(1); LD(2); \
    for (int c=0;c<NC;c++){ \
        asm volatile("cp.async.wait_group 2;":::"memory"); \
        __syncthreads(); \
        uint32_t ta = sb+(c&3)*STG, tb = ta+10240; \
        MMA_COMPUTE(ta, tb); \
        LD(c+3); \
    }

template<int OUTM>
__device__ __forceinline__ void gbody(const bf16* __restrict__ A, const bf16* __restrict__ B,
    void* __restrict__ Cv, int Md, int Nd, int Kd, int lda, int ldb, int ldc, int m0, int n0)
{
    extern __shared__ char smc[];
    const int tid = threadIdx.x, lane = tid&31, wid = tid>>5;
    const int wm = wid>>2, wn = wid&3, g = lane>>3, r8 = lane&7;
    uint32_t sb = smem_u32(smc);
    float acc[4][4][4];
#pragma unroll
    for (int a=0;a<4;a++)
#pragma unroll
        for (int b=0;b<4;b++)
#pragma unroll
            for (int c=0;c<4;c++) acc[a][b][c]=0.f;
    const int NC = (Kd+31)>>5;
    GEMM_MAINLOOP(A, B, Md, Nd, Kd, lda, ldb)
#pragma unroll
    for (int mt=0;mt<4;mt++){
        int r0 = m0+wm*64+mt*16+(lane>>2);
#pragma unroll
        for (int nt=0;nt<4;nt++){
            int c0 = n0+wn*32+nt*8+(lane&3)*2;
            if (c0 >= Nd) continue;
            float x0=acc[mt][nt][0],x1=acc[mt][nt][1],x2=acc[mt][nt][2],x3=acc[mt][nt][3];
            if (OUTM==0){
                float* C=(float*)Cv;
                if (r0<Md)   *(float2*)&C[(size_t)r0*ldc+c0]     = make_float2(x0,x1);
                if (r0+8<Md) *(float2*)&C[(size_t)(r0+8)*ldc+c0] = make_float2(x2,x3);
            } else {
                bf16* C=(bf16*)Cv;
                if (r0<Md)   *(bf162*)&C[(size_t)r0*ldc+c0]     = __floats2bfloat162_rn(x0,x1);
                if (r0+8<Md) *(bf162*)&C[(size_t)(r0+8)*ldc+c0] = __floats2bfloat162_rn(x2,x3);
            }
        }
    }
}

template<int OUTM>
__global__ void __launch_bounds__(256,2)
bgemm(const bf16* __restrict__ A, const bf16* __restrict__ B, void* __restrict__ Cv,
      int Md, int Nd, int Kd, int lda, int ldb, int ldc, size_t sA, size_t sB, size_t sC)
{
    const int z = blockIdx.z;
    void* C = (OUTM==0) ? (void*)((float*)Cv+(size_t)z*sC) : (void*)((bf16*)Cv+(size_t)z*sC);
    gbody<OUTM>(A+(size_t)z*sA, B+(size_t)z*sB, C, Md, Nd, Kd, lda, ldb, ldc,
                blockIdx.y*128, blockIdx.x*128);
}

// S GEMM: E=exp(WvT·VbT^T), ET via swizzled smem, + per-warp row/col partial sums
__global__ void __launch_bounds__(256,2)
sgemm(const bf16* __restrict__ WvT, const bf16* __restrict__ VbT,
      bf16* __restrict__ Ep, bf16* __restrict__ ETp,
      float* __restrict__ rps, float* __restrict__ cps)
{
    extern __shared__ char smc[];
    const int z = blockIdx.z;
    const bf16* A = WvT + (size_t)z*NCn;
    const bf16* B = VbT + (size_t)z*NCn;
    bf16* Eb  = Ep  + (size_t)z*NN;
    bf16* ETb = ETp + (size_t)z*NN;
    const int m0 = blockIdx.y*128, n0 = blockIdx.x*128;
    const int tid = threadIdx.x, lane = tid&31, wid = tid>>5;
    const int wm = wid>>2, wn = wid&3, g = lane>>3, r8 = lane&7;
    uint32_t sb = smem_u32(smc);
    float acc[4][4][4];
#pragma unroll
    for (int a=0;a<4;a++)
#pragma unroll
        for (int b=0;b<4;b++)
#pragma unroll
            for (int c=0;c<4;c++) acc[a][b][c]=0.f;
    const int NC = 8;
    GEMM_MAINLOOP(A, B, NPix, NPix, CC, CC, CC)

    __syncthreads();
    bf16* sh = (bf16*)smc;
    float rp0[4]={0,0,0,0}, rp1[4]={0,0,0,0};
    float cq0[4]={0,0,0,0}, cq1[4]={0,0,0,0};
#pragma unroll
    for (int mt=0;mt<4;mt++){
        int rl0 = wm*64+mt*16+(lane>>2);
        int r0 = m0+rl0;
        bool rok0 = r0<NPix, rok1 = (r0+8)<NPix;
#pragma unroll
        for (int nt=0;nt<4;nt++){
            int cl0 = wn*32+nt*8+(lane&3)*2;
            int c0 = n0+cl0;
            bool cok = c0<NPix;
            float x0=__expf(acc[mt][nt][0]),x1=__expf(acc[mt][nt][1]);
            float x2=__expf(acc[mt][nt][2]),x3=__expf(acc[mt][nt][3]);
            if (cok) {
                if (rok0) *(bf162*)&Eb[(size_t)r0*NPix+c0]     = __floats2bfloat162_rn(x0,x1);
                if (rok1) *(bf162*)&Eb[(size_t)(r0+8)*NPix+c0] = __floats2bfloat162_rn(x2,x3);
                rp0[mt]+=x0+x1; rp1[mt]+=x2+x3;
            }
            if (rok0){ cq0[nt]+=x0; cq1[nt]+=x1; }
            if (rok1){ cq0[nt]+=x2; cq1[nt]+=x3; }
#define TST(rr,cc,xx) sh[(cc)*136 + (((((rr)>>3)^((cc)>>3))&15)<<3) + ((rr)&7)] = __float2bfloat16(xx)
            TST(rl0,   cl0,   x0); TST(rl0,   cl0+1, x1);
            TST(rl0+8, cl0,   x2); TST(rl0+8, cl0+1, x3);
#undef TST
        }
    }
#pragma unroll
    for (int mt=0;mt<4;mt++){
#pragma unroll
        for (int o=1;o<=2;o<<=1){
            rp0[mt]+=__shfl_xor_sync(~0u,rp0[mt],o);
            rp1[mt]+=__shfl_xor_sync(~0u,rp1[mt],o);
        }
    }
    if ((lane&3)==0){
        float* rp = rps + ((size_t)z*116 + blockIdx.x*4 + wn)*NPix;
#pragma unroll
        for (int mt=0;mt<4;mt++){
            int r0 = m0+wm*64+mt*16+(lane>>2);
            if (r0<NPix)   rp[r0]   = rp0[mt];
            if (r0+8<NPix) rp[r0+8] = rp1[mt];
        }
    }
#pragma unroll
    for (int nt=0;nt<4;nt++){
#pragma unroll
        for (int o=4;o<=16;o<<=1){
            cq0[nt]+=__shfl_xor_sync(~0u,cq0[nt],o);
            cq1[nt]+=__shfl_xor_sync(~0u,cq1[nt],o);
        }
    }
    if (lane<4){
        float* cp = cps + ((size_t)z*116 + blockIdx.y*4 + wm)*NPix;
#pragma unroll
        for (int nt=0;nt<4;nt++){
            int c0 = n0+wn*32+nt*8+(lane&3)*2;
            if (c0<NPix){ cp[c0]=cq0[nt]; cp[c0+1]=cq1[nt]; }
        }
    }
    __syncthreads();
#pragma unroll
    for (int rr=0; rr<16; rr++){
        int cp2 = wid*16 + rr;
        int mg = n0 + cp2;
        if (mg >= NPix) continue;
        int cb = cp2>>3;
        int rb = lane>>1, half = lane&1;
        int ng = m0 + rb*8 + half*4;
        if (ng >= NPix) continue;
        uint2 v = *(uint2*)(sh + cp2*136 + (((rb^cb)&15)<<3) + half*4);
        *(uint2*)&ETb[(size_t)mg*NPix + ng] = v;
    }
}

// ===== fused Z GEMM (64x256 tile) + normalization + gate + bf16 store =====
#define ZSTG 25600
#define ZSMEM (4*ZSTG)
__global__ void __launch_bounds__(256,2)
zfused(const bf16* __restrict__ E, const bf16* __restrict__ ET,
       const bf16* __restrict__ Vab, const bf16* __restrict__ Vbb,
       const float* __restrict__ riv, const float* __restrict__ civ,
       const float* __restrict__ gw,
       bf16* __restrict__ a1b, bf16* __restrict__ a2b)
{
    extern __shared__ char smc[];
    int z = blockIdx.z, br = z>>1, b = z&1;
    const bf16* A = (br?ET:E) + (size_t)b*NN;
    const bf16* B = (br?Vab:Vbb) + (size_t)b*CN;
    const float* iv = (br?civ:riv) + (size_t)b*NPix;
    bf16* out = (br?a2b:a1b) + (size_t)b*NCn;
    const int m0 = blockIdx.y*64;
    const int tid = threadIdx.x, lane = tid&31, wid = tid>>5;
    const int wm = wid>>2, wn = wid&3, g = lane>>3, r8 = lane&7;
    uint32_t sb = smem_u32(smc);
    float acc[2][8][4];
#pragma unroll
    for (int a=0;a<2;a++)
#pragma unroll
        for (int bb=0;bb<8;bb++)
#pragma unroll
            for (int c=0;c<4;c++) acc[a][bb][c]=0.f;
    const int NC = 113;

    const int rowA = tid>>2, sgA = tid&3;
    const bool vA = (m0+rowA)<NPix;
    const bf16* pA = A + (vA?((size_t)(m0+rowA)*NPix):0) + sgA*8;
    const bf16* pB = B + (size_t)rowA*NPix + sgA*8;
    const uint32_t dA = rowA*80 + sgA*16;
    const uint32_t dB = 5120 + rowA*80 + sgA*16;
    auto LD = [&](int c){
        if (c < NC) {
            uint32_t st = sb + (c&3)*ZSTG;
            int k0 = c<<5;
            bool kok = (k0+sgA*8) < NPix;
            cpa16(st+dA, pA+k0, vA&&kok);
#pragma unroll
            for (int q=0;q<4;q++)
                cpa16(st+dB + q*64*80, pB + (size_t)q*64*NPix + k0, kok);
        }
        asm volatile("cp.async.commit_group;":::"memory");
    };
    LD(0); LD(1); LD(2);
    for (int c=0;c<NC;c++){
        asm volatile("cp.async.wait_group 2;":::"memory");
        __syncthreads();
        uint32_t ta = sb+(c&3)*ZSTG, tb = ta+5120;
#pragma unroll
        for (int s=0;s<2;s++){
            uint32_t af[2][4], bq[8][2];
#pragma unroll
            for (int mt=0;mt<2;mt++)
                ldmx4(af[mt], ta + (uint32_t)((wm*32+mt*16+(g&1)*8+r8)*80 + (g>>1)*16 + s*32));
#pragma unroll
            for (int np=0;np<4;np++){
                uint32_t t4[4];
                ldmx4(t4, tb + (uint32_t)((wn*64+np*16+(g>>1)*8+r8)*80 + (g&1)*16 + s*32));
                bq[np*2][0]=t4[0]; bq[np*2][1]=t4[1]; bq[np*2+1][0]=t4[2]; bq[np*2+1][1]=t4[3];
            }
#pragma unroll
            for (int mt=0;mt<2;mt++)
#pragma unroll
                for (int nt=0;nt<8;nt++)
                    mma_bf16(acc[mt][nt], af[mt], bq[nt]);
        }
        LD(c+3);
    }

    // epilogue: gate dot, cross-warp combine, normalize+sigmoid, bf16 store
    float gwv[8][2];
#pragma unroll
    for (int nt=0;nt<8;nt++){
        int c0 = wn*64+nt*8+(lane&3)*2;
        gwv[nt][0]=gw[c0]; gwv[nt][1]=gw[c0+1];
    }
    float praw[2][2]={{0,0},{0,0}};
#pragma unroll
    for (int mt=0;mt<2;mt++)
#pragma unroll
        for (int nt=0;nt<8;nt++){
            praw[mt][0] += gwv[nt][0]*acc[mt][nt][0] + gwv[nt][1]*acc[mt][nt][1];
            praw[mt][1] += gwv[nt][0]*acc[mt][nt][2] + gwv[nt][1]*acc[mt][nt][3];
        }
#pragma unroll
    for (int mt=0;mt<2;mt++)
#pragma unroll
        for (int o=1;o<=2;o<<=1){
            praw[mt][0]+=__shfl_xor_sync(~0u,praw[mt][0],o);
            praw[mt][1]+=__shfl_xor_sync(~0u,praw[mt][1],o);
        }
    __syncthreads();
    float* dotv = (float*)smc;   // [wn 4][rl 64]
    if ((lane&3)==0){
#pragma unroll
        for (int mt=0;mt<2;mt++){
            int rl = wm*32+mt*16+(lane>>2);
            dotv[wn*64 + rl]     = praw[mt][0];
            dotv[wn*64 + rl + 8] = praw[mt][1];
        }
    }
    __syncthreads();
#pragma unroll
    for (int mt=0;mt<2;mt++){
#pragma unroll
        for (int hf=0;hf<2;hf++){
            int rl = wm*32+mt*16+hf*8+(lane>>2);
            int r = m0+rl;
            if (r >= NPix) continue;
            float d = dotv[rl] + dotv[64+rl] + dotv[128+rl] + dotv[192+rl];
            float v = iv[r];
            float mul = v/(1.f+__expf(-d*v));
#pragma unroll
            for (int nt=0;nt<8;nt++){
                int c0 = wn*64+nt*8+(lane&3)*2;
                *(bf162*)&out[(size_t)r*CC+c0] =
                    __floats2bfloat162_rn(acc[mt][nt][hf*2]*mul, acc[mt][nt][hf*2+1]*mul);
            }
        }
    }
}

// both convs: z=0,1 conv1 (3 srcs), z=2,3 conv2 (2 srcs); 9 shifted accumulated GEMMs
__global__ void __launch_bounds__(256,2)
convpair(const bf16* __restrict__ a1b, const bf16* __restrict__ a2b,
         const bf16* __restrict__ VaT, const bf16* __restrict__ VbT, const bf16* __restrict__ DaT,
         const bf16* __restrict__ wr1, const bf16* __restrict__ wr2,
         float* __restrict__ x1T, float* __restrict__ x2T)
{
    extern __shared__ char smc[];
    int zz = blockIdx.z, br = zz>>1, b = zz&1;
    const bf16 *s0 = br?a2b:a1b, *s1 = br?VbT:VaT, *s2 = br?VbT:DaT;
    const bf16 *W = br?wr2:wr1;
    float* out = br?x2T:x1T;
    const int SR = br?2:3;
    const int LDB = SR*256, KPC = SR*8, NC = 9*KPC;
    const size_t so = (size_t)b*NCn;
    const int m0 = blockIdx.y*128, n0 = blockIdx.x*128;
    const int tid = threadIdx.x, lane = tid&31, wid = tid>>5;
    const int wm = wid>>2, wn = wid&3, g = lane>>3, r8 = lane&7;
    uint32_t sb = smem_u32(smc);
    float acc[4][4][4];
#pragma unroll
    for (int a=0;a<4;a++)
#pragma unroll
        for (int bb=0;bb<4;bb++)
#pragma unroll
            for (int c=0;c<4;c++) acc[a][bb][c]=0.f;

    const int rowL = tid>>1, sgA = (tid&1)*2;
    const int j = m0+rowL;
    const bool jv = j<NPix;
    const int h = (jv?j:0)/60, w = (jv?j:0) - ((jv?j:0)/60)*60;
    uint32_t vmask = 0;
#pragma unroll
    for (int rr=0;rr<9;rr++){
        int dh = rr/3-1, dw = rr-(rr/3)*3-1;
        if (jv && (unsigned)(h+dh)<60u && (unsigned)(w+dw)<60u) vmask |= 1u<<rr;
    }
    const size_t jb = (size_t)(jv?j:0)*CC + sgA*8;
    const bf16 *pS0 = s0+so+jb, *pS1 = s1+so+jb, *pS2 = s2+so+jb;
    const bf16 *pW = W + (size_t)(n0+rowL)*LDB + sgA*8;
    const uint32_t dAs = rowL*80+sgA*16, dBs = 10240+rowL*80+sgA*16;

    int ld_vc = 0, ld_rr = 0, ld_kc = 0, ld_dh = -1, ld_dw = -1;
    size_t woff = 0;
    auto LD = [&](){
        if (ld_vc < NC) {
            uint32_t st = sb + (ld_vc&3)*STG;
            bool vv = (vmask>>ld_rr)&1;
            int off = ld_dh*60 + ld_dw;
            int srcSel = ld_kc>>3;
            const bf16* sp = (srcSel==0)?pS0:((srcSel==1)?pS1:pS2);
            const bf16* ap = sp + (intptr_t)off*CC + (ld_kc&7)*32;
            cpa16(st+dAs,    vv?ap:s0,     vv);
            cpa16(st+dAs+16, vv?(ap+8):s0, vv);
            cpa16(st+dBs,    pW+woff,   true);
            cpa16(st+dBs+16, pW+woff+8, true);
            ld_vc++; ld_kc++; woff += 32;
            if (ld_kc == KPC) {
                ld_kc = 0; ld_rr++;
                woff += (size_t)(CC-1)*LDB;
                ld_dw++; if (ld_dw==2){ ld_dw=-1; ld_dh++; }
            }
        }
        asm volatile("cp.async.commit_group;":::"memory");
    };
    LD(); LD(); LD();
    for (int c=0;c<NC;c++){
        asm volatile("cp.async.wait_group 2;":::"memory");
        __syncthreads();
        uint32_t ta = sb+(c&3)*STG, tb = ta+10240;
        MMA_COMPUTE(ta, tb);
        LD();
    }
    float* C = out + so;
#pragma unroll
    for (int mt=0;mt<4;mt++){
        int r0 = m0+wm*64+mt*16+(lane>>2);
#pragma unroll
        for (int nt=0;nt<4;nt++){
            int c0 = n0+wn*32+nt*8+(lane&3)*2;
            if (r0<NPix)   *(float2*)&C[(size_t)r0*CC+c0]     = make_float2(acc[mt][nt][0],acc[mt][nt][1]);
            if (r0+8<NPix) *(float2*)&C[(size_t)(r0+8)*CC+c0] = make_float2(acc[mt][nt][2],acc[mt][nt][3]);
        }
    }
}

__global__ void wprep(const float* __restrict__ W_e, const float* __restrict__ c1w,
                      const float* __restrict__ c2w, bf16* __restrict__ Web,
                      bf16* __restrict__ wr1, bf16* __restrict__ wr2)
{
    int idx = blockIdx.x*256+threadIdx.x;
    const int N0 = CC*CC, N1 = 9*CC*768, N2 = 9*CC*512;
    if (idx < N0) { Web[idx] = __float2bfloat16(W_e[idx]); return; }
    idx -= N0;
    if (idx < N1) {
        int r = idx/(CC*768), rem = idx - r*(CC*768);
        int co = rem/768, ci = rem - co*768;
        wr1[idx] = __float2bfloat16(c1w[(size_t)co*768*9 + ci*9 + r]);
        return;
    }
    idx -= N1;
    if (idx < N2) {
        int r = idx/(CC*512), rem = idx - r*(CC*512);
        int co = rem/512, ci = rem - co*512;
        wr2[idx] = __float2bfloat16(c2w[(size_t)co*512*9 + ci*9 + r]);
    }
}

__global__ void trans3(const float* __restrict__ Va, const float* __restrict__ Vb,
                       const float* __restrict__ Da,
                       bf16* __restrict__ VaT, bf16* __restrict__ VbT, bf16* __restrict__ DaT,
                       bf16* __restrict__ Vab, bf16* __restrict__ Vbb)
{
    __shared__ float t[32][33];
    int z = blockIdx.z, src = z>>1, b = z&1;
    const float* in = (src==0?Va:(src==1?Vb:Da)) + (size_t)b*CN;
    bf16* outT = (src==0?VaT:(src==1?VbT:DaT)) + (size_t)b*NCn;
    bf16* outN = (src==0?Vab:(src==1?Vbb:(bf16*)nullptr));
    if (outN) outN += (size_t)b*CN;
    int c0 = blockIdx.x*32, r0 = blockIdx.y*32;
    int tx = threadIdx.x&31, ty = threadIdx.x>>5;
#pragma unroll
    for (int i=0;i<4;i++){
        int rr=r0+ty+i*8, cc=c0+tx;
        if (cc<NPix){
            float v = in[(size_t)rr*NPix+cc];
            t[ty+i*8][tx] = v;
            if (outN) outN[(size_t)rr*NPix+cc] = __float2bfloat16(v);
        }
    }
    __syncthreads();
#pragma unroll
    for (int i=0;i<4;i++){
        int cc=c0+ty+i*8, rr=r0+tx;
        if (cc<NPix) outT[(size_t)cc*CC+rr] = __float2bfloat16(t[tx][ty+i*8]);
    }
}

__global__ void sumcomb_k(const float* __restrict__ rps, const float* __restrict__ cps,
                          float* __restrict__ ri, float* __restrict__ ci)
{
    int i = blockIdx.x*256+threadIdx.x;
    int zz = blockIdx.y;
    if (i >= BB*NPix) return;
    int b = i/NPix, r = i - b*NPix;
    const float* p = (zz?cps:rps) + (size_t)b*116*NPix + r;
    float s = 0.f;
#pragma unroll 4
    for (int t=0;t<116;t++) s += p[(size_t)t*NPix];
    (zz?ci:ri)[i] = 1.f/s;
}

__global__ void bnpart_k(const float* __restrict__ x1T, const float* __restrict__ x2T,
                         float* __restrict__ ps, float* __restrict__ pq)
{
    int z = blockIdx.z;
    const float* x = z?x2T:x1T;
    int c = threadIdx.x, b = blockIdx.y, blk = blockIdx.x;
    int n0 = blk*128, nend = min(n0+128, NPix);
    const float* xp = x + (size_t)b*NCn + c;
    float s=0.f, q=0.f;
    for (int n=n0;n<nend;n++){ float v=xp[(size_t)n*CC]; s+=v; q+=v*v; }
    int p = z*58 + b*29 + blk;
    ps[p*CC+c]=s; pq[p*CC+c]=q;
}

__global__ void bncomb_k(const float* __restrict__ ps, const float* __restrict__ pq,
                         const float* __restrict__ g1, const float* __restrict__ b1,
                         const float* __restrict__ g2, const float* __restrict__ b2,
                         float* __restrict__ sc, float* __restrict__ sh)
{
    int c = threadIdx.x, z = blockIdx.x;
    float s=0.f, q=0.f;
    for (int p=z*58;p<z*58+58;p++){ s+=ps[p*CC+c]; q+=pq[p*CC+c]; }
    const float inv = 1.f/(BB*NPix);
    float mean=s*inv, var=q*inv-mean*mean;
    float k = (z?g2:g1)[c]*rsqrtf(var+1e-5f);
    sc[z*CC+c]=k; sh[z*CC+c]=(z?b2:b1)[c]-mean*k;
}

__global__ void bncls_k(const float* __restrict__ x1T, const float* __restrict__ x2T,
                        const float* __restrict__ sc, const float* __restrict__ sh,
                        const float* __restrict__ c1w, const float* __restrict__ c1b,
                        const float* __restrict__ c2w, const float* __restrict__ c2b,
                        float* __restrict__ y1, float* __restrict__ y2)
{
    int z = blockIdx.z;
    const float* x = z?x2T:x1T;
    const float* cw = z?c2w:c1w;
    const float* cb = z?c2b:c1b;
    float* y = z?y2:y1;
    __shared__ float ssc[CC], ssh[CC], w0[CC], w1[CC];
    int tid = threadIdx.x;
    for (int c=tid;c<CC;c+=256){ ssc[c]=sc[z*CC+c]; ssh[c]=sh[z*CC+c]; w0[c]=cw[c]; w1[c]=cw[CC+c]; }
    __syncthreads();
    int lane=tid&31, wid=tid>>5;
    int p = blockIdx.x*8+wid, b = blockIdx.y;
    const float* xp = x + ((size_t)b*NPix+p)*CC + lane*8;
    float4 u0=*(const float4*)xp, u1=*(const float4*)(xp+4);
    float vv[8]={u0.x,u0.y,u0.z,u0.w,u1.x,u1.y,u1.z,u1.w};
    int c8=lane*8;
    float a0=0.f, a1=0.f;
#pragma unroll
    for (int u=0;u<8;u++){
        float v = fmaxf(vv[u]*ssc[c8+u]+ssh[c8+u], 0.f);
        a0 += v*w0[c8+u]; a1 += v*w1[c8+u];
    }
#pragma unroll
    for (int o=16;o;o>>=1){ a0+=__shfl_xor_sync(~0u,a0,o); a1+=__shfl_xor_sync(~0u,a1,o); }
    if (lane==0){
        y[(size_t)(b*NCls+0)*NPix+p] = a0+cb[0];
        y[(size_t)(b*NCls+1)*NPix+p] = a1+cb[1];
    }
}

__global__ void resize_k(float* __restrict__ out)
{
    const size_t per = (size_t)BB*NCls*HOUT*WOUT;
    size_t idx = (size_t)blockIdx.x*256+threadIdx.x;
    if (idx >= 2*per) return;
    int t = idx >= per;
    size_t r = idx - (size_t)t*per;
    int x=(int)(r%WOUT); r/=WOUT;
    int y=(int)(r%HOUT); r/=HOUT;
    int kc=(int)(r%NCls); int b=(int)(r/NCls);
    const float* src = (t?g_y2:g_y1) + (size_t)(b*NCls+kc)*NPix;
    const float sc = 60.f/473.f;
    float syf=(y+0.5f)*sc-0.5f, sxf=(x+0.5f)*sc-0.5f;
    float fy0=floorf(syf), fx0=floorf(sxf);
    float fy=syf-fy0, fx=sxf-fx0;
    int y0=max((int)fy0,0), x0=max((int)fx0,0);
    int y1i=min((int)fy0+1,59), x1i=min((int)fx0+1,59);
    float v00=src[y0*60+x0], v01=src[y0*60+x1i], v10=src[y1i*60+x0], v11=src[y1i*60+x1i];
    float vt=v00+(v01-v00)*fx, vb=v10+(v11-v10)*fx;
    out[idx] = 1.f/(1.f+__expf(-(vt+(vb-vt)*fy)));
}

extern "C" void kernel_launch(void* const* d_in, const int* in_sizes, int n_in,
                              void* d_out, int out_size)
{
    const float *V_a=(const float*)d_in[0], *V_b=(const float*)d_in[1], *D_a=(const float*)d_in[2];
    const float *W_e=(const float*)d_in[3], *gate_w=(const float*)d_in[4];
    const float *c1w=(const float*)d_in[5], *c2w=(const float*)d_in[6];
    const float *bn1g=(const float*)d_in[7], *bn1b=(const float*)d_in[8];
    const float *bn2g=(const float*)d_in[9], *bn2b=(const float*)d_in[10];
    const float *cl1w=(const float*)d_in[11], *cl1b=(const float*)d_in[12];
    const float *cl2w=(const float*)d_in[13], *cl2b=(const float*)d_in[14];
    float* out = (float*)d_out;

    bf16 *Vab,*Vbb,*Web,*wr1,*wr2,*VaT,*VbT,*DaT,*WvT,*E,*ET,*a1b,*a2b;
    float *x1T,*x2T,*ri,*ci,*bp,*bq,*bsc,*bsh,*y1,*y2,*rps,*cps;
    cudaGetSymbolAddress((void**)&Vab,g_Vab);  cudaGetSymbolAddress((void**)&Vbb,g_Vbb);
    cudaGetSymbolAddress((void**)&Web,g_Web);  cudaGetSymbolAddress((void**)&wr1,g_wr1);
    cudaGetSymbolAddress((void**)&wr2,g_wr2);  cudaGetSymbolAddress((void**)&VaT,g_VaT);
    cudaGetSymbolAddress((void**)&VbT,g_VbT);  cudaGetSymbolAddress((void**)&DaT,g_DaT);
    cudaGetSymbolAddress((void**)&WvT,g_WvT);  cudaGetSymbolAddress((void**)&E,g_E);
    cudaGetSymbolAddress((void**)&ET,g_ET);
    cudaGetSymbolAddress((void**)&a1b,g_a1Tb); cudaGetSymbolAddress((void**)&a2b,g_a2Tb);
    cudaGetSymbolAddress((void**)&x1T,g_x1T);  cudaGetSymbolAddress((void**)&x2T,g_x2T);
    cudaGetSymbolAddress((void**)&ri,g_rowinv);cudaGetSymbolAddress((void**)&ci,g_colinv);
    cudaGetSymbolAddress((void**)&bp,g_bp);    cudaGetSymbolAddress((void**)&bq,g_bq);
    cudaGetSymbolAddress((void**)&bsc,g_bnsc); cudaGetSymbolAddress((void**)&bsh,g_bnsh);
    cudaGetSymbolAddress((void**)&y1,g_y1);    cudaGetSymbolAddress((void**)&y2,g_y2);
    cudaGetSymbolAddress((void**)&rps,g_rps);  cudaGetSymbolAddress((void**)&cps,g_cps);

    cudaFuncSetAttribute(bgemm<1>, cudaFuncAttributeMaxDynamicSharedMemorySize, GSMEM);
    cudaFuncSetAttribute(sgemm,    cudaFuncAttributeMaxDynamicSharedMemorySize, GSMEM);
    cudaFuncSetAttribute(zfused,   cudaFuncAttributeMaxDynamicSharedMemorySize, ZSMEM);
    cudaFuncSetAttribute(convpair, cudaFuncAttributeMaxDynamicSharedMemorySize, GSMEM);

    const int WTOT = CC*CC + 9*CC*768 + 9*CC*512;
    wprep<<<(WTOT+255)/256,256>>>(W_e, c1w, c2w, Web, wr1, wr2);
    trans3<<<dim3(113,8,6),256>>>(V_a, V_b, D_a, VaT, VbT, DaT, Vab, Vbb);
    bgemm<1><<<dim3(2,29,BB),256,GSMEM>>>(VaT, Web, WvT, NPix, CC, CC, CC, CC, CC, NCn, 0, NCn);
    sgemm<<<dim3(29,29,BB),256,GSMEM>>>(WvT, VbT, E, ET, rps, cps);
    sumcomb_k<<<dim3((BB*NPix+255)/256,2),256>>>(rps, cps, ri, ci);
    zfused<<<dim3(1,57,4),256,ZSMEM>>>(E, ET, Vab, Vbb, ri, ci, gate_w, a1b, a2b);
    convpair<<<dim3(2,29,4),256,GSMEM>>>(a1b, a2b, VaT, VbT, DaT, wr1, wr2, x1T, x2T);
    bnpart_k<<<dim3(29,BB,2),256>>>(x1T, x2T, bp, bq);
    bncomb_k<<<2,256>>>(bp, bq, bn1g, bn1b, bn2g, bn2b, bsc, bsh);
    bncls_k<<<dim3(450,BB,2),256>>>(x1T, x2T, bsc, bsh, cl1w, cl1b, cl2w, cl2b, y1, y2);
    const size_t total = 2ull*BB*NCls*HOUT*WOUT;
    resize_k<<<(int)((total+255)/256),256>>>(out);
}

// round 12
// speedup vs baseline: 6.7374x; 1.0273x over previous
#include <cuda_runtime.h>
#include <cuda_bf16.h>
#include <cstdint>
#include <math.h>

#define BB 2
#define CC 256
#define NPix 3600
#define NCls 2
#define HOUT 473
#define WOUT 473
typedef __nv_bfloat16 bf16;
typedef __nv_bfloat162 bf162;

static const size_t CN = (size_t)CC*NPix, NN = (size_t)NPix*NPix, NCn = (size_t)NPix*CC;

__device__ bf16 g_Vab[BB*CC*NPix], g_Vbb[BB*CC*NPix];
__device__ bf16 g_Web[CC*CC];
__device__ bf16 g_wr1[9*CC*768], g_wr2[9*CC*512];
__device__ bf16 g_VaT[BB*NPix*CC], g_VbT[BB*NPix*CC], g_DaT[BB*NPix*CC], g_WvT[BB*NPix*CC];
__device__ bf16 g_E[(size_t)BB*NPix*NPix], g_ET[(size_t)BB*NPix*NPix];
__device__ bf16 g_a1Tb[BB*NPix*CC], g_a2Tb[BB*NPix*CC];
__device__ float g_x1T[BB*NPix*CC], g_x2T[BB*NPix*CC];
__device__ float g_bp[2*58*CC], g_bq[2*58*CC];
__device__ float g_bnsc[2*CC], g_bnsh[2*CC];
__device__ float g_y1[BB*NCls*NPix], g_y2[BB*NCls*NPix];

__device__ __forceinline__ uint32_t smem_u32(const void* p){
    uint32_t a; asm("{ .reg .u64 t; cvta.to.shared.u64 t, %1; cvt.u32.u64 %0, t; }":"=r"(a):"l"(p)); return a;
}
__device__ __forceinline__ void cpa16(uint32_t d, const void* s, bool v){
    asm volatile("cp.async.cg.shared.global [%0],[%1],16,%2;"::"r"(d),"l"(s),"r"(v?16:0));
}
__device__ __forceinline__ void ldmx4(uint32_t* r, uint32_t a){
    asm volatile("ldmatrix.sync.aligned.m8n8.x4.shared.b16 {%0,%1,%2,%3},[%4];"
        :"=r"(r[0]),"=r"(r[1]),"=r"(r[2]),"=r"(r[3]):"r"(a));
}
__device__ __forceinline__ void mma_bf16(float* c, const uint32_t* a, const uint32_t* b){
    asm volatile("mma.sync.aligned.m16n8k16.row.col.f32.bf16.bf16.f32 "
        "{%0,%1,%2,%3},{%4,%5,%6,%7},{%8,%9},{%0,%1,%2,%3};"
        :"+f"(c[0]),"+f"(c[1]),"+f"(c[2]),"+f"(c[3])
        :"r"(a[0]),"r"(a[1]),"r"(a[2]),"r"(a[3]),"r"(b[0]),"r"(b[1]));
}

#define STG 20480
#define GSMEM (4*STG)

#define MMA_COMPUTE(ta, tb) \
    _Pragma("unroll") \
    for (int s = 0; s < 2; s++) { \
        uint32_t af[4][4], bq[4][2]; \
        _Pragma("unroll") \
        for (int mt = 0; mt < 4; mt++) \
            ldmx4(af[mt], (ta) + (uint32_t)((wm*64+mt*16+(g&1)*8+r8)*80 + (g>>1)*16 + s*32)); \
        _Pragma("unroll") \
        for (int np = 0; np < 2; np++) { \
            uint32_t t4[4]; \
            ldmx4(t4, (tb) + (uint32_t)((wn*32+np*16+(g>>1)*8+r8)*80 + (g&1)*16 + s*32)); \
            bq[np*2][0]=t4[0]; bq[np*2][1]=t4[1]; bq[np*2+1][0]=t4[2]; bq[np*2+1][1]=t4[3]; \
        } \
        _Pragma("unroll") \
        for (int mt = 0; mt < 4; mt++) \
            _Pragma("unroll") \
            for (int nt = 0; nt < 4; nt++) \
                mma_bf16(acc[mt][nt], af[mt], bq[nt]); \
    }

#define GEMM_MAINLOOP(Aptr, Bptr, MMd, NNd, KKd, llda, lldb) \
    const int rowL = tid>>1, sgA = (tid&1)*2; \
    const bool vA = (m0+rowL)<(MMd), vB = (n0+rowL)<(NNd); \
    const bf16* pA = (Aptr) + (vA?((size_t)(m0+rowL)*(llda)):0) + sgA*8; \
    const bf16* pB = (Bptr) + (vB?((size_t)(n0+rowL)*(lldb)):0) + sgA*8; \
    const uint32_t dA = rowL*80+sgA*16, dB = 10240+rowL*80+sgA*16; \
    auto LD = [&](int c){ \
        if (c < NC) { \
            uint32_t st = sb + (c&3)*STG; \
            int k0 = c<<5; \
            bool k0ok = (k0+sgA*8)<(KKd), k1ok = (k0+sgA*8+8)<(KKd); \
            cpa16(st+dA,    pA+k0,   vA&&k0ok); \
            cpa16(st+dA+16, pA+k0+8, vA&&k1ok); \
            cpa16(st+dB,    pB+k0,   vB&&k0ok); \
            cpa16(st+dB+16, pB+k0+8, vB&&k1ok); \
        } \
        asm volatile("cp.async.commit_group;":::"memory"); \
    }; \
    LD(0); LD(1); LD(2); \
    for (int c=0;c<NC;c++){ \
        asm volatile("cp.async.wait_group 2;":::"memory"); \
        __syncthreads(); \
        uint32_t ta = sb+(c&3)*STG, tb = ta+10240; \
        MMA_COMPUTE(ta, tb); \
        LD(c+3); \
    }

template<int OUTM>
__device__ __forceinline__ void gbody(const bf16* __restrict__ A, const bf16* __restrict__ B,
    void* __restrict__ Cv, int Md, int Nd, int Kd, int lda, int ldb, int ldc, int m0, int n0)
{
    extern __shared__ char smc[];
    const int tid = threadIdx.x, lane = tid&31, wid = tid>>5;
    const int wm = wid>>2, wn = wid&3, g = lane>>3, r8 = lane&7;
    uint32_t sb = smem_u32(smc);
    float acc[4][4][4];
#pragma unroll
    for (int a=0;a<4;a++)
#pragma unroll
        for (int b=0;b<4;b++)
#pragma unroll
            for (int c=0;c<4;c++) acc[a][b][c]=0.f;
    const int NC = (Kd+31)>>5;
    GEMM_MAINLOOP(A, B, Md, Nd, Kd, lda, ldb)
#pragma unroll
    for (int mt=0;mt<4;mt++){
        int r0 = m0+wm*64+mt*16+(lane>>2);
#pragma unroll
        for (int nt=0;nt<4;nt++){
            int c0 = n0+wn*32+nt*8+(lane&3)*2;
            if (c0 >= Nd) continue;
            float x0=acc[mt][nt][0],x1=acc[mt][nt][1],x2=acc[mt][nt][2],x3=acc[mt][nt][3];
            if (OUTM==0){
                float* C=(float*)Cv;
                if (r0<Md)   *(float2*)&C[(size_t)r0*ldc+c0]     = make_float2(x0,x1);
                if (r0+8<Md) *(float2*)&C[(size_t)(r0+8)*ldc+c0] = make_float2(x2,x3);
            } else {
                bf16* C=(bf16*)Cv;
                if (r0<Md)   *(bf162*)&C[(size_t)r0*ldc+c0]     = __floats2bfloat162_rn(x0,x1);
                if (r0+8<Md) *(bf162*)&C[(size_t)(r0+8)*ldc+c0] = __floats2bfloat162_rn(x2,x3);
            }
        }
    }
}

template<int OUTM>
__global__ void __launch_bounds__(256,2)
bgemm(const bf16* __restrict__ A, const bf16* __restrict__ B, void* __restrict__ Cv,
      int Md, int Nd, int Kd, int lda, int ldb, int ldc, size_t sA, size_t sB, size_t sC)
{
    const int z = blockIdx.z;
    void* C = (OUTM==0) ? (void*)((float*)Cv+(size_t)z*sC) : (void*)((bf16*)Cv+(size_t)z*sC);
    gbody<OUTM>(A+(size_t)z*sA, B+(size_t)z*sB, C, Md, Nd, Kd, lda, ldb, ldc,
                blockIdx.y*128, blockIdx.x*128);
}

// S GEMM: E=exp(WvT·VbT^T) and ET (transposed via swizzled smem staging)
__global__ void __launch_bounds__(256,2)
sgemm(const bf16* __restrict__ WvT, const bf16* __restrict__ VbT,
      bf16* __restrict__ Ep, bf16* __restrict__ ETp)
{
    extern __shared__ char smc[];
    const int z = blockIdx.z;
    const bf16* A = WvT + (size_t)z*NCn;
    const bf16* B = VbT + (size_t)z*NCn;
    bf16* Eb  = Ep  + (size_t)z*NN;
    bf16* ETb = ETp + (size_t)z*NN;
    const int m0 = blockIdx.y*128, n0 = blockIdx.x*128;
    const int tid = threadIdx.x, lane = tid&31, wid = tid>>5;
    const int wm = wid>>2, wn = wid&3, g = lane>>3, r8 = lane&7;
    uint32_t sb = smem_u32(smc);
    float acc[4][4][4];
#pragma unroll
    for (int a=0;a<4;a++)
#pragma unroll
        for (int b=0;b<4;b++)
#pragma unroll
            for (int c=0;c<4;c++) acc[a][b][c]=0.f;
    const int NC = 8;
    GEMM_MAINLOOP(A, B, NPix, NPix, CC, CC, CC)

    __syncthreads();
    bf16* sh = (bf16*)smc;
#pragma unroll
    for (int mt=0;mt<4;mt++){
        int rl0 = wm*64+mt*16+(lane>>2);
        int r0 = m0+rl0;
        bool rok0 = r0<NPix, rok1 = (r0+8)<NPix;
#pragma unroll
        for (int nt=0;nt<4;nt++){
            int cl0 = wn*32+nt*8+(lane&3)*2;
            int c0 = n0+cl0;
            bool cok = c0<NPix;
            float x0=__expf(acc[mt][nt][0]),x1=__expf(acc[mt][nt][1]);
            float x2=__expf(acc[mt][nt][2]),x3=__expf(acc[mt][nt][3]);
            if (cok) {
                if (rok0) *(bf162*)&Eb[(size_t)r0*NPix+c0]     = __floats2bfloat162_rn(x0,x1);
                if (rok1) *(bf162*)&Eb[(size_t)(r0+8)*NPix+c0] = __floats2bfloat162_rn(x2,x3);
            }
#define TST(rr,cc,xx) sh[(cc)*136 + (((((rr)>>3)^((cc)>>3))&15)<<3) + ((rr)&7)] = __float2bfloat16(xx)
            TST(rl0,   cl0,   x0); TST(rl0,   cl0+1, x1);
            TST(rl0+8, cl0,   x2); TST(rl0+8, cl0+1, x3);
#undef TST
        }
    }
    __syncthreads();
#pragma unroll
    for (int rr=0; rr<16; rr++){
        int cp2 = wid*16 + rr;
        int mg = n0 + cp2;
        if (mg >= NPix) continue;
        int cb = cp2>>3;
        int rb = lane>>1, half = lane&1;
        int ng = m0 + rb*8 + half*4;
        if (ng >= NPix) continue;
        uint2 v = *(uint2*)(sh + cp2*136 + (((rb^cb)&15)<<3) + half*4);
        *(uint2*)&ETb[(size_t)mg*NPix + ng] = v;
    }
}

// ===== fused Z GEMM (64x256) + in-kernel rowsum + normalize + gate + bf16 store =====
#define ZSTG 25600
#define ZSMEM (4*ZSTG)
__global__ void __launch_bounds__(256,2)
zfused(const bf16* __restrict__ E, const bf16* __restrict__ ET,
       const bf16* __restrict__ Vab, const bf16* __restrict__ Vbb,
       const float* __restrict__ gw,
       bf16* __restrict__ a1b, bf16* __restrict__ a2b)
{
    extern __shared__ char smc[];
    int z = blockIdx.z, br = z>>1, b = z&1;
    const bf16* A = (br?ET:E) + (size_t)b*NN;
    const bf16* B = (br?Vab:Vbb) + (size_t)b*CN;
    bf16* out = (br?a2b:a1b) + (size_t)b*NCn;
    const int m0 = blockIdx.y*64;
    const int tid = threadIdx.x, lane = tid&31, wid = tid>>5;
    const int wm = wid>>2, wn = wid&3, g = lane>>3, r8 = lane&7;
    uint32_t sb = smem_u32(smc);
    float acc[2][8][4];
#pragma unroll
    for (int a=0;a<2;a++)
#pragma unroll
        for (int bb=0;bb<8;bb++)
#pragma unroll
            for (int c=0;c<4;c++) acc[a][bb][c]=0.f;
    const int NC = 113;

    const int rowA = tid>>2, sgA = tid&3;
    const bool vA = (m0+rowA)<NPix;
    const bf16* pA = A + (vA?((size_t)(m0+rowA)*NPix):0) + sgA*8;
    const bf16* pB = B + (size_t)rowA*NPix + sgA*8;
    const uint32_t dA = rowA*80 + sgA*16;
    const uint32_t dB = 5120 + rowA*80 + sgA*16;
    auto LD = [&](int c){
        if (c < NC) {
            uint32_t st = sb + (c&3)*ZSTG;
            int k0 = c<<5;
            bool kok = (k0+sgA*8) < NPix;
            cpa16(st+dA, pA+k0, vA&&kok);
#pragma unroll
            for (int q=0;q<4;q++)
                cpa16(st+dB + q*64*80, pB + (size_t)q*64*NPix + k0, kok);
        }
        asm volatile("cp.async.commit_group;":::"memory");
    };
    LD(0); LD(1); LD(2);
    float rs = 0.f;          // partial row-sum of A (this thread's row/seg slice)
    for (int c=0;c<NC;c++){
        asm volatile("cp.async.wait_group 2;":::"memory");
        __syncthreads();
        uint32_t ta = sb+(c&3)*ZSTG, tb = ta+5120;
        // accumulate row sums from staged A tile (rows of E -> normalization sums)
        {
            const uint4 v4 = *(const uint4*)(smc + (size_t)(c&3)*ZSTG + rowA*80 + sgA*16);
            const uint32_t vv[4] = {v4.x, v4.y, v4.z, v4.w};
#pragma unroll
            for (int u=0;u<4;u++){
                float2 f = __bfloat1622float2(*(const bf162*)&vv[u]);
                rs += f.x + f.y;
            }
        }
#pragma unroll
        for (int s=0;s<2;s++){
            uint32_t af[2][4], bq[8][2];
#pragma unroll
            for (int mt=0;mt<2;mt++)
                ldmx4(af[mt], ta + (uint32_t)((wm*32+mt*16+(g&1)*8+r8)*80 + (g>>1)*16 + s*32));
#pragma unroll
            for (int np=0;np<4;np++){
                uint32_t t4[4];
                ldmx4(t4, tb + (uint32_t)((wn*64+np*16+(g>>1)*8+r8)*80 + (g&1)*16 + s*32));
                bq[np*2][0]=t4[0]; bq[np*2][1]=t4[1]; bq[np*2+1][0]=t4[2]; bq[np*2+1][1]=t4[3];
            }
#pragma unroll
            for (int mt=0;mt<2;mt++)
#pragma unroll
                for (int nt=0;nt<8;nt++)
                    mma_bf16(acc[mt][nt], af[mt], bq[nt]);
        }
        LD(c+3);
    }
    // combine the 4 seg-partials of each row (lanes differing in bits 0-1)
    rs += __shfl_xor_sync(~0u, rs, 1);
    rs += __shfl_xor_sync(~0u, rs, 2);

    // epilogue: gate dot, cross-warp combine, normalize+sigmoid, bf16 store
    float gwv[8][2];
#pragma unroll
    for (int nt=0;nt<8;nt++){
        int c0 = wn*64+nt*8+(lane&3)*2;
        gwv[nt][0]=gw[c0]; gwv[nt][1]=gw[c0+1];
    }
    float praw[2][2]={{0,0},{0,0}};
#pragma unroll
    for (int mt=0;mt<2;mt++)
#pragma unroll
        for (int nt=0;nt<8;nt++){
            praw[mt][0] += gwv[nt][0]*acc[mt][nt][0] + gwv[nt][1]*acc[mt][nt][1];
            praw[mt][1] += gwv[nt][0]*acc[mt][nt][2] + gwv[nt][1]*acc[mt][nt][3];
        }
#pragma unroll
    for (int mt=0;mt<2;mt++)
#pragma unroll
        for (int o=1;o<=2;o<<=1){
            praw[mt][0]+=__shfl_xor_sync(~0u,praw[mt][0],o);
            praw[mt][1]+=__shfl_xor_sync(~0u,praw[mt][1],o);
        }
    __syncthreads();
    float* dotv  = (float*)smc;          // [wn 4][rl 64]
    float* rsums = (float*)smc + 256;    // [rl 64]
    if ((lane&3)==0){
#pragma unroll
        for (int mt=0;mt<2;mt++){
            int rl = wm*32+mt*16+(lane>>2);
            dotv[wn*64 + rl]     = praw[mt][0];
            dotv[wn*64 + rl + 8] = praw[mt][1];
        }
    }
    if (sgA==0) rsums[rowA] = rs;
    __syncthreads();
#pragma unroll
    for (int mt=0;mt<2;mt++){
#pragma unroll
        for (int hf=0;hf<2;hf++){
            int rl = wm*32+mt*16+hf*8+(lane>>2);
            int r = m0+rl;
            if (r >= NPix) continue;
            float d = dotv[rl] + dotv[64+rl] + dotv[128+rl] + dotv[192+rl];
            float v = 1.f/rsums[rl];
            float mul = v/(1.f+__expf(-d*v));
#pragma unroll
            for (int nt=0;nt<8;nt++){
                int c0 = wn*64+nt*8+(lane&3)*2;
                *(bf162*)&out[(size_t)r*CC+c0] =
                    __floats2bfloat162_rn(acc[mt][nt][hf*2]*mul, acc[mt][nt][hf*2+1]*mul);
            }
        }
    }
}

// both convs: z=0,1 conv1 (3 srcs), z=2,3 conv2 (2 srcs); 9 shifted accumulated GEMMs
__global__ void __launch_bounds__(256,2)
convpair(const bf16* __restrict__ a1b, const bf16* __restrict__ a2b,
         const bf16* __restrict__ VaT, const bf16* __restrict__ VbT, const bf16* __restrict__ DaT,
         const bf16* __restrict__ wr1, const bf16* __restrict__ wr2,
         float* __restrict__ x1T, float* __restrict__ x2T)
{
    extern __shared__ char smc[];
    int zz = blockIdx.z, br = zz>>1, b = zz&1;
    const bf16 *s0 = br?a2b:a1b, *s1 = br?VbT:VaT, *s2 = br?VbT:DaT;
    const bf16 *W = br?wr2:wr1;
    float* out = br?x2T:x1T;
    const int SR = br?2:3;
    const int LDB = SR*256, KPC = SR*8, NC = 9*KPC;
    const size_t so = (size_t)b*NCn;
    const int m0 = blockIdx.y*128, n0 = blockIdx.x*128;
    const int tid = threadIdx.x, lane = tid&31, wid = tid>>5;
    const int wm = wid>>2, wn = wid&3, g = lane>>3, r8 = lane&7;
    uint32_t sb = smem_u32(smc);
    float acc[4][4][4];
#pragma unroll
    for (int a=0;a<4;a++)
#pragma unroll
        for (int bb=0;bb<4;bb++)
#pragma unroll
            for (int c=0;c<4;c++) acc[a][bb][c]=0.f;

    const int rowL = tid>>1, sgA = (tid&1)*2;
    const int j = m0+rowL;
    const bool jv = j<NPix;
    const int h = (jv?j:0)/60, w = (jv?j:0) - ((jv?j:0)/60)*60;
    uint32_t vmask = 0;
#pragma unroll
    for (int rr=0;rr<9;rr++){
        int dh = rr/3-1, dw = rr-(rr/3)*3-1;
        if (jv && (unsigned)(h+dh)<60u && (unsigned)(w+dw)<60u) vmask |= 1u<<rr;
    }
    const size_t jb = (size_t)(jv?j:0)*CC + sgA*8;
    const bf16 *pS0 = s0+so+jb, *pS1 = s1+so+jb, *pS2 = s2+so+jb;
    const bf16 *pW = W + (size_t)(n0+rowL)*LDB + sgA*8;
    const uint32_t dAs = rowL*80+sgA*16, dBs = 10240+rowL*80+sgA*16;

    int ld_vc = 0, ld_rr = 0, ld_kc = 0, ld_dh = -1, ld_dw = -1;
    size_t woff = 0;
    auto LD = [&](){
        if (ld_vc < NC) {
            uint32_t st = sb + (ld_vc&3)*STG;
            bool vv = (vmask>>ld_rr)&1;
            int off = ld_dh*60 + ld_dw;
            int srcSel = ld_kc>>3;
            const bf16* sp = (srcSel==0)?pS0:((srcSel==1)?pS1:pS2);
            const bf16* ap = sp + (intptr_t)off*CC + (ld_kc&7)*32;
            cpa16(st+dAs,    vv?ap:s0,     vv);
            cpa16(st+dAs+16, vv?(ap+8):s0, vv);
            cpa16(st+dBs,    pW+woff,   true);
            cpa16(st+dBs+16, pW+woff+8, true);
            ld_vc++; ld_kc++; woff += 32;
            if (ld_kc == KPC) {
                ld_kc = 0; ld_rr++;
                woff += (size_t)(CC-1)*LDB;
                ld_dw++; if (ld_dw==2){ ld_dw=-1; ld_dh++; }
            }
        }
        asm volatile("cp.async.commit_group;":::"memory");
    };
    LD(); LD(); LD();
    for (int c=0;c<NC;c++){
        asm volatile("cp.async.wait_group 2;":::"memory");
        __syncthreads();
        uint32_t ta = sb+(c&3)*STG, tb = ta+10240;
        MMA_COMPUTE(ta, tb);
        LD();
    }
    float* C = out + so;
#pragma unroll
    for (int mt=0;mt<4;mt++){
        int r0 = m0+wm*64+mt*16+(lane>>2);
#pragma unroll
        for (int nt=0;nt<4;nt++){
            int c0 = n0+wn*32+nt*8+(lane&3)*2;
            if (r0<NPix)   *(float2*)&C[(size_t)r0*CC+c0]     = make_float2(acc[mt][nt][0],acc[mt][nt][1]);
            if (r0+8<NPix) *(float2*)&C[(size_t)(r0+8)*CC+c0] = make_float2(acc[mt][nt][2],acc[mt][nt][3]);
        }
    }
}

__global__ void wprep(const float* __restrict__ W_e, const float* __restrict__ c1w,
                      const float* __restrict__ c2w, bf16* __restrict__ Web,
                      bf16* __restrict__ wr1, bf16* __restrict__ wr2)
{
    int idx = blockIdx.x*256+threadIdx.x;
    const int N0 = CC*CC, N1 = 9*CC*768, N2 = 9*CC*512;
    if (idx < N0) { Web[idx] = __float2bfloat16(W_e[idx]); return; }
    idx -= N0;
    if (idx < N1) {
        int r = idx/(CC*768), rem = idx - r*(CC*768);
        int co = rem/768, ci = rem - co*768;
        wr1[idx] = __float2bfloat16(c1w[(size_t)co*768*9 + ci*9 + r]);
        return;
    }
    idx -= N1;
    if (idx < N2) {
        int r = idx/(CC*512), rem = idx - r*(CC*512);
        int co = rem/512, ci = rem - co*512;
        wr2[idx] = __float2bfloat16(c2w[(size_t)co*512*9 + ci*9 + r]);
    }
}

__global__ void trans3(const float* __restrict__ Va, const float* __restrict__ Vb,
                       const float* __restrict__ Da,
                       bf16* __restrict__ VaT, bf16* __restrict__ VbT, bf16* __restrict__ DaT,
                       bf16* __restrict__ Vab, bf16* __restrict__ Vbb)
{
    __shared__ float t[32][33];
    int z = blockIdx.z, src = z>>1, b = z&1;
    const float* in = (src==0?Va:(src==1?Vb:Da)) + (size_t)b*CN;
    bf16* outT = (src==0?VaT:(src==1?VbT:DaT)) + (size_t)b*NCn;
    bf16* outN = (src==0?Vab:(src==1?Vbb:(bf16*)nullptr));
    if (outN) outN += (size_t)b*CN;
    int c0 = blockIdx.x*32, r0 = blockIdx.y*32;
    int tx = threadIdx.x&31, ty = threadIdx.x>>5;
#pragma unroll
    for (int i=0;i<4;i++){
        int rr=r0+ty+i*8, cc=c0+tx;
        if (cc<NPix){
            float v = in[(size_t)rr*NPix+cc];
            t[ty+i*8][tx] = v;
            if (outN) outN[(size_t)rr*NPix+cc] = __float2bfloat16(v);
        }
    }
    __syncthreads();
#pragma unroll
    for (int i=0;i<4;i++){
        int cc=c0+ty+i*8, rr=r0+tx;
        if (cc<NPix) outT[(size_t)cc*CC+rr] = __float2bfloat16(t[tx][ty+i*8]);
    }
}

__global__ void bnpart_k(const float* __restrict__ x1T, const float* __restrict__ x2T,
                         float* __restrict__ ps, float* __restrict__ pq)
{
    int z = blockIdx.z;
    const float* x = z?x2T:x1T;
    int c = threadIdx.x, b = blockIdx.y, blk = blockIdx.x;
    int n0 = blk*128, nend = min(n0+128, NPix);
    const float* xp = x + (size_t)b*NCn + c;
    float s=0.f, q=0.f;
    for (int n=n0;n<nend;n++){ float v=xp[(size_t)n*CC]; s+=v; q+=v*v; }
    int p = z*58 + b*29 + blk;
    ps[p*CC+c]=s; pq[p*CC+c]=q;
}

__global__ void bncomb_k(const float* __restrict__ ps, const float* __restrict__ pq,
                         const float* __restrict__ g1, const float* __restrict__ b1,
                         const float* __restrict__ g2, const float* __restrict__ b2,
                         float* __restrict__ sc, float* __restrict__ sh)
{
    int c = threadIdx.x, z = blockIdx.x;
    float s=0.f, q=0.f;
    for (int p=z*58;p<z*58+58;p++){ s+=ps[p*CC+c]; q+=pq[p*CC+c]; }
    const float inv = 1.f/(BB*NPix);
    float mean=s*inv, var=q*inv-mean*mean;
    float k = (z?g2:g1)[c]*rsqrtf(var+1e-5f);
    sc[z*CC+c]=k; sh[z*CC+c]=(z?b2:b1)[c]-mean*k;
}

__global__ void bncls_k(const float* __restrict__ x1T, const float* __restrict__ x2T,
                        const float* __restrict__ sc, const float* __restrict__ sh,
                        const float* __restrict__ c1w, const float* __restrict__ c1b,
                        const float* __restrict__ c2w, const float* __restrict__ c2b,
                        float* __restrict__ y1, float* __restrict__ y2)
{
    int z = blockIdx.z;
    const float* x = z?x2T:x1T;
    const float* cw = z?c2w:c1w;
    const float* cb = z?c2b:c1b;
    float* y = z?y2:y1;
    __shared__ float ssc[CC], ssh[CC], w0[CC], w1[CC];
    int tid = threadIdx.x;
    for (int c=tid;c<CC;c+=256){ ssc[c]=sc[z*CC+c]; ssh[c]=sh[z*CC+c]; w0[c]=cw[c]; w1[c]=cw[CC+c]; }
    __syncthreads();
    int lane=tid&31, wid=tid>>5;
    int p = blockIdx.x*8+wid, b = blockIdx.y;
    const float* xp = x + ((size_t)b*NPix+p)*CC + lane*8;
    float4 u0=*(const float4*)xp, u1=*(const float4*)(xp+4);
    float vv[8]={u0.x,u0.y,u0.z,u0.w,u1.x,u1.y,u1.z,u1.w};
    int c8=lane*8;
    float a0=0.f, a1=0.f;
#pragma unroll
    for (int u=0;u<8;u++){
        float v = fmaxf(vv[u]*ssc[c8+u]+ssh[c8+u], 0.f);
        a0 += v*w0[c8+u]; a1 += v*w1[c8+u];
    }
#pragma unroll
    for (int o=16;o;o>>=1){ a0+=__shfl_xor_sync(~0u,a0,o); a1+=__shfl_xor_sync(~0u,a1,o); }
    if (lane==0){
        y[(size_t)(b*NCls+0)*NPix+p] = a0+cb[0];
        y[(size_t)(b*NCls+1)*NPix+p] = a1+cb[1];
    }
}

__global__ void resize_k(float* __restrict__ out)
{
    const size_t per = (size_t)BB*NCls*HOUT*WOUT;
    size_t idx = (size_t)blockIdx.x*256+threadIdx.x;
    if (idx >= 2*per) return;
    int t = idx >= per;
    size_t r = idx - (size_t)t*per;
    int x=(int)(r%WOUT); r/=WOUT;
    int y=(int)(r%HOUT); r/=HOUT;
    int kc=(int)(r%NCls); int b=(int)(r/NCls);
    const float* src = (t?g_y2:g_y1) + (size_t)(b*NCls+kc)*NPix;
    const float sc = 60.f/473.f;
    float syf=(y+0.5f)*sc-0.5f, sxf=(x+0.5f)*sc-0.5f;
    float fy0=floorf(syf), fx0=floorf(sxf);
    float fy=syf-fy0, fx=sxf-fx0;
    int y0=max((int)fy0,0), x0=max((int)fx0,0);
    int y1i=min((int)fy0+1,59), x1i=min((int)fx0+1,59);
    float v00=src[y0*60+x0], v01=src[y0*60+x1i], v10=src[y1i*60+x0], v11=src[y1i*60+x1i];
    float vt=v00+(v01-v00)*fx, vb=v10+(v11-v10)*fx;
    out[idx] = 1.f/(1.f+__expf(-(vt+(vb-vt)*fy)));
}

extern "C" void kernel_launch(void* const* d_in, const int* in_sizes, int n_in,
                              void* d_out, int out_size)
{
    const float *V_a=(const float*)d_in[0], *V_b=(const float*)d_in[1], *D_a=(const float*)d_in[2];
    const float *W_e=(const float*)d_in[3], *gate_w=(const float*)d_in[4];
    const float *c1w=(const float*)d_in[5], *c2w=(const float*)d_in[6];
    const float *bn1g=(const float*)d_in[7], *bn1b=(const float*)d_in[8];
    const float *bn2g=(const float*)d_in[9], *bn2b=(const float*)d_in[10];
    const float *cl1w=(const float*)d_in[11], *cl1b=(const float*)d_in[12];
    const float *cl2w=(const float*)d_in[13], *cl2b=(const float*)d_in[14];
    float* out = (float*)d_out;

    bf16 *Vab,*Vbb,*Web,*wr1,*wr2,*VaT,*VbT,*DaT,*WvT,*E,*ET,*a1b,*a2b;
    float *x1T,*x2T,*bp,*bq,*bsc,*bsh,*y1,*y2;
    cudaGetSymbolAddress((void**)&Vab,g_Vab);  cudaGetSymbolAddress((void**)&Vbb,g_Vbb);
    cudaGetSymbolAddress((void**)&Web,g_Web);  cudaGetSymbolAddress((void**)&wr1,g_wr1);
    cudaGetSymbolAddress((void**)&wr2,g_wr2);  cudaGetSymbolAddress((void**)&VaT,g_VaT);
    cudaGetSymbolAddress((void**)&VbT,g_VbT);  cudaGetSymbolAddress((void**)&DaT,g_DaT);
    cudaGetSymbolAddress((void**)&WvT,g_WvT);  cudaGetSymbolAddress((void**)&E,g_E);
    cudaGetSymbolAddress((void**)&ET,g_ET);
    cudaGetSymbolAddress((void**)&a1b,g_a1Tb); cudaGetSymbolAddress((void**)&a2b,g_a2Tb);
    cudaGetSymbolAddress((void**)&x1T,g_x1T);  cudaGetSymbolAddress((void**)&x2T,g_x2T);
    cudaGetSymbolAddress((void**)&bp,g_bp);    cudaGetSymbolAddress((void**)&bq,g_bq);
    cudaGetSymbolAddress((void**)&bsc,g_bnsc); cudaGetSymbolAddress((void**)&bsh,g_bnsh);
    cudaGetSymbolAddress((void**)&y1,g_y1);    cudaGetSymbolAddress((void**)&y2,g_y2);

    cudaFuncSetAttribute(bgemm<1>, cudaFuncAttributeMaxDynamicSharedMemorySize, GSMEM);
    cudaFuncSetAttribute(sgemm,    cudaFuncAttributeMaxDynamicSharedMemorySize, GSMEM);
    cudaFuncSetAttribute(zfused,   cudaFuncAttributeMaxDynamicSharedMemorySize, ZSMEM);
    cudaFuncSetAttribute(convpair, cudaFuncAttributeMaxDynamicSharedMemorySize, GSMEM);

    const int WTOT = CC*CC + 9*CC*768 + 9*CC*512;
    wprep<<<(WTOT+255)/256,256>>>(W_e, c1w, c2w, Web, wr1, wr2);
    trans3<<<dim3(113,8,6),256>>>(V_a, V_b, D_a, VaT, VbT, DaT, Vab, Vbb);
    bgemm<1><<<dim3(2,29,BB),256,GSMEM>>>(VaT, Web, WvT, NPix, CC, CC, CC, CC, CC, NCn, 0, NCn);
    sgemm<<<dim3(29,29,BB),256,GSMEM>>>(WvT, VbT, E, ET);
    zfused<<<dim3(1,57,4),256,ZSMEM>>>(E, ET, Vab, Vbb, gate_w, a1b, a2b);
    convpair<<<dim3(2,29,4),256,GSMEM>>>(a1b, a2b, VaT, VbT, DaT, wr1, wr2, x1T, x2T);
    bnpart_k<<<dim3(29,BB,2),256>>>(x1T, x2T, bp, bq);
    bncomb_k<<<2,256>>>(bp, bq, bn1g, bn1b, bn2g, bn2b, bsc, bsh);
    bncls_k<<<dim3(450,BB,2),256>>>(x1T, x2T, bsc, bsh, cl1w, cl1b, cl2w, cl2b, y1, y2);
    const size_t total = 2ull*BB*NCls*HOUT*WOUT;
    resize_k<<<(int)((total+255)/256),256>>>(out);
}